// round 6
// baseline (speedup 1.0000x reference)
#include <cuda_runtime.h>
#include <math.h>
#include <stdint.h>

#define CCH   256
#define TT      4
#define HH     64
#define WWID   64
#define NWIN  128
#define MTOT  (NWIN*256)
#define ATT_SCALE 0.1767766952966369f
#define LOG2E     1.4426950408889634f

// -------- global scratch --------
__device__ float g_xw [MTOT * CCH];
__device__ float g_xn [MTOT * CCH];          // tf32-rounded LN output
__device__ float g_qkv[MTOT * 3 * CCH];      // q: scaled(+log2e)+tf32+d-permuted, k: tf32+d-permuted, v: tf32
__device__ float g_att[MTOT * CCH];          // tf32-rounded attention output
__device__ float g_wqkv[768 * 256];          // tf32-rounded weights
__device__ float g_wproj[256 * 256];

__device__ __forceinline__ float to_tf32(float x) {
    float r;
    asm("cvt.rna.tf32.f32 %0, %1;" : "=f"(r) : "f"(x));
    return r;
}

__device__ __forceinline__ float ex2_approx(float x) {
    float r;
    asm("ex2.approx.f32 %0, %1;" : "=f"(r) : "f"(x));
    return r;
}

__device__ __forceinline__ void mma_tf32(float* c,
                                         uint32_t a0, uint32_t a1, uint32_t a2, uint32_t a3,
                                         uint32_t b0, uint32_t b1) {
    asm volatile("mma.sync.aligned.m16n8k8.row.col.f32.tf32.tf32.f32 "
                 "{%0,%1,%2,%3}, {%4,%5,%6,%7}, {%8,%9}, {%0,%1,%2,%3};"
                 : "+f"(c[0]), "+f"(c[1]), "+f"(c[2]), "+f"(c[3])
                 : "r"(a0), "r"(a1), "r"(a2), "r"(a3), "r"(b0), "r"(b1));
}

__device__ __forceinline__ void cpasync16(uint32_t dst, const void* src) {
    asm volatile("cp.async.ca.shared.global [%0], [%1], 16;\n" :: "r"(dst), "l"(src));
}
#define CP_COMMIT asm volatile("cp.async.commit_group;\n" ::: "memory")
#define CP_WAIT1  asm volatile("cp.async.wait_group 1;\n" ::: "memory")
#define CP_WAIT0  asm volatile("cp.async.wait_group 0;\n" ::: "memory")

// ============================================================
// Kernel 0: weight prep (fp32 -> tf32-rounded copies)
// ============================================================
__global__ void prep_weights(const float* __restrict__ wq, const float* __restrict__ wp)
{
    int i = blockIdx.x * blockDim.x + threadIdx.x;
    if (i < 768 * 256)  g_wqkv[i]  = to_tf32(wq[i]);
    if (i < 256 * 256)  g_wproj[i] = to_tf32(wp[i]);
}

// ============================================================
// Kernel 1: coalesced gather + LayerNorm
// ============================================================
__global__ __launch_bounds__(256) void ln_gather_kernel(const float* __restrict__ x,
                                                        const float* __restrict__ gamma,
                                                        const float* __restrict__ beta)
{
    __shared__ float tile[256][65];
    __shared__ float rsum[4][64], rsq[4][64];
    __shared__ float mus[64], rstds[64];

    int bx  = blockIdx.x;
    int bt  = bx >> 6;
    int h   = bx & 63;
    int tid = threadIdx.x;

    const float* slice = x + ((size_t)bt * 256) * 4096 + h * 64;

    int cl = tid >> 4;
    int w4 = (tid & 15) * 4;
    #pragma unroll
    for (int it = 0; it < 16; it++) {
        int c = it * 16 + cl;
        float4 v = *(const float4*)(slice + (size_t)c * 4096 + w4);
        tile[c][w4 + 0] = v.x; tile[c][w4 + 1] = v.y;
        tile[c][w4 + 2] = v.z; tile[c][w4 + 3] = v.w;
    }
    __syncthreads();

    {
        int w = tid & 63, part = tid >> 6;
        float s = 0.f, q = 0.f;
        #pragma unroll
        for (int i = 0; i < 64; i++) {
            float v = tile[part * 64 + i][w];
            s += v; q += v * v;
        }
        rsum[part][w] = s; rsq[part][w] = q;
    }
    __syncthreads();
    if (tid < 64) {
        float tot = rsum[0][tid] + rsum[1][tid] + rsum[2][tid] + rsum[3][tid];
        float tq  = rsq[0][tid]  + rsq[1][tid]  + rsq[2][tid]  + rsq[3][tid];
        float mu  = tot * (1.0f / 256.0f);
        float var = tq * (1.0f / 256.0f) - mu * mu;
        mus[tid]  = mu;
        rstds[tid] = rsqrtf(var + 1e-5f);
    }
    __syncthreads();

    int c = tid;
    float gm = gamma[c], be = beta[c];
    int b  = bt >> 2, t = bt & 3;
    int hi = h >> 3, r = h & 7;
    int nbase = b * 64 + hi * 8;
    int lbase = t * 64 + r * 8;
    #pragma unroll 8
    for (int w = 0; w < 64; w++) {
        int n = nbase + (w >> 3);
        int l = lbase + (w & 7);
        size_t m = (size_t)n * 256 + l;
        float val = tile[c][w];
        float xn  = (val - mus[w]) * rstds[w] * gm + be;
        g_xw[m * 256 + c] = val;
        g_xn[m * 256 + c] = to_tf32(xn);
    }
}

// ============================================================
// cp.async stage loader for 128x32 tiles (pitch 36)
// ============================================================
__device__ __forceinline__ void stage_load(float (*As)[36], float (*Bs)[36],
                                           const float* Ag, const float* Bg,
                                           int r0, int c4)
{
    #pragma unroll
    for (int i = 0; i < 4; i++) {
        uint32_t da = (uint32_t)__cvta_generic_to_shared(&As[r0 + 32*i][c4]);
        uint32_t db = (uint32_t)__cvta_generic_to_shared(&Bs[r0 + 32*i][c4]);
        cpasync16(da, Ag + (size_t)(r0 + 32*i) * 256 + c4);
        cpasync16(db, Bg + (size_t)(r0 + 32*i) * 256 + c4);
    }
}

// ============================================================
// Kernel 2: QKV GEMM.  Epilogue: q scaled by ATT_SCALE*LOG2E,
// q and k written d-permuted (within head: p = (d&3)*8 + d>>2).
// ============================================================
__global__ __launch_bounds__(256) void gemm_qkv_mma(const float* __restrict__ bias)
{
    __shared__ float As[2][128][36];
    __shared__ float Bs[2][128][36];

    int tid  = threadIdx.x;
    int lane = tid & 31, warp = tid >> 5;
    int g = lane >> 2, t = lane & 3;
    int wm = (warp & 1) * 64;
    int wn = (warp >> 1) * 32;

    const float* Ab = g_xn   + (size_t)blockIdx.y * 128 * 256;
    const float* Bb = g_wqkv + (size_t)blockIdx.x * 128 * 256;

    int r0 = tid >> 3;
    int c4 = (tid & 7) * 4;

    stage_load(As[0], Bs[0], Ab, Bb, r0, c4);
    CP_COMMIT;

    float c[4][4][4] = {};

    for (int it = 0; it < 8; it++) {
        if (it < 7)
            stage_load(As[(it+1)&1], Bs[(it+1)&1], Ab + (it+1)*32, Bb + (it+1)*32, r0, c4);
        CP_COMMIT;
        CP_WAIT1;
        __syncthreads();
        int s = it & 1;
        #pragma unroll
        for (int ks = 0; ks < 4; ks++) {
            int k0 = ks * 8;
            uint32_t bf[4][2];
            #pragma unroll
            for (int j = 0; j < 4; j++) {
                bf[j][0] = __float_as_uint(Bs[s][wn + j*8 + g][k0 + t]);
                bf[j][1] = __float_as_uint(Bs[s][wn + j*8 + g][k0 + t + 4]);
            }
            #pragma unroll
            for (int m = 0; m < 4; m++) {
                int rb = wm + m*16;
                uint32_t a0 = __float_as_uint(As[s][rb + g    ][k0 + t    ]);
                uint32_t a1 = __float_as_uint(As[s][rb + g + 8][k0 + t    ]);
                uint32_t a2 = __float_as_uint(As[s][rb + g    ][k0 + t + 4]);
                uint32_t a3 = __float_as_uint(As[s][rb + g + 8][k0 + t + 4]);
                #pragma unroll
                for (int j = 0; j < 4; j++)
                    mma_tf32(c[m][j], a0, a1, a2, a3, bf[j][0], bf[j][1]);
            }
        }
        __syncthreads();
    }

    float sc = (blockIdx.x < 2) ? ATT_SCALE * LOG2E : 1.0f;
    bool permute = (blockIdx.x < 4);   // q and k blocks

    int mbase = blockIdx.y * 128 + wm;
    int nbase = blockIdx.x * 128 + wn;
    #pragma unroll
    for (int m = 0; m < 4; m++) {
        int row0 = mbase + m*16 + g;
        #pragma unroll
        for (int j = 0; j < 4; j++) {
            int col = nbase + j*8 + 2*t;
            float2 bv = *(const float2*)&bias[col];
            float v00 = to_tf32((c[m][j][0] + bv.x) * sc);
            float v01 = to_tf32((c[m][j][1] + bv.y) * sc);
            float v10 = to_tf32((c[m][j][2] + bv.x) * sc);
            float v11 = to_tf32((c[m][j][3] + bv.y) * sc);
            if (permute) {
                int b32 = col & ~31;
                int d0  = col & 31, d1 = d0 + 1;
                int p0  = ((d0 & 3) << 3) + (d0 >> 2);
                int p1  = ((d1 & 3) << 3) + (d1 >> 2);
                g_qkv[(size_t)row0       * 768 + b32 + p0] = v00;
                g_qkv[(size_t)row0       * 768 + b32 + p1] = v01;
                g_qkv[(size_t)(row0 + 8) * 768 + b32 + p0] = v10;
                g_qkv[(size_t)(row0 + 8) * 768 + b32 + p1] = v11;
            } else {
                *(float2*)&g_qkv[(size_t)row0       * 768 + col] = make_float2(v00, v01);
                *(float2*)&g_qkv[(size_t)(row0 + 8) * 768 + col] = make_float2(v10, v11);
            }
        }
    }
}

// ============================================================
// Kernel 3: tensor-core attention, fragment-major operands.
// One block per (window, head), 4 warps.
// Ks: 256 keys x 32 d (d-permuted), xor-swizzled chunks (chunk ^ key&7).
// Vt: 32 d x 256 keys', key' = (key%8)*32 + key/8, swizzle q^(q>>3)^(d&7).
// ============================================================
__global__ __launch_bounds__(128) void attn_mma()
{
    __shared__ float Ks[256 * 32];
    __shared__ float Vt[32 * 256];

    int win  = blockIdx.x >> 3;
    int head = blockIdx.x & 7;
    int tid  = threadIdx.x;
    int lane = tid & 31, warp = tid >> 5;
    int g = lane >> 2, t = lane & 3;
    bool odd = t & 1;
    int srcA = (lane & ~3) | (t >> 1);
    int srcB = srcA + 2;

    const float* base  = g_qkv + (size_t)win * 256 * 768 + head * 32;
    float*       obase = g_att + (size_t)win * 256 * 256;

    // --- K via cp.async into swizzled chunks ---
    int keyl = tid >> 3;          // 0..15
    int qc   = tid & 7;           // chunk 0..7
    #pragma unroll
    for (int it = 0; it < 16; it++) {
        int key = it * 16 + keyl;
        int qsw = qc ^ (key & 7);
        uint32_t dst = (uint32_t)__cvta_generic_to_shared(&Ks[key * 32 + qsw * 4]);
        cpasync16(dst, base + (size_t)key * 768 + 256 + qc * 4);
    }
    CP_COMMIT;

    // --- Q fragments for all 4 m-tiles (32B-aligned full-sector LDG.128) ---
    float qg[4][8], qh[4][8];
    #pragma unroll
    for (int mt = 0; mt < 4; mt++) {
        int mrow = (mt * 4 + warp) * 16;
        const float* qp = base + (size_t)mrow * 768 + t * 8;
        *(float4*)&qg[mt][0] = *(const float4*)(qp + (size_t)g * 768);
        *(float4*)&qg[mt][4] = *(const float4*)(qp + (size_t)g * 768 + 4);
        *(float4*)&qh[mt][0] = *(const float4*)(qp + (size_t)(g + 8) * 768);
        *(float4*)&qh[mt][4] = *(const float4*)(qp + (size_t)(g + 8) * 768 + 4);
    }

    // --- V transpose into swizzled Vt ---
    int d4 = qc * 4;
    #pragma unroll
    for (int it = 0; it < 16; it++) {
        int key = it * 16 + keyl;
        float4 v = *(const float4*)(base + (size_t)key * 768 + 512 + d4);
        int keyp = (key & 7) * 32 + (key >> 3);
        int q  = keyp >> 2, lo = keyp & 3;
        int qt = q >> 3;
        Vt[(d4+0)*256 + ((q ^ qt ^ ((d4+0)&7)) << 2) + lo] = v.x;
        Vt[(d4+1)*256 + ((q ^ qt ^ ((d4+1)&7)) << 2) + lo] = v.y;
        Vt[(d4+2)*256 + ((q ^ qt ^ ((d4+2)&7)) << 2) + lo] = v.z;
        Vt[(d4+3)*256 + ((q ^ qt ^ ((d4+3)&7)) << 2) + lo] = v.w;
    }
    CP_WAIT0;
    __syncthreads();

    #pragma unroll
    for (int mt = 0; mt < 4; mt++) {
        int mrow = (mt * 4 + warp) * 16;
        const float* QG = qg[mt];
        const float* QH = qh[mt];

        float rs0 = 0.f, rs1 = 0.f;
        float co[4][4] = {};

        #pragma unroll
        for (int ch = 0; ch < 4; ch++) {
            int kb = ch * 64;

            // ---- S = Q K^T chunk (16 x 64) ----
            float sf[8][4];
            #pragma unroll
            for (int nf = 0; nf < 8; nf++) { sf[nf][0]=0.f; sf[nf][1]=0.f; sf[nf][2]=0.f; sf[nf][3]=0.f; }
            #pragma unroll
            for (int nf = 0; nf < 8; nf++) {
                int key = kb + nf * 8 + g;
                const float* kr = &Ks[key * 32];
                float kbuf[8];
                *(float4*)&kbuf[0] = *(const float4*)(kr + (((2*t    ) ^ g) << 2));
                *(float4*)&kbuf[4] = *(const float4*)(kr + (((2*t + 1) ^ g) << 2));
                #pragma unroll
                for (int kf = 0; kf < 4; kf++) {
                    mma_tf32(sf[nf],
                             __float_as_uint(QG[2*kf]),   __float_as_uint(QH[2*kf]),
                             __float_as_uint(QG[2*kf+1]), __float_as_uint(QH[2*kf+1]),
                             __float_as_uint(kbuf[2*kf]), __float_as_uint(kbuf[2*kf+1]));
                }
            }

            // ---- exp2 + rowsum + C-frag -> A-frag (quad shuffles) ----
            #pragma unroll
            for (int nf = 0; nf < 8; nf++) {
                float e0 = ex2_approx(sf[nf][0]);
                float e1 = ex2_approx(sf[nf][1]);
                float e2 = ex2_approx(sf[nf][2]);
                float e3 = ex2_approx(sf[nf][3]);
                rs0 += e0 + e1;
                rs1 += e2 + e3;
                uint32_t u0 = __float_as_uint(e0);
                uint32_t u1 = __float_as_uint(e1);
                uint32_t u2 = __float_as_uint(e2);
                uint32_t u3 = __float_as_uint(e3);
                uint32_t x0 = __shfl_sync(0xffffffffu, u0, srcA);
                uint32_t x1 = __shfl_sync(0xffffffffu, u1, srcA);
                uint32_t y0 = __shfl_sync(0xffffffffu, u0, srcB);
                uint32_t y1 = __shfl_sync(0xffffffffu, u1, srcB);
                uint32_t z0 = __shfl_sync(0xffffffffu, u2, srcA);
                uint32_t z1 = __shfl_sync(0xffffffffu, u3, srcA);
                uint32_t w0 = __shfl_sync(0xffffffffu, u2, srcB);
                uint32_t w1 = __shfl_sync(0xffffffffu, u3, srcB);
                sf[nf][0] = __uint_as_float(odd ? x1 : x0);
                sf[nf][2] = __uint_as_float(odd ? y1 : y0);
                sf[nf][1] = __uint_as_float(odd ? z1 : z0);
                sf[nf][3] = __uint_as_float(odd ? w1 : w0);
            }

            // ---- O += P V (fragment-major Vt reads, 4 LDS.128 per nf) ----
            #pragma unroll
            for (int nf = 0; nf < 4; nf++) {
                int row = nf * 8 + g;
                const float* vr = &Vt[row * 256];
                float vA[8], vB[8];
                int qa0 = t*8 + ch*2;           // q>>3 = t
                int qb0 = (t+4)*8 + ch*2;       // q>>3 = t+4
                *(float4*)&vA[0] = *(const float4*)(vr + (((qa0    ) ^ t       ^ g) << 2));
                *(float4*)&vA[4] = *(const float4*)(vr + (((qa0 + 1) ^ t       ^ g) << 2));
                *(float4*)&vB[0] = *(const float4*)(vr + (((qb0    ) ^ (t + 4) ^ g) << 2));
                *(float4*)&vB[4] = *(const float4*)(vr + (((qb0 + 1) ^ (t + 4) ^ g) << 2));
                #pragma unroll
                for (int kf = 0; kf < 8; kf++) {
                    mma_tf32(co[nf],
                             __float_as_uint(sf[kf][0]), __float_as_uint(sf[kf][1]),
                             __float_as_uint(sf[kf][2]), __float_as_uint(sf[kf][3]),
                             __float_as_uint(vA[kf]),    __float_as_uint(vB[kf]));
                }
            }
        }

        rs0 += __shfl_xor_sync(0xffffffffu, rs0, 1);
        rs0 += __shfl_xor_sync(0xffffffffu, rs0, 2);
        rs1 += __shfl_xor_sync(0xffffffffu, rs1, 1);
        rs1 += __shfl_xor_sync(0xffffffffu, rs1, 2);
        float inv0 = 1.0f / rs0;
        float inv1 = 1.0f / rs1;

        #pragma unroll
        for (int nf = 0; nf < 4; nf++) {
            int col = head * 32 + nf*8 + 2*t;
            float2 o0 = make_float2(to_tf32(co[nf][0] * inv0), to_tf32(co[nf][1] * inv0));
            float2 o1 = make_float2(to_tf32(co[nf][2] * inv1), to_tf32(co[nf][3] * inv1));
            *(float2*)&obase[(size_t)(mrow + g    ) * 256 + col] = o0;
            *(float2*)&obase[(size_t)(mrow + g + 8) * 256 + col] = o1;
        }
    }
}

// ============================================================
// Kernel 4: proj GEMM + bias + residual + coalesced scatter
// ============================================================
__global__ __launch_bounds__(256) void gemm_proj_mma(const float* __restrict__ bias,
                                                     float* __restrict__ out)
{
    __shared__ float smem_all[2 * 2 * 128 * 36];
    float (*As)[128][36] = (float (*)[128][36])smem_all;
    float (*Bs)[128][36] = (float (*)[128][36])(smem_all + 2 * 128 * 36);
    float (*Cs)[130]     = (float (*)[130])smem_all;

    int tid  = threadIdx.x;
    int lane = tid & 31, warp = tid >> 5;
    int g = lane >> 2, t = lane & 3;
    int wm = (warp & 1) * 64;
    int wn = (warp >> 1) * 32;

    const float* Ab = g_att   + (size_t)blockIdx.y * 128 * 256;
    const float* Bb = g_wproj + (size_t)blockIdx.x * 128 * 256;

    int r0 = tid >> 3;
    int c4 = (tid & 7) * 4;

    stage_load(As[0], Bs[0], Ab, Bb, r0, c4);
    CP_COMMIT;

    float c[4][4][4] = {};

    for (int it = 0; it < 8; it++) {
        if (it < 7)
            stage_load(As[(it+1)&1], Bs[(it+1)&1], Ab + (it+1)*32, Bb + (it+1)*32, r0, c4);
        CP_COMMIT;
        CP_WAIT1;
        __syncthreads();
        int s = it & 1;
        #pragma unroll
        for (int ks = 0; ks < 4; ks++) {
            int k0 = ks * 8;
            uint32_t bf[4][2];
            #pragma unroll
            for (int j = 0; j < 4; j++) {
                bf[j][0] = __float_as_uint(Bs[s][wn + j*8 + g][k0 + t]);
                bf[j][1] = __float_as_uint(Bs[s][wn + j*8 + g][k0 + t + 4]);
            }
            #pragma unroll
            for (int m = 0; m < 4; m++) {
                int rb = wm + m*16;
                uint32_t a0 = __float_as_uint(As[s][rb + g    ][k0 + t    ]);
                uint32_t a1 = __float_as_uint(As[s][rb + g + 8][k0 + t    ]);
                uint32_t a2 = __float_as_uint(As[s][rb + g    ][k0 + t + 4]);
                uint32_t a3 = __float_as_uint(As[s][rb + g + 8][k0 + t + 4]);
                #pragma unroll
                for (int j = 0; j < 4; j++)
                    mma_tf32(c[m][j], a0, a1, a2, a3, bf[j][0], bf[j][1]);
            }
        }
        __syncthreads();
    }

    int nbase = blockIdx.x * 128;
    #pragma unroll
    for (int m = 0; m < 4; m++) {
        int rl = wm + m*16 + g;
        #pragma unroll
        for (int j = 0; j < 4; j++) {
            int cl = wn + j*8 + 2*t;
            float2 bv = *(const float2*)&bias[nbase + cl];
            *(float2*)&Cs[rl    ][cl] = make_float2(c[m][j][0] + bv.x, c[m][j][1] + bv.y);
            *(float2*)&Cs[rl + 8][cl] = make_float2(c[m][j][2] + bv.x, c[m][j][3] + bv.y);
        }
    }
    __syncthreads();

    int by   = blockIdx.y;
    int n    = by >> 1;
    int half = by & 1;
    int b  = n >> 6, hi = (n >> 3) & 7, wi = n & 7;

    int cc  = tid & 127;
    int trh = tid >> 7;
    #pragma unroll
    for (int tr2 = 0; tr2 < 8; tr2++) {
        int tr = tr2 * 2 + trh;
        int t2 = tr >> 3, r = tr & 7;
        int l0 = t2 * 64 + r * 8;
        int t_full = half * 2 + t2;
        int bt = b * 4 + t_full;
        int h  = hi * 8 + r;
        int col = nbase + cc;
        size_t m0 = (size_t)by * 128 + l0;
        size_t oaddr = (((size_t)bt * 256 + col) * 64 + h) * 64 + wi * 8;
        #pragma unroll
        for (int j = 0; j < 2; j++) {
            float4 v;
            v.x = Cs[l0 + 4*j + 0][cc] + g_xw[(m0 + 4*j + 0) * 256 + col];
            v.y = Cs[l0 + 4*j + 1][cc] + g_xw[(m0 + 4*j + 1) * 256 + col];
            v.z = Cs[l0 + 4*j + 2][cc] + g_xw[(m0 + 4*j + 2) * 256 + col];
            v.w = Cs[l0 + 4*j + 3][cc] + g_xw[(m0 + 4*j + 3) * 256 + col];
            *(float4*)&out[oaddr + 4*j] = v;
        }
    }
}

// ============================================================
extern "C" void kernel_launch(void* const* d_in, const int* in_sizes, int n_in,
                              void* d_out, int out_size)
{
    const float* x      = (const float*)d_in[0];
    const float* w_qkv  = (const float*)d_in[1];
    const float* b_qkv  = (const float*)d_in[2];
    const float* w_proj = (const float*)d_in[3];
    const float* b_proj = (const float*)d_in[4];
    const float* gamma  = (const float*)d_in[5];
    const float* beta   = (const float*)d_in[6];
    float* out = (float*)d_out;

    prep_weights<<<768, 256>>>(w_qkv, w_proj);
    ln_gather_kernel<<<512, 256>>>(x, gamma, beta);
    gemm_qkv_mma<<<dim3(6, 256), 256>>>(b_qkv);
    attn_mma<<<NWIN * 8, 128>>>();
    gemm_proj_mma<<<dim3(2, 256), 256>>>(b_proj, out);
}

// round 7
// speedup vs baseline: 1.2551x; 1.2551x over previous
#include <cuda_runtime.h>
#include <math.h>
#include <stdint.h>

#define CCH   256
#define TT      4
#define HH     64
#define WWID   64
#define NWIN  128
#define MTOT  (NWIN*256)
#define ATT_SCALE 0.1767766952966369f
#define LOG2E     1.4426950408889634f

// -------- global scratch --------
__device__ float g_xw [MTOT * CCH];
__device__ float g_xn [MTOT * CCH];          // tf32-rounded LN output
__device__ float g_qkv[MTOT * 3 * CCH];      // q: scaled(*log2e)+tf32+d-permuted, k: tf32+d-permuted, v: tf32
__device__ float g_att[MTOT * CCH];          // tf32-rounded attention output
__device__ float g_wqkv[768 * 256];          // tf32-rounded weights
__device__ float g_wproj[256 * 256];

__device__ __forceinline__ float to_tf32(float x) {
    float r;
    asm("cvt.rna.tf32.f32 %0, %1;" : "=f"(r) : "f"(x));
    return r;
}

__device__ __forceinline__ float ex2_approx(float x) {
    float r;
    asm("ex2.approx.f32 %0, %1;" : "=f"(r) : "f"(x));
    return r;
}

__device__ __forceinline__ void mma_tf32(float* c,
                                         uint32_t a0, uint32_t a1, uint32_t a2, uint32_t a3,
                                         uint32_t b0, uint32_t b1) {
    asm volatile("mma.sync.aligned.m16n8k8.row.col.f32.tf32.tf32.f32 "
                 "{%0,%1,%2,%3}, {%4,%5,%6,%7}, {%8,%9}, {%0,%1,%2,%3};"
                 : "+f"(c[0]), "+f"(c[1]), "+f"(c[2]), "+f"(c[3])
                 : "r"(a0), "r"(a1), "r"(a2), "r"(a3), "r"(b0), "r"(b1));
}

__device__ __forceinline__ void cpasync16(uint32_t dst, const void* src) {
    asm volatile("cp.async.ca.shared.global [%0], [%1], 16;\n" :: "r"(dst), "l"(src));
}
#define CP_COMMIT asm volatile("cp.async.commit_group;\n" ::: "memory")
#define CP_WAIT1  asm volatile("cp.async.wait_group 1;\n" ::: "memory")
#define CP_WAIT0  asm volatile("cp.async.wait_group 0;\n" ::: "memory")

// ============================================================
// Kernel 0: weight prep (fp32 -> tf32-rounded copies)
// ============================================================
__global__ void prep_weights(const float* __restrict__ wq, const float* __restrict__ wp)
{
    int i = blockIdx.x * blockDim.x + threadIdx.x;
    if (i < 768 * 256)  g_wqkv[i]  = to_tf32(wq[i]);
    if (i < 256 * 256)  g_wproj[i] = to_tf32(wp[i]);
}

// ============================================================
// Kernel 1: coalesced gather + LayerNorm
// ============================================================
__global__ __launch_bounds__(256) void ln_gather_kernel(const float* __restrict__ x,
                                                        const float* __restrict__ gamma,
                                                        const float* __restrict__ beta)
{
    __shared__ float tile[256][65];
    __shared__ float rsum[4][64], rsq[4][64];
    __shared__ float mus[64], rstds[64];

    int bx  = blockIdx.x;
    int bt  = bx >> 6;
    int h   = bx & 63;
    int tid = threadIdx.x;

    const float* slice = x + ((size_t)bt * 256) * 4096 + h * 64;

    int cl = tid >> 4;
    int w4 = (tid & 15) * 4;
    #pragma unroll
    for (int it = 0; it < 16; it++) {
        int c = it * 16 + cl;
        float4 v = *(const float4*)(slice + (size_t)c * 4096 + w4);
        tile[c][w4 + 0] = v.x; tile[c][w4 + 1] = v.y;
        tile[c][w4 + 2] = v.z; tile[c][w4 + 3] = v.w;
    }
    __syncthreads();

    {
        int w = tid & 63, part = tid >> 6;
        float s = 0.f, q = 0.f;
        #pragma unroll
        for (int i = 0; i < 64; i++) {
            float v = tile[part * 64 + i][w];
            s += v; q += v * v;
        }
        rsum[part][w] = s; rsq[part][w] = q;
    }
    __syncthreads();
    if (tid < 64) {
        float tot = rsum[0][tid] + rsum[1][tid] + rsum[2][tid] + rsum[3][tid];
        float tq  = rsq[0][tid]  + rsq[1][tid]  + rsq[2][tid]  + rsq[3][tid];
        float mu  = tot * (1.0f / 256.0f);
        float var = tq * (1.0f / 256.0f) - mu * mu;
        mus[tid]  = mu;
        rstds[tid] = rsqrtf(var + 1e-5f);
    }
    __syncthreads();

    int c = tid;
    float gm = gamma[c], be = beta[c];
    int b  = bt >> 2, t = bt & 3;
    int hi = h >> 3, r = h & 7;
    int nbase = b * 64 + hi * 8;
    int lbase = t * 64 + r * 8;
    #pragma unroll 8
    for (int w = 0; w < 64; w++) {
        int n = nbase + (w >> 3);
        int l = lbase + (w & 7);
        size_t m = (size_t)n * 256 + l;
        float val = tile[c][w];
        float xn  = (val - mus[w]) * rstds[w] * gm + be;
        g_xw[m * 256 + c] = val;
        g_xn[m * 256 + c] = to_tf32(xn);
    }
}

// ============================================================
// cp.async stage loader for 128x32 tiles (pitch 36)
// ============================================================
__device__ __forceinline__ void stage_load(float (*As)[36], float (*Bs)[36],
                                           const float* Ag, const float* Bg,
                                           int r0, int c4)
{
    #pragma unroll
    for (int i = 0; i < 4; i++) {
        uint32_t da = (uint32_t)__cvta_generic_to_shared(&As[r0 + 32*i][c4]);
        uint32_t db = (uint32_t)__cvta_generic_to_shared(&Bs[r0 + 32*i][c4]);
        cpasync16(da, Ag + (size_t)(r0 + 32*i) * 256 + c4);
        cpasync16(db, Bg + (size_t)(r0 + 32*i) * 256 + c4);
    }
}

// ============================================================
// Kernel 2: QKV GEMM.  Epilogue: q scaled by ATT_SCALE*LOG2E,
// q and k written d-permuted (within head: p = (d&3)*8 + d>>2).
// ============================================================
__global__ __launch_bounds__(256) void gemm_qkv_mma(const float* __restrict__ bias)
{
    __shared__ float As[2][128][36];
    __shared__ float Bs[2][128][36];

    int tid  = threadIdx.x;
    int lane = tid & 31, warp = tid >> 5;
    int g = lane >> 2, t = lane & 3;
    int wm = (warp & 1) * 64;
    int wn = (warp >> 1) * 32;

    const float* Ab = g_xn   + (size_t)blockIdx.y * 128 * 256;
    const float* Bb = g_wqkv + (size_t)blockIdx.x * 128 * 256;

    int r0 = tid >> 3;
    int c4 = (tid & 7) * 4;

    stage_load(As[0], Bs[0], Ab, Bb, r0, c4);
    CP_COMMIT;

    float c[4][4][4] = {};

    for (int it = 0; it < 8; it++) {
        if (it < 7)
            stage_load(As[(it+1)&1], Bs[(it+1)&1], Ab + (it+1)*32, Bb + (it+1)*32, r0, c4);
        CP_COMMIT;
        CP_WAIT1;
        __syncthreads();
        int s = it & 1;
        #pragma unroll
        for (int ks = 0; ks < 4; ks++) {
            int k0 = ks * 8;
            uint32_t bf[4][2];
            #pragma unroll
            for (int j = 0; j < 4; j++) {
                bf[j][0] = __float_as_uint(Bs[s][wn + j*8 + g][k0 + t]);
                bf[j][1] = __float_as_uint(Bs[s][wn + j*8 + g][k0 + t + 4]);
            }
            #pragma unroll
            for (int m = 0; m < 4; m++) {
                int rb = wm + m*16;
                uint32_t a0 = __float_as_uint(As[s][rb + g    ][k0 + t    ]);
                uint32_t a1 = __float_as_uint(As[s][rb + g + 8][k0 + t    ]);
                uint32_t a2 = __float_as_uint(As[s][rb + g    ][k0 + t + 4]);
                uint32_t a3 = __float_as_uint(As[s][rb + g + 8][k0 + t + 4]);
                #pragma unroll
                for (int j = 0; j < 4; j++)
                    mma_tf32(c[m][j], a0, a1, a2, a3, bf[j][0], bf[j][1]);
            }
        }
        __syncthreads();
    }

    float sc = (blockIdx.x < 2) ? ATT_SCALE * LOG2E : 1.0f;
    bool permute = (blockIdx.x < 4);   // q and k blocks

    int mbase = blockIdx.y * 128 + wm;
    int nbase = blockIdx.x * 128 + wn;
    #pragma unroll
    for (int m = 0; m < 4; m++) {
        int row0 = mbase + m*16 + g;
        #pragma unroll
        for (int j = 0; j < 4; j++) {
            int col = nbase + j*8 + 2*t;
            float2 bv = *(const float2*)&bias[col];
            float v00 = to_tf32((c[m][j][0] + bv.x) * sc);
            float v01 = to_tf32((c[m][j][1] + bv.y) * sc);
            float v10 = to_tf32((c[m][j][2] + bv.x) * sc);
            float v11 = to_tf32((c[m][j][3] + bv.y) * sc);
            if (permute) {
                int b32 = col & ~31;
                int d0  = col & 31, d1 = d0 + 1;
                int p0  = ((d0 & 3) << 3) + (d0 >> 2);
                int p1  = ((d1 & 3) << 3) + (d1 >> 2);
                g_qkv[(size_t)row0       * 768 + b32 + p0] = v00;
                g_qkv[(size_t)row0       * 768 + b32 + p1] = v01;
                g_qkv[(size_t)(row0 + 8) * 768 + b32 + p0] = v10;
                g_qkv[(size_t)(row0 + 8) * 768 + b32 + p1] = v11;
            } else {
                *(float2*)&g_qkv[(size_t)row0       * 768 + col] = make_float2(v00, v01);
                *(float2*)&g_qkv[(size_t)(row0 + 8) * 768 + col] = make_float2(v10, v11);
            }
        }
    }
}

// ============================================================
// Kernel 3: tensor-core attention, fragment-major operands.
// One block per (window, head), 8 warps x 2 m-tiles.
// Ks: 256 keys x 32 d (d-permuted), xor-swizzled (chunk ^ key&7).
// Vt: 32 d x 256 keys' (keyp = (key%8)*32 + key/8),
//     swizzle q' = q ^ (q>>3) ^ ((d&1)<<2) ^ (d>>2) — conflict-free
//     for both mainloop reads and transpose writes.
// ============================================================
__global__ __launch_bounds__(256) void attn_mma()
{
    __shared__ float Ks[256 * 32];
    __shared__ float Vt[32 * 256];

    int win  = blockIdx.x >> 3;
    int head = blockIdx.x & 7;
    int tid  = threadIdx.x;
    int lane = tid & 31, warp = tid >> 5;
    int g = lane >> 2, t = lane & 3;
    bool odd = t & 1;
    int srcA = (lane & ~3) | (t >> 1);
    int srcB = srcA + 2;

    const float* base  = g_qkv + (size_t)win * 256 * 768 + head * 32;
    float*       obase = g_att + (size_t)win * 256 * 256;

    int keyl = tid >> 3;          // 0..31
    int qc   = tid & 7;           // chunk 0..7

    // --- K via cp.async into swizzled chunks ---
    #pragma unroll
    for (int it = 0; it < 8; it++) {
        int key = it * 32 + keyl;
        int qsw = qc ^ (key & 7);
        uint32_t dst = (uint32_t)__cvta_generic_to_shared(&Ks[key * 32 + qsw * 4]);
        cpasync16(dst, base + (size_t)key * 768 + 256 + qc * 4);
    }
    CP_COMMIT;

    // --- V transpose into swizzled Vt ---
    int d4 = qc * 4;
    #pragma unroll
    for (int it = 0; it < 8; it++) {
        int key = it * 32 + keyl;
        float4 v = *(const float4*)(base + (size_t)key * 768 + 512 + d4);
        int keyp = (key & 7) * 32 + (key >> 3);
        int q  = keyp >> 2, lo = keyp & 3;
        int qh3 = q >> 3;
        // d = d4 + i;  swizzle c(d) = ((d&1)<<2) ^ (d>>2);  d>>2 = qc
        Vt[(d4+0)*256 + ((q ^ qh3 ^ 0 ^ qc) << 2) + lo] = v.x;
        Vt[(d4+1)*256 + ((q ^ qh3 ^ 4 ^ qc) << 2) + lo] = v.y;
        Vt[(d4+2)*256 + ((q ^ qh3 ^ 0 ^ qc) << 2) + lo] = v.z;
        Vt[(d4+3)*256 + ((q ^ qh3 ^ 4 ^ qc) << 2) + lo] = v.w;
    }
    CP_WAIT0;
    __syncthreads();

    #pragma unroll
    for (int mt = 0; mt < 2; mt++) {
        int mrow = (mt * 8 + warp) * 16;

        // Q fragments: 32B-aligned full-sector LDG.128 (d-permuted layout)
        float QG[8], QH[8];
        {
            const float* qp = base + (size_t)mrow * 768 + t * 8;
            *(float4*)&QG[0] = *(const float4*)(qp + (size_t)g * 768);
            *(float4*)&QG[4] = *(const float4*)(qp + (size_t)g * 768 + 4);
            *(float4*)&QH[0] = *(const float4*)(qp + (size_t)(g + 8) * 768);
            *(float4*)&QH[4] = *(const float4*)(qp + (size_t)(g + 8) * 768 + 4);
        }

        float rs0 = 0.f, rs1 = 0.f;
        float co[4][4] = {};

        #pragma unroll
        for (int ch = 0; ch < 4; ch++) {
            int kb = ch * 64;

            // ---- S = Q K^T chunk (16 x 64) ----
            float sf[8][4];
            #pragma unroll
            for (int nf = 0; nf < 8; nf++) { sf[nf][0]=0.f; sf[nf][1]=0.f; sf[nf][2]=0.f; sf[nf][3]=0.f; }
            #pragma unroll
            for (int nf = 0; nf < 8; nf++) {
                int key = kb + nf * 8 + g;
                const float* kr = &Ks[key * 32];
                float kbuf[8];
                *(float4*)&kbuf[0] = *(const float4*)(kr + (((2*t    ) ^ g) << 2));
                *(float4*)&kbuf[4] = *(const float4*)(kr + (((2*t + 1) ^ g) << 2));
                #pragma unroll
                for (int kf = 0; kf < 4; kf++) {
                    mma_tf32(sf[nf],
                             __float_as_uint(QG[2*kf]),   __float_as_uint(QH[2*kf]),
                             __float_as_uint(QG[2*kf+1]), __float_as_uint(QH[2*kf+1]),
                             __float_as_uint(kbuf[2*kf]), __float_as_uint(kbuf[2*kf+1]));
                }
            }

            // ---- exp2 + rowsum + C-frag -> A-frag (quad shuffles) ----
            #pragma unroll
            for (int nf = 0; nf < 8; nf++) {
                float e0 = ex2_approx(sf[nf][0]);
                float e1 = ex2_approx(sf[nf][1]);
                float e2 = ex2_approx(sf[nf][2]);
                float e3 = ex2_approx(sf[nf][3]);
                rs0 += e0 + e1;
                rs1 += e2 + e3;
                uint32_t u0 = __float_as_uint(e0);
                uint32_t u1 = __float_as_uint(e1);
                uint32_t u2 = __float_as_uint(e2);
                uint32_t u3 = __float_as_uint(e3);
                uint32_t x0 = __shfl_sync(0xffffffffu, u0, srcA);
                uint32_t x1 = __shfl_sync(0xffffffffu, u1, srcA);
                uint32_t y0 = __shfl_sync(0xffffffffu, u0, srcB);
                uint32_t y1 = __shfl_sync(0xffffffffu, u1, srcB);
                uint32_t z0 = __shfl_sync(0xffffffffu, u2, srcA);
                uint32_t z1 = __shfl_sync(0xffffffffu, u3, srcA);
                uint32_t w0 = __shfl_sync(0xffffffffu, u2, srcB);
                uint32_t w1 = __shfl_sync(0xffffffffu, u3, srcB);
                sf[nf][0] = __uint_as_float(odd ? x1 : x0);
                sf[nf][2] = __uint_as_float(odd ? y1 : y0);
                sf[nf][1] = __uint_as_float(odd ? z1 : z0);
                sf[nf][3] = __uint_as_float(odd ? w1 : w0);
            }

            // ---- O += P V (fragment-major swizzled Vt reads) ----
            #pragma unroll
            for (int nf = 0; nf < 4; nf++) {
                int row = nf * 8 + g;
                int csw = ((g & 1) << 2) ^ (row >> 2);
                const float* vr = &Vt[row * 256];
                float vA[8], vB[8];
                int qa0 = t*8 + ch*2;           // q>>3 = t
                int qb0 = (t+4)*8 + ch*2;       // q>>3 = t+4
                *(float4*)&vA[0] = *(const float4*)(vr + (((qa0    ) ^ t       ^ csw) << 2));
                *(float4*)&vA[4] = *(const float4*)(vr + (((qa0 + 1) ^ t       ^ csw) << 2));
                *(float4*)&vB[0] = *(const float4*)(vr + (((qb0    ) ^ (t + 4) ^ csw) << 2));
                *(float4*)&vB[4] = *(const float4*)(vr + (((qb0 + 1) ^ (t + 4) ^ csw) << 2));
                #pragma unroll
                for (int kf = 0; kf < 8; kf++) {
                    mma_tf32(co[nf],
                             __float_as_uint(sf[kf][0]), __float_as_uint(sf[kf][1]),
                             __float_as_uint(sf[kf][2]), __float_as_uint(sf[kf][3]),
                             __float_as_uint(vA[kf]),    __float_as_uint(vB[kf]));
                }
            }
        }

        rs0 += __shfl_xor_sync(0xffffffffu, rs0, 1);
        rs0 += __shfl_xor_sync(0xffffffffu, rs0, 2);
        rs1 += __shfl_xor_sync(0xffffffffu, rs1, 1);
        rs1 += __shfl_xor_sync(0xffffffffu, rs1, 2);
        float inv0 = 1.0f / rs0;
        float inv1 = 1.0f / rs1;

        #pragma unroll
        for (int nf = 0; nf < 4; nf++) {
            int col = head * 32 + nf*8 + 2*t;
            float2 o0 = make_float2(to_tf32(co[nf][0] * inv0), to_tf32(co[nf][1] * inv0));
            float2 o1 = make_float2(to_tf32(co[nf][2] * inv1), to_tf32(co[nf][3] * inv1));
            *(float2*)&obase[(size_t)(mrow + g    ) * 256 + col] = o0;
            *(float2*)&obase[(size_t)(mrow + g + 8) * 256 + col] = o1;
        }
    }
}

// ============================================================
// Kernel 4: proj GEMM + bias + residual + coalesced scatter
// ============================================================
__global__ __launch_bounds__(256) void gemm_proj_mma(const float* __restrict__ bias,
                                                     float* __restrict__ out)
{
    __shared__ float smem_all[2 * 2 * 128 * 36];
    float (*As)[128][36] = (float (*)[128][36])smem_all;
    float (*Bs)[128][36] = (float (*)[128][36])(smem_all + 2 * 128 * 36);
    float (*Cs)[130]     = (float (*)[130])smem_all;

    int tid  = threadIdx.x;
    int lane = tid & 31, warp = tid >> 5;
    int g = lane >> 2, t = lane & 3;
    int wm = (warp & 1) * 64;
    int wn = (warp >> 1) * 32;

    const float* Ab = g_att   + (size_t)blockIdx.y * 128 * 256;
    const float* Bb = g_wproj + (size_t)blockIdx.x * 128 * 256;

    int r0 = tid >> 3;
    int c4 = (tid & 7) * 4;

    stage_load(As[0], Bs[0], Ab, Bb, r0, c4);
    CP_COMMIT;

    float c[4][4][4] = {};

    for (int it = 0; it < 8; it++) {
        if (it < 7)
            stage_load(As[(it+1)&1], Bs[(it+1)&1], Ab + (it+1)*32, Bb + (it+1)*32, r0, c4);
        CP_COMMIT;
        CP_WAIT1;
        __syncthreads();
        int s = it & 1;
        #pragma unroll
        for (int ks = 0; ks < 4; ks++) {
            int k0 = ks * 8;
            uint32_t bf[4][2];
            #pragma unroll
            for (int j = 0; j < 4; j++) {
                bf[j][0] = __float_as_uint(Bs[s][wn + j*8 + g][k0 + t]);
                bf[j][1] = __float_as_uint(Bs[s][wn + j*8 + g][k0 + t + 4]);
            }
            #pragma unroll
            for (int m = 0; m < 4; m++) {
                int rb = wm + m*16;
                uint32_t a0 = __float_as_uint(As[s][rb + g    ][k0 + t    ]);
                uint32_t a1 = __float_as_uint(As[s][rb + g + 8][k0 + t    ]);
                uint32_t a2 = __float_as_uint(As[s][rb + g    ][k0 + t + 4]);
                uint32_t a3 = __float_as_uint(As[s][rb + g + 8][k0 + t + 4]);
                #pragma unroll
                for (int j = 0; j < 4; j++)
                    mma_tf32(c[m][j], a0, a1, a2, a3, bf[j][0], bf[j][1]);
            }
        }
        __syncthreads();
    }

    int nbase = blockIdx.x * 128;
    #pragma unroll
    for (int m = 0; m < 4; m++) {
        int rl = wm + m*16 + g;
        #pragma unroll
        for (int j = 0; j < 4; j++) {
            int cl = wn + j*8 + 2*t;
            float2 bv = *(const float2*)&bias[nbase + cl];
            *(float2*)&Cs[rl    ][cl] = make_float2(c[m][j][0] + bv.x, c[m][j][1] + bv.y);
            *(float2*)&Cs[rl + 8][cl] = make_float2(c[m][j][2] + bv.x, c[m][j][3] + bv.y);
        }
    }
    __syncthreads();

    int by   = blockIdx.y;
    int n    = by >> 1;
    int half = by & 1;
    int b  = n >> 6, hi = (n >> 3) & 7, wi = n & 7;

    int cc  = tid & 127;
    int trh = tid >> 7;
    #pragma unroll
    for (int tr2 = 0; tr2 < 8; tr2++) {
        int tr = tr2 * 2 + trh;
        int t2 = tr >> 3, r = tr & 7;
        int l0 = t2 * 64 + r * 8;
        int t_full = half * 2 + t2;
        int bt = b * 4 + t_full;
        int h  = hi * 8 + r;
        int col = nbase + cc;
        size_t m0 = (size_t)by * 128 + l0;
        size_t oaddr = (((size_t)bt * 256 + col) * 64 + h) * 64 + wi * 8;
        #pragma unroll
        for (int j = 0; j < 2; j++) {
            float4 v;
            v.x = Cs[l0 + 4*j + 0][cc] + g_xw[(m0 + 4*j + 0) * 256 + col];
            v.y = Cs[l0 + 4*j + 1][cc] + g_xw[(m0 + 4*j + 1) * 256 + col];
            v.z = Cs[l0 + 4*j + 2][cc] + g_xw[(m0 + 4*j + 2) * 256 + col];
            v.w = Cs[l0 + 4*j + 3][cc] + g_xw[(m0 + 4*j + 3) * 256 + col];
            *(float4*)&out[oaddr + 4*j] = v;
        }
    }
}

// ============================================================
extern "C" void kernel_launch(void* const* d_in, const int* in_sizes, int n_in,
                              void* d_out, int out_size)
{
    const float* x      = (const float*)d_in[0];
    const float* w_qkv  = (const float*)d_in[1];
    const float* b_qkv  = (const float*)d_in[2];
    const float* w_proj = (const float*)d_in[3];
    const float* b_proj = (const float*)d_in[4];
    const float* gamma  = (const float*)d_in[5];
    const float* beta   = (const float*)d_in[6];
    float* out = (float*)d_out;

    prep_weights<<<768, 256>>>(w_qkv, w_proj);
    ln_gather_kernel<<<512, 256>>>(x, gamma, beta);
    gemm_qkv_mma<<<dim3(6, 256), 256>>>(b_qkv);
    attn_mma<<<NWIN * 8, 256>>>();
    gemm_proj_mma<<<dim3(2, 256), 256>>>(b_proj, out);
}

// round 8
// speedup vs baseline: 1.3461x; 1.0725x over previous
#include <cuda_runtime.h>
#include <math.h>
#include <stdint.h>

#define CCH   256
#define TT      4
#define HH     64
#define WWID   64
#define NWIN  128
#define MTOT  (NWIN*256)
#define ATT_SCALE 0.1767766952966369f
#define LOG2E     1.4426950408889634f

// -------- global scratch --------
__device__ float g_xw [MTOT * CCH];
__device__ float g_xn [MTOT * CCH];          // tf32-rounded LN output
__device__ float g_qkv[MTOT * 3 * CCH];      // q: scaled(*log2e)+tf32+d-permuted, k: tf32+d-permuted, v: tf32
__device__ float g_att[MTOT * CCH];          // tf32-rounded attention output
__device__ float g_wqkv[768 * 256];          // tf32-rounded weights
__device__ float g_wproj[256 * 256];

__device__ __forceinline__ float to_tf32(float x) {
    float r;
    asm("cvt.rna.tf32.f32 %0, %1;" : "=f"(r) : "f"(x));
    return r;
}

__device__ __forceinline__ float ex2_approx(float x) {
    float r;
    asm("ex2.approx.f32 %0, %1;" : "=f"(r) : "f"(x));
    return r;
}

__device__ __forceinline__ void mma_tf32(float* c,
                                         uint32_t a0, uint32_t a1, uint32_t a2, uint32_t a3,
                                         uint32_t b0, uint32_t b1) {
    asm volatile("mma.sync.aligned.m16n8k8.row.col.f32.tf32.tf32.f32 "
                 "{%0,%1,%2,%3}, {%4,%5,%6,%7}, {%8,%9}, {%0,%1,%2,%3};"
                 : "+f"(c[0]), "+f"(c[1]), "+f"(c[2]), "+f"(c[3])
                 : "r"(a0), "r"(a1), "r"(a2), "r"(a3), "r"(b0), "r"(b1));
}

__device__ __forceinline__ void cpasync16(uint32_t dst, const void* src) {
    asm volatile("cp.async.ca.shared.global [%0], [%1], 16;\n" :: "r"(dst), "l"(src));
}
#define CP_COMMIT asm volatile("cp.async.commit_group;\n" ::: "memory")
#define CP_WAIT1  asm volatile("cp.async.wait_group 1;\n" ::: "memory")
#define CP_WAIT0  asm volatile("cp.async.wait_group 0;\n" ::: "memory")

// ============================================================
// Kernel 0: weight prep (fp32 -> tf32-rounded copies)
// ============================================================
__global__ void prep_weights(const float* __restrict__ wq, const float* __restrict__ wp)
{
    int i = blockIdx.x * blockDim.x + threadIdx.x;
    if (i < 768 * 256)  g_wqkv[i]  = to_tf32(wq[i]);
    if (i < 256 * 256)  g_wproj[i] = to_tf32(wp[i]);
}

// ============================================================
// Kernel 1: coalesced gather + LayerNorm
// ============================================================
__global__ __launch_bounds__(256) void ln_gather_kernel(const float* __restrict__ x,
                                                        const float* __restrict__ gamma,
                                                        const float* __restrict__ beta)
{
    __shared__ float tile[256][65];
    __shared__ float rsum[4][64], rsq[4][64];
    __shared__ float mus[64], rstds[64];

    int bx  = blockIdx.x;
    int bt  = bx >> 6;
    int h   = bx & 63;
    int tid = threadIdx.x;

    const float* slice = x + ((size_t)bt * 256) * 4096 + h * 64;

    int cl = tid >> 4;
    int w4 = (tid & 15) * 4;
    #pragma unroll
    for (int it = 0; it < 16; it++) {
        int c = it * 16 + cl;
        float4 v = *(const float4*)(slice + (size_t)c * 4096 + w4);
        tile[c][w4 + 0] = v.x; tile[c][w4 + 1] = v.y;
        tile[c][w4 + 2] = v.z; tile[c][w4 + 3] = v.w;
    }
    __syncthreads();

    {
        int w = tid & 63, part = tid >> 6;
        float s = 0.f, q = 0.f;
        #pragma unroll
        for (int i = 0; i < 64; i++) {
            float v = tile[part * 64 + i][w];
            s += v; q += v * v;
        }
        rsum[part][w] = s; rsq[part][w] = q;
    }
    __syncthreads();
    if (tid < 64) {
        float tot = rsum[0][tid] + rsum[1][tid] + rsum[2][tid] + rsum[3][tid];
        float tq  = rsq[0][tid]  + rsq[1][tid]  + rsq[2][tid]  + rsq[3][tid];
        float mu  = tot * (1.0f / 256.0f);
        float var = tq * (1.0f / 256.0f) - mu * mu;
        mus[tid]  = mu;
        rstds[tid] = rsqrtf(var + 1e-5f);
    }
    __syncthreads();

    int c = tid;
    float gm = gamma[c], be = beta[c];
    int b  = bt >> 2, t = bt & 3;
    int hi = h >> 3, r = h & 7;
    int nbase = b * 64 + hi * 8;
    int lbase = t * 64 + r * 8;
    #pragma unroll 8
    for (int w = 0; w < 64; w++) {
        int n = nbase + (w >> 3);
        int l = lbase + (w & 7);
        size_t m = (size_t)n * 256 + l;
        float val = tile[c][w];
        float xn  = (val - mus[w]) * rstds[w] * gm + be;
        g_xw[m * 256 + c] = val;
        g_xn[m * 256 + c] = to_tf32(xn);
    }
}

// ============================================================
// cp.async stage loader for 128x32 tiles (pitch 36)
// ============================================================
__device__ __forceinline__ void stage_load(float (*As)[36], float (*Bs)[36],
                                           const float* Ag, const float* Bg,
                                           int r0, int c4)
{
    #pragma unroll
    for (int i = 0; i < 4; i++) {
        uint32_t da = (uint32_t)__cvta_generic_to_shared(&As[r0 + 32*i][c4]);
        uint32_t db = (uint32_t)__cvta_generic_to_shared(&Bs[r0 + 32*i][c4]);
        cpasync16(da, Ag + (size_t)(r0 + 32*i) * 256 + c4);
        cpasync16(db, Bg + (size_t)(r0 + 32*i) * 256 + c4);
    }
}

// ============================================================
// Kernel 2: QKV GEMM.  Epilogue: q scaled by ATT_SCALE*LOG2E,
// q and k written d-permuted (within head: p = (d&3)*8 + d>>2).
// ============================================================
__global__ __launch_bounds__(256) void gemm_qkv_mma(const float* __restrict__ bias)
{
    __shared__ float As[2][128][36];
    __shared__ float Bs[2][128][36];

    int tid  = threadIdx.x;
    int lane = tid & 31, warp = tid >> 5;
    int g = lane >> 2, t = lane & 3;
    int wm = (warp & 1) * 64;
    int wn = (warp >> 1) * 32;

    const float* Ab = g_xn   + (size_t)blockIdx.y * 128 * 256;
    const float* Bb = g_wqkv + (size_t)blockIdx.x * 128 * 256;

    int r0 = tid >> 3;
    int c4 = (tid & 7) * 4;

    stage_load(As[0], Bs[0], Ab, Bb, r0, c4);
    CP_COMMIT;

    float c[4][4][4] = {};

    for (int it = 0; it < 8; it++) {
        if (it < 7)
            stage_load(As[(it+1)&1], Bs[(it+1)&1], Ab + (it+1)*32, Bb + (it+1)*32, r0, c4);
        CP_COMMIT;
        CP_WAIT1;
        __syncthreads();
        int s = it & 1;
        #pragma unroll
        for (int ks = 0; ks < 4; ks++) {
            int k0 = ks * 8;
            uint32_t bf[4][2];
            #pragma unroll
            for (int j = 0; j < 4; j++) {
                bf[j][0] = __float_as_uint(Bs[s][wn + j*8 + g][k0 + t]);
                bf[j][1] = __float_as_uint(Bs[s][wn + j*8 + g][k0 + t + 4]);
            }
            #pragma unroll
            for (int m = 0; m < 4; m++) {
                int rb = wm + m*16;
                uint32_t a0 = __float_as_uint(As[s][rb + g    ][k0 + t    ]);
                uint32_t a1 = __float_as_uint(As[s][rb + g + 8][k0 + t    ]);
                uint32_t a2 = __float_as_uint(As[s][rb + g    ][k0 + t + 4]);
                uint32_t a3 = __float_as_uint(As[s][rb + g + 8][k0 + t + 4]);
                #pragma unroll
                for (int j = 0; j < 4; j++)
                    mma_tf32(c[m][j], a0, a1, a2, a3, bf[j][0], bf[j][1]);
            }
        }
        __syncthreads();
    }

    float sc = (blockIdx.x < 2) ? ATT_SCALE * LOG2E : 1.0f;
    bool permute = (blockIdx.x < 4);   // q and k blocks

    int mbase = blockIdx.y * 128 + wm;
    int nbase = blockIdx.x * 128 + wn;
    #pragma unroll
    for (int m = 0; m < 4; m++) {
        int row0 = mbase + m*16 + g;
        #pragma unroll
        for (int j = 0; j < 4; j++) {
            int col = nbase + j*8 + 2*t;
            float2 bv = *(const float2*)&bias[col];
            float v00 = to_tf32((c[m][j][0] + bv.x) * sc);
            float v01 = to_tf32((c[m][j][1] + bv.y) * sc);
            float v10 = to_tf32((c[m][j][2] + bv.x) * sc);
            float v11 = to_tf32((c[m][j][3] + bv.y) * sc);
            if (permute) {
                int b32 = col & ~31;
                int d0  = col & 31, d1 = d0 + 1;
                int p0  = ((d0 & 3) << 3) + (d0 >> 2);
                int p1  = ((d1 & 3) << 3) + (d1 >> 2);
                g_qkv[(size_t)row0       * 768 + b32 + p0] = v00;
                g_qkv[(size_t)row0       * 768 + b32 + p1] = v01;
                g_qkv[(size_t)(row0 + 8) * 768 + b32 + p0] = v10;
                g_qkv[(size_t)(row0 + 8) * 768 + b32 + p1] = v11;
            } else {
                *(float2*)&g_qkv[(size_t)row0       * 768 + col] = make_float2(v00, v01);
                *(float2*)&g_qkv[(size_t)(row0 + 8) * 768 + col] = make_float2(v10, v11);
            }
        }
    }
}

// ============================================================
// Kernel 3: tensor-core attention, fragment-major operands.
// One block per (window, head), 8 warps x 2 m-tiles.
// __launch_bounds__(256, 2) caps regs at 128 -> 2 CTAs/SM.
// ============================================================
__global__ __launch_bounds__(256, 2) void attn_mma()
{
    __shared__ float Ks[256 * 32];
    __shared__ float Vt[32 * 256];

    int win  = blockIdx.x >> 3;
    int head = blockIdx.x & 7;
    int tid  = threadIdx.x;
    int lane = tid & 31, warp = tid >> 5;
    int g = lane >> 2, t = lane & 3;
    bool odd = t & 1;
    int srcA = (lane & ~3) | (t >> 1);
    int srcB = srcA + 2;

    const float* base  = g_qkv + (size_t)win * 256 * 768 + head * 32;
    float*       obase = g_att + (size_t)win * 256 * 256;

    int keyl = tid >> 3;          // 0..31
    int qc   = tid & 7;           // chunk 0..7

    // --- K via cp.async into swizzled chunks ---
    #pragma unroll
    for (int it = 0; it < 8; it++) {
        int key = it * 32 + keyl;
        int qsw = qc ^ (key & 7);
        uint32_t dst = (uint32_t)__cvta_generic_to_shared(&Ks[key * 32 + qsw * 4]);
        cpasync16(dst, base + (size_t)key * 768 + 256 + qc * 4);
    }
    CP_COMMIT;

    // --- V transpose into swizzled Vt ---
    int d4 = qc * 4;
    #pragma unroll
    for (int it = 0; it < 8; it++) {
        int key = it * 32 + keyl;
        float4 v = *(const float4*)(base + (size_t)key * 768 + 512 + d4);
        int keyp = (key & 7) * 32 + (key >> 3);
        int q  = keyp >> 2, lo = keyp & 3;
        int qh3 = q >> 3;
        Vt[(d4+0)*256 + ((q ^ qh3 ^ 0 ^ qc) << 2) + lo] = v.x;
        Vt[(d4+1)*256 + ((q ^ qh3 ^ 4 ^ qc) << 2) + lo] = v.y;
        Vt[(d4+2)*256 + ((q ^ qh3 ^ 0 ^ qc) << 2) + lo] = v.z;
        Vt[(d4+3)*256 + ((q ^ qh3 ^ 4 ^ qc) << 2) + lo] = v.w;
    }
    CP_WAIT0;
    __syncthreads();

    for (int mt = 0; mt < 2; mt++) {
        int mrow = (mt * 8 + warp) * 16;

        // Q fragments: 32B-aligned full-sector LDG.128 (d-permuted layout)
        float QG[8], QH[8];
        {
            const float* qp = base + (size_t)mrow * 768 + t * 8;
            *(float4*)&QG[0] = *(const float4*)(qp + (size_t)g * 768);
            *(float4*)&QG[4] = *(const float4*)(qp + (size_t)g * 768 + 4);
            *(float4*)&QH[0] = *(const float4*)(qp + (size_t)(g + 8) * 768);
            *(float4*)&QH[4] = *(const float4*)(qp + (size_t)(g + 8) * 768 + 4);
        }

        float rs0 = 0.f, rs1 = 0.f;
        float co[4][4] = {};

        #pragma unroll
        for (int ch = 0; ch < 4; ch++) {
            int kb = ch * 64;

            // ---- S = Q K^T chunk (16 x 64) ----
            float sf[8][4];
            #pragma unroll
            for (int nf = 0; nf < 8; nf++) { sf[nf][0]=0.f; sf[nf][1]=0.f; sf[nf][2]=0.f; sf[nf][3]=0.f; }
            #pragma unroll
            for (int nf = 0; nf < 8; nf++) {
                int key = kb + nf * 8 + g;
                const float* kr = &Ks[key * 32];
                float kbuf[8];
                *(float4*)&kbuf[0] = *(const float4*)(kr + (((2*t    ) ^ g) << 2));
                *(float4*)&kbuf[4] = *(const float4*)(kr + (((2*t + 1) ^ g) << 2));
                #pragma unroll
                for (int kf = 0; kf < 4; kf++) {
                    mma_tf32(sf[nf],
                             __float_as_uint(QG[2*kf]),   __float_as_uint(QH[2*kf]),
                             __float_as_uint(QG[2*kf+1]), __float_as_uint(QH[2*kf+1]),
                             __float_as_uint(kbuf[2*kf]), __float_as_uint(kbuf[2*kf+1]));
                }
            }

            // ---- exp2 + rowsum + C-frag -> A-frag (quad shuffles) ----
            #pragma unroll
            for (int nf = 0; nf < 8; nf++) {
                float e0 = ex2_approx(sf[nf][0]);
                float e1 = ex2_approx(sf[nf][1]);
                float e2 = ex2_approx(sf[nf][2]);
                float e3 = ex2_approx(sf[nf][3]);
                rs0 += e0 + e1;
                rs1 += e2 + e3;
                uint32_t u0 = __float_as_uint(e0);
                uint32_t u1 = __float_as_uint(e1);
                uint32_t u2 = __float_as_uint(e2);
                uint32_t u3 = __float_as_uint(e3);
                uint32_t x0 = __shfl_sync(0xffffffffu, u0, srcA);
                uint32_t x1 = __shfl_sync(0xffffffffu, u1, srcA);
                uint32_t y0 = __shfl_sync(0xffffffffu, u0, srcB);
                uint32_t y1 = __shfl_sync(0xffffffffu, u1, srcB);
                uint32_t z0 = __shfl_sync(0xffffffffu, u2, srcA);
                uint32_t z1 = __shfl_sync(0xffffffffu, u3, srcA);
                uint32_t w0 = __shfl_sync(0xffffffffu, u2, srcB);
                uint32_t w1 = __shfl_sync(0xffffffffu, u3, srcB);
                sf[nf][0] = __uint_as_float(odd ? x1 : x0);
                sf[nf][2] = __uint_as_float(odd ? y1 : y0);
                sf[nf][1] = __uint_as_float(odd ? z1 : z0);
                sf[nf][3] = __uint_as_float(odd ? w1 : w0);
            }

            // ---- O += P V (fragment-major swizzled Vt reads) ----
            #pragma unroll
            for (int nf = 0; nf < 4; nf++) {
                int row = nf * 8 + g;
                int csw = ((g & 1) << 2) ^ (row >> 2);
                const float* vr = &Vt[row * 256];
                float vA[8], vB[8];
                int qa0 = t*8 + ch*2;           // q>>3 = t
                int qb0 = (t+4)*8 + ch*2;       // q>>3 = t+4
                *(float4*)&vA[0] = *(const float4*)(vr + (((qa0    ) ^ t       ^ csw) << 2));
                *(float4*)&vA[4] = *(const float4*)(vr + (((qa0 + 1) ^ t       ^ csw) << 2));
                *(float4*)&vB[0] = *(const float4*)(vr + (((qb0    ) ^ (t + 4) ^ csw) << 2));
                *(float4*)&vB[4] = *(const float4*)(vr + (((qb0 + 1) ^ (t + 4) ^ csw) << 2));
                #pragma unroll
                for (int kf = 0; kf < 8; kf++) {
                    mma_tf32(co[nf],
                             __float_as_uint(sf[kf][0]), __float_as_uint(sf[kf][1]),
                             __float_as_uint(sf[kf][2]), __float_as_uint(sf[kf][3]),
                             __float_as_uint(vA[kf]),    __float_as_uint(vB[kf]));
                }
            }
        }

        rs0 += __shfl_xor_sync(0xffffffffu, rs0, 1);
        rs0 += __shfl_xor_sync(0xffffffffu, rs0, 2);
        rs1 += __shfl_xor_sync(0xffffffffu, rs1, 1);
        rs1 += __shfl_xor_sync(0xffffffffu, rs1, 2);
        float inv0 = 1.0f / rs0;
        float inv1 = 1.0f / rs1;

        #pragma unroll
        for (int nf = 0; nf < 4; nf++) {
            int col = head * 32 + nf*8 + 2*t;
            float2 o0 = make_float2(to_tf32(co[nf][0] * inv0), to_tf32(co[nf][1] * inv0));
            float2 o1 = make_float2(to_tf32(co[nf][2] * inv1), to_tf32(co[nf][3] * inv1));
            *(float2*)&obase[(size_t)(mrow + g    ) * 256 + col] = o0;
            *(float2*)&obase[(size_t)(mrow + g + 8) * 256 + col] = o1;
        }
    }
}

// ============================================================
// Kernel 4: proj GEMM + bias + residual + coalesced scatter
// ============================================================
__global__ __launch_bounds__(256) void gemm_proj_mma(const float* __restrict__ bias,
                                                     float* __restrict__ out)
{
    __shared__ float smem_all[2 * 2 * 128 * 36];
    float (*As)[128][36] = (float (*)[128][36])smem_all;
    float (*Bs)[128][36] = (float (*)[128][36])(smem_all + 2 * 128 * 36);
    float (*Cs)[130]     = (float (*)[130])smem_all;

    int tid  = threadIdx.x;
    int lane = tid & 31, warp = tid >> 5;
    int g = lane >> 2, t = lane & 3;
    int wm = (warp & 1) * 64;
    int wn = (warp >> 1) * 32;

    const float* Ab = g_att   + (size_t)blockIdx.y * 128 * 256;
    const float* Bb = g_wproj + (size_t)blockIdx.x * 128 * 256;

    int r0 = tid >> 3;
    int c4 = (tid & 7) * 4;

    stage_load(As[0], Bs[0], Ab, Bb, r0, c4);
    CP_COMMIT;

    float c[4][4][4] = {};

    for (int it = 0; it < 8; it++) {
        if (it < 7)
            stage_load(As[(it+1)&1], Bs[(it+1)&1], Ab + (it+1)*32, Bb + (it+1)*32, r0, c4);
        CP_COMMIT;
        CP_WAIT1;
        __syncthreads();
        int s = it & 1;
        #pragma unroll
        for (int ks = 0; ks < 4; ks++) {
            int k0 = ks * 8;
            uint32_t bf[4][2];
            #pragma unroll
            for (int j = 0; j < 4; j++) {
                bf[j][0] = __float_as_uint(Bs[s][wn + j*8 + g][k0 + t]);
                bf[j][1] = __float_as_uint(Bs[s][wn + j*8 + g][k0 + t + 4]);
            }
            #pragma unroll
            for (int m = 0; m < 4; m++) {
                int rb = wm + m*16;
                uint32_t a0 = __float_as_uint(As[s][rb + g    ][k0 + t    ]);
                uint32_t a1 = __float_as_uint(As[s][rb + g + 8][k0 + t    ]);
                uint32_t a2 = __float_as_uint(As[s][rb + g    ][k0 + t + 4]);
                uint32_t a3 = __float_as_uint(As[s][rb + g + 8][k0 + t + 4]);
                #pragma unroll
                for (int j = 0; j < 4; j++)
                    mma_tf32(c[m][j], a0, a1, a2, a3, bf[j][0], bf[j][1]);
            }
        }
        __syncthreads();
    }

    int nbase = blockIdx.x * 128;
    #pragma unroll
    for (int m = 0; m < 4; m++) {
        int rl = wm + m*16 + g;
        #pragma unroll
        for (int j = 0; j < 4; j++) {
            int cl = wn + j*8 + 2*t;
            float2 bv = *(const float2*)&bias[nbase + cl];
            *(float2*)&Cs[rl    ][cl] = make_float2(c[m][j][0] + bv.x, c[m][j][1] + bv.y);
            *(float2*)&Cs[rl + 8][cl] = make_float2(c[m][j][2] + bv.x, c[m][j][3] + bv.y);
        }
    }
    __syncthreads();

    int by   = blockIdx.y;
    int n    = by >> 1;
    int half = by & 1;
    int b  = n >> 6, hi = (n >> 3) & 7, wi = n & 7;

    int cc  = tid & 127;
    int trh = tid >> 7;
    #pragma unroll
    for (int tr2 = 0; tr2 < 8; tr2++) {
        int tr = tr2 * 2 + trh;
        int t2 = tr >> 3, r = tr & 7;
        int l0 = t2 * 64 + r * 8;
        int t_full = half * 2 + t2;
        int bt = b * 4 + t_full;
        int h  = hi * 8 + r;
        int col = nbase + cc;
        size_t m0 = (size_t)by * 128 + l0;
        size_t oaddr = (((size_t)bt * 256 + col) * 64 + h) * 64 + wi * 8;
        #pragma unroll
        for (int j = 0; j < 2; j++) {
            float4 v;
            v.x = Cs[l0 + 4*j + 0][cc] + g_xw[(m0 + 4*j + 0) * 256 + col];
            v.y = Cs[l0 + 4*j + 1][cc] + g_xw[(m0 + 4*j + 1) * 256 + col];
            v.z = Cs[l0 + 4*j + 2][cc] + g_xw[(m0 + 4*j + 2) * 256 + col];
            v.w = Cs[l0 + 4*j + 3][cc] + g_xw[(m0 + 4*j + 3) * 256 + col];
            *(float4*)&out[oaddr + 4*j] = v;
        }
    }
}

// ============================================================
extern "C" void kernel_launch(void* const* d_in, const int* in_sizes, int n_in,
                              void* d_out, int out_size)
{
    const float* x      = (const float*)d_in[0];
    const float* w_qkv  = (const float*)d_in[1];
    const float* b_qkv  = (const float*)d_in[2];
    const float* w_proj = (const float*)d_in[3];
    const float* b_proj = (const float*)d_in[4];
    const float* gamma  = (const float*)d_in[5];
    const float* beta   = (const float*)d_in[6];
    float* out = (float*)d_out;

    prep_weights<<<768, 256>>>(w_qkv, w_proj);
    ln_gather_kernel<<<512, 256>>>(x, gamma, beta);
    gemm_qkv_mma<<<dim3(6, 256), 256>>>(b_qkv);
    attn_mma<<<NWIN * 8, 256>>>();
    gemm_proj_mma<<<dim3(2, 256), 256>>>(b_proj, out);
}

// round 9
// speedup vs baseline: 1.5902x; 1.1813x over previous
#include <cuda_runtime.h>
#include <cuda_bf16.h>
#include <math.h>
#include <stdint.h>

#define CCH   256
#define TT      4
#define HH     64
#define WWID   64
#define NWIN  128
#define MTOT  (NWIN*256)
#define ATT_SCALE 0.1767766952966369f
#define LOG2E     1.4426950408889634f

// -------- global scratch --------
__device__ float          g_xw   [MTOT * CCH];       // residual (fp32)
__device__ __nv_bfloat16  g_xn_bf[MTOT * CCH];       // LN output (bf16)
__device__ float          g_qkv  [MTOT * 3 * CCH];   // fp32: q scaled(*log2e)+tf32+d-permuted, k tf32+d-permuted, v tf32
__device__ __nv_bfloat16  g_att_bf[MTOT * CCH];      // attention output (bf16)
__device__ __nv_bfloat16  g_wqkv_bf[768 * 256];
__device__ __nv_bfloat16  g_wproj_bf[256 * 256];

__device__ __forceinline__ float to_tf32(float x) {
    float r;
    asm("cvt.rna.tf32.f32 %0, %1;" : "=f"(r) : "f"(x));
    return r;
}

__device__ __forceinline__ float ex2_approx(float x) {
    float r;
    asm("ex2.approx.f32 %0, %1;" : "=f"(r) : "f"(x));
    return r;
}

// pack (lo, hi) floats into bf16x2 word: mem order [lo, hi]
__device__ __forceinline__ uint32_t pack_bf16x2(float lo, float hi) {
    uint32_t r;
    asm("cvt.rn.bf16x2.f32 %0, %1, %2;" : "=r"(r) : "f"(hi), "f"(lo));
    return r;
}

__device__ __forceinline__ void mma_tf32(float* c,
                                         uint32_t a0, uint32_t a1, uint32_t a2, uint32_t a3,
                                         uint32_t b0, uint32_t b1) {
    asm volatile("mma.sync.aligned.m16n8k8.row.col.f32.tf32.tf32.f32 "
                 "{%0,%1,%2,%3}, {%4,%5,%6,%7}, {%8,%9}, {%0,%1,%2,%3};"
                 : "+f"(c[0]), "+f"(c[1]), "+f"(c[2]), "+f"(c[3])
                 : "r"(a0), "r"(a1), "r"(a2), "r"(a3), "r"(b0), "r"(b1));
}

__device__ __forceinline__ void mma_bf16(float* c,
                                         uint32_t a0, uint32_t a1, uint32_t a2, uint32_t a3,
                                         uint32_t b0, uint32_t b1) {
    asm volatile("mma.sync.aligned.m16n8k16.row.col.f32.bf16.bf16.f32 "
                 "{%0,%1,%2,%3}, {%4,%5,%6,%7}, {%8,%9}, {%0,%1,%2,%3};"
                 : "+f"(c[0]), "+f"(c[1]), "+f"(c[2]), "+f"(c[3])
                 : "r"(a0), "r"(a1), "r"(a2), "r"(a3), "r"(b0), "r"(b1));
}

__device__ __forceinline__ void ldsm_x4(uint32_t& r0, uint32_t& r1, uint32_t& r2, uint32_t& r3,
                                        uint32_t addr) {
    asm volatile("ldmatrix.sync.aligned.m8n8.x4.shared.b16 {%0,%1,%2,%3}, [%4];"
                 : "=r"(r0), "=r"(r1), "=r"(r2), "=r"(r3) : "r"(addr));
}

__device__ __forceinline__ void cpasync16(uint32_t dst, const void* src) {
    asm volatile("cp.async.ca.shared.global [%0], [%1], 16;\n" :: "r"(dst), "l"(src));
}
#define CP_COMMIT asm volatile("cp.async.commit_group;\n" ::: "memory")
#define CP_WAIT1  asm volatile("cp.async.wait_group 1;\n" ::: "memory")
#define CP_WAIT0  asm volatile("cp.async.wait_group 0;\n" ::: "memory")

// ============================================================
// Kernel 0: weight prep (fp32 -> bf16 copies)
// ============================================================
__global__ void prep_weights(const float* __restrict__ wq, const float* __restrict__ wp)
{
    int i = blockIdx.x * blockDim.x + threadIdx.x;
    if (i < 768 * 256)  g_wqkv_bf[i]  = __float2bfloat16_rn(wq[i]);
    if (i < 256 * 256)  g_wproj_bf[i] = __float2bfloat16_rn(wp[i]);
}

// ============================================================
// Kernel 1: coalesced gather + LayerNorm (bf16 xn output)
// ============================================================
__global__ __launch_bounds__(256) void ln_gather_kernel(const float* __restrict__ x,
                                                        const float* __restrict__ gamma,
                                                        const float* __restrict__ beta)
{
    __shared__ float tile[256][65];
    __shared__ float rsum[4][64], rsq[4][64];
    __shared__ float mus[64], rstds[64];

    int bx  = blockIdx.x;
    int bt  = bx >> 6;
    int h   = bx & 63;
    int tid = threadIdx.x;

    const float* slice = x + ((size_t)bt * 256) * 4096 + h * 64;

    int cl = tid >> 4;
    int w4 = (tid & 15) * 4;
    #pragma unroll
    for (int it = 0; it < 16; it++) {
        int c = it * 16 + cl;
        float4 v = *(const float4*)(slice + (size_t)c * 4096 + w4);
        tile[c][w4 + 0] = v.x; tile[c][w4 + 1] = v.y;
        tile[c][w4 + 2] = v.z; tile[c][w4 + 3] = v.w;
    }
    __syncthreads();

    {
        int w = tid & 63, part = tid >> 6;
        float s = 0.f, q = 0.f;
        #pragma unroll
        for (int i = 0; i < 64; i++) {
            float v = tile[part * 64 + i][w];
            s += v; q += v * v;
        }
        rsum[part][w] = s; rsq[part][w] = q;
    }
    __syncthreads();
    if (tid < 64) {
        float tot = rsum[0][tid] + rsum[1][tid] + rsum[2][tid] + rsum[3][tid];
        float tq  = rsq[0][tid]  + rsq[1][tid]  + rsq[2][tid]  + rsq[3][tid];
        float mu  = tot * (1.0f / 256.0f);
        float var = tq * (1.0f / 256.0f) - mu * mu;
        mus[tid]  = mu;
        rstds[tid] = rsqrtf(var + 1e-5f);
    }
    __syncthreads();

    int c = tid;
    float gm = gamma[c], be = beta[c];
    int b  = bt >> 2, t = bt & 3;
    int hi = h >> 3, r = h & 7;
    int nbase = b * 64 + hi * 8;
    int lbase = t * 64 + r * 8;
    #pragma unroll 8
    for (int w = 0; w < 64; w++) {
        int n = nbase + (w >> 3);
        int l = lbase + (w & 7);
        size_t m = (size_t)n * 256 + l;
        float val = tile[c][w];
        float xn  = (val - mus[w]) * rstds[w] * gm + be;
        g_xw[m * 256 + c]    = val;
        g_xn_bf[m * 256 + c] = __float2bfloat16_rn(xn);
    }
}

// ============================================================
// bf16 GEMM common: 128x128 block, BK=32, 8 warps (64x32 each),
// pitch-40 bf16 smem rows (conflict-free ldmatrix), cp.async 2-stage.
// ============================================================
#define STAGE_BYTES (128 * 40 * 2)

__device__ __forceinline__ void stage_load_bf(uint32_t sA, uint32_t sB,
                                              const __nv_bfloat16* Ag,
                                              const __nv_bfloat16* Bg,
                                              int lrow, int lhalf, int kt)
{
    const __nv_bfloat16* a = Ag + (size_t)lrow * 256 + kt + lhalf * 16;
    const __nv_bfloat16* b = Bg + (size_t)lrow * 256 + kt + lhalf * 16;
    uint32_t da = sA + (lrow * 40 + lhalf * 16) * 2;
    uint32_t db = sB + (lrow * 40 + lhalf * 16) * 2;
    cpasync16(da,      a);
    cpasync16(da + 16, a + 8);
    cpasync16(db,      b);
    cpasync16(db + 16, b + 8);
}

// runs the mainloop, leaves C fragments in c[4][4][4]
__device__ __forceinline__ void gemm_bf16_main(float (*c)[4][4],
                                               const __nv_bfloat16* Ab,
                                               const __nv_bfloat16* Bb,
                                               uint32_t asb, uint32_t bsb)
{
    int tid  = threadIdx.x;
    int lane = tid & 31, warp = tid >> 5;
    int wm = (warp & 1) * 64;
    int wn = (warp >> 1) * 32;

    int lrow = tid >> 1, lhalf = tid & 1;

    // ldmatrix lane->element mapping
    int a_row = lane & 15;
    int a_col = (lane >> 4) * 8;
    int b_row = (lane & 7) + (lane >> 4) * 8;
    int b_col = ((lane >> 3) & 1) * 8;

    uint32_t aS[2] = { asb, asb + STAGE_BYTES };
    uint32_t bS[2] = { bsb, bsb + STAGE_BYTES };

    stage_load_bf(aS[0], bS[0], Ab, Bb, lrow, lhalf, 0);
    CP_COMMIT;

    for (int it = 0; it < 8; it++) {
        if (it < 7)
            stage_load_bf(aS[(it+1)&1], bS[(it+1)&1], Ab, Bb, lrow, lhalf, (it+1)*32);
        CP_COMMIT;
        CP_WAIT1;
        __syncthreads();
        int s = it & 1;
        #pragma unroll
        for (int ks = 0; ks < 2; ks++) {
            uint32_t af[4][4];
            #pragma unroll
            for (int mi = 0; mi < 4; mi++) {
                uint32_t addr = aS[s] + ((wm + mi*16 + a_row) * 40 + ks*16 + a_col) * 2;
                ldsm_x4(af[mi][0], af[mi][1], af[mi][2], af[mi][3], addr);
            }
            uint32_t bf[4][2];
            {
                uint32_t addr0 = bS[s] + ((wn +  0 + b_row) * 40 + ks*16 + b_col) * 2;
                uint32_t addr1 = bS[s] + ((wn + 16 + b_row) * 40 + ks*16 + b_col) * 2;
                ldsm_x4(bf[0][0], bf[0][1], bf[1][0], bf[1][1], addr0);
                ldsm_x4(bf[2][0], bf[2][1], bf[3][0], bf[3][1], addr1);
            }
            #pragma unroll
            for (int mi = 0; mi < 4; mi++)
                #pragma unroll
                for (int j = 0; j < 4; j++)
                    mma_bf16(c[mi][j], af[mi][0], af[mi][1], af[mi][2], af[mi][3],
                             bf[j][0], bf[j][1]);
        }
        __syncthreads();
    }
}

// ============================================================
// Kernel 2: QKV GEMM (bf16).  Epilogue fp32: q scaled by
// ATT_SCALE*LOG2E, q/k d-permuted (p = (d&3)*8 + d>>2), tf32-rounded.
// ============================================================
__global__ __launch_bounds__(256, 2) void gemm_qkv_bf16(const float* __restrict__ bias)
{
    __shared__ __align__(16) __nv_bfloat16 As[2][128][40];
    __shared__ __align__(16) __nv_bfloat16 Bs[2][128][40];

    int tid  = threadIdx.x;
    int lane = tid & 31, warp = tid >> 5;
    int g = lane >> 2, t = lane & 3;
    int wm = (warp & 1) * 64;
    int wn = (warp >> 1) * 32;

    const __nv_bfloat16* Ab = g_xn_bf   + (size_t)blockIdx.y * 128 * 256;
    const __nv_bfloat16* Bb = g_wqkv_bf + (size_t)blockIdx.x * 128 * 256;

    uint32_t asb = (uint32_t)__cvta_generic_to_shared(&As[0][0][0]);
    uint32_t bsb = (uint32_t)__cvta_generic_to_shared(&Bs[0][0][0]);

    float c[4][4][4] = {};
    gemm_bf16_main(c, Ab, Bb, asb, bsb);

    float sc = (blockIdx.x < 2) ? ATT_SCALE * LOG2E : 1.0f;
    bool permute = (blockIdx.x < 4);   // q and k blocks

    int mbase = blockIdx.y * 128 + wm;
    int nbase = blockIdx.x * 128 + wn;
    #pragma unroll
    for (int m = 0; m < 4; m++) {
        int row0 = mbase + m*16 + g;
        #pragma unroll
        for (int j = 0; j < 4; j++) {
            int col = nbase + j*8 + 2*t;
            float2 bv = *(const float2*)&bias[col];
            float v00 = to_tf32((c[m][j][0] + bv.x) * sc);
            float v01 = to_tf32((c[m][j][1] + bv.y) * sc);
            float v10 = to_tf32((c[m][j][2] + bv.x) * sc);
            float v11 = to_tf32((c[m][j][3] + bv.y) * sc);
            if (permute) {
                int b32 = col & ~31;
                int d0  = col & 31, d1 = d0 + 1;
                int p0  = ((d0 & 3) << 3) + (d0 >> 2);
                int p1  = ((d1 & 3) << 3) + (d1 >> 2);
                g_qkv[(size_t)row0       * 768 + b32 + p0] = v00;
                g_qkv[(size_t)row0       * 768 + b32 + p1] = v01;
                g_qkv[(size_t)(row0 + 8) * 768 + b32 + p0] = v10;
                g_qkv[(size_t)(row0 + 8) * 768 + b32 + p1] = v11;
            } else {
                *(float2*)&g_qkv[(size_t)row0       * 768 + col] = make_float2(v00, v01);
                *(float2*)&g_qkv[(size_t)(row0 + 8) * 768 + col] = make_float2(v10, v11);
            }
        }
    }
}

// ============================================================
// Kernel 3: tensor-core attention (unchanged mainloop from R8),
// epilogue writes bf16 to g_att_bf.
// ============================================================
__global__ __launch_bounds__(256, 2) void attn_mma()
{
    __shared__ float Ks[256 * 32];
    __shared__ float Vt[32 * 256];

    int win  = blockIdx.x >> 3;
    int head = blockIdx.x & 7;
    int tid  = threadIdx.x;
    int lane = tid & 31, warp = tid >> 5;
    int g = lane >> 2, t = lane & 3;
    bool odd = t & 1;
    int srcA = (lane & ~3) | (t >> 1);
    int srcB = srcA + 2;

    const float* base = g_qkv + (size_t)win * 256 * 768 + head * 32;
    uint32_t* obase = (uint32_t*)g_att_bf + (size_t)win * 256 * 128;

    int keyl = tid >> 3;
    int qc   = tid & 7;

    #pragma unroll
    for (int it = 0; it < 8; it++) {
        int key = it * 32 + keyl;
        int qsw = qc ^ (key & 7);
        uint32_t dst = (uint32_t)__cvta_generic_to_shared(&Ks[key * 32 + qsw * 4]);
        cpasync16(dst, base + (size_t)key * 768 + 256 + qc * 4);
    }
    CP_COMMIT;

    int d4 = qc * 4;
    #pragma unroll
    for (int it = 0; it < 8; it++) {
        int key = it * 32 + keyl;
        float4 v = *(const float4*)(base + (size_t)key * 768 + 512 + d4);
        int keyp = (key & 7) * 32 + (key >> 3);
        int q  = keyp >> 2, lo = keyp & 3;
        int qh3 = q >> 3;
        Vt[(d4+0)*256 + ((q ^ qh3 ^ 0 ^ qc) << 2) + lo] = v.x;
        Vt[(d4+1)*256 + ((q ^ qh3 ^ 4 ^ qc) << 2) + lo] = v.y;
        Vt[(d4+2)*256 + ((q ^ qh3 ^ 0 ^ qc) << 2) + lo] = v.z;
        Vt[(d4+3)*256 + ((q ^ qh3 ^ 4 ^ qc) << 2) + lo] = v.w;
    }
    CP_WAIT0;
    __syncthreads();

    for (int mt = 0; mt < 2; mt++) {
        int mrow = (mt * 8 + warp) * 16;

        float QG[8], QH[8];
        {
            const float* qp = base + (size_t)mrow * 768 + t * 8;
            *(float4*)&QG[0] = *(const float4*)(qp + (size_t)g * 768);
            *(float4*)&QG[4] = *(const float4*)(qp + (size_t)g * 768 + 4);
            *(float4*)&QH[0] = *(const float4*)(qp + (size_t)(g + 8) * 768);
            *(float4*)&QH[4] = *(const float4*)(qp + (size_t)(g + 8) * 768 + 4);
        }

        float rs0 = 0.f, rs1 = 0.f;
        float co[4][4] = {};

        #pragma unroll
        for (int ch = 0; ch < 4; ch++) {
            int kb = ch * 64;

            float sf[8][4];
            #pragma unroll
            for (int nf = 0; nf < 8; nf++) { sf[nf][0]=0.f; sf[nf][1]=0.f; sf[nf][2]=0.f; sf[nf][3]=0.f; }
            #pragma unroll
            for (int nf = 0; nf < 8; nf++) {
                int key = kb + nf * 8 + g;
                const float* kr = &Ks[key * 32];
                float kbuf[8];
                *(float4*)&kbuf[0] = *(const float4*)(kr + (((2*t    ) ^ g) << 2));
                *(float4*)&kbuf[4] = *(const float4*)(kr + (((2*t + 1) ^ g) << 2));
                #pragma unroll
                for (int kf = 0; kf < 4; kf++) {
                    mma_tf32(sf[nf],
                             __float_as_uint(QG[2*kf]),   __float_as_uint(QH[2*kf]),
                             __float_as_uint(QG[2*kf+1]), __float_as_uint(QH[2*kf+1]),
                             __float_as_uint(kbuf[2*kf]), __float_as_uint(kbuf[2*kf+1]));
                }
            }

            #pragma unroll
            for (int nf = 0; nf < 8; nf++) {
                float e0 = ex2_approx(sf[nf][0]);
                float e1 = ex2_approx(sf[nf][1]);
                float e2 = ex2_approx(sf[nf][2]);
                float e3 = ex2_approx(sf[nf][3]);
                rs0 += e0 + e1;
                rs1 += e2 + e3;
                uint32_t u0 = __float_as_uint(e0);
                uint32_t u1 = __float_as_uint(e1);
                uint32_t u2 = __float_as_uint(e2);
                uint32_t u3 = __float_as_uint(e3);
                uint32_t x0 = __shfl_sync(0xffffffffu, u0, srcA);
                uint32_t x1 = __shfl_sync(0xffffffffu, u1, srcA);
                uint32_t y0 = __shfl_sync(0xffffffffu, u0, srcB);
                uint32_t y1 = __shfl_sync(0xffffffffu, u1, srcB);
                uint32_t z0 = __shfl_sync(0xffffffffu, u2, srcA);
                uint32_t z1 = __shfl_sync(0xffffffffu, u3, srcA);
                uint32_t w0 = __shfl_sync(0xffffffffu, u2, srcB);
                uint32_t w1 = __shfl_sync(0xffffffffu, u3, srcB);
                sf[nf][0] = __uint_as_float(odd ? x1 : x0);
                sf[nf][2] = __uint_as_float(odd ? y1 : y0);
                sf[nf][1] = __uint_as_float(odd ? z1 : z0);
                sf[nf][3] = __uint_as_float(odd ? w1 : w0);
            }

            #pragma unroll
            for (int nf = 0; nf < 4; nf++) {
                int row = nf * 8 + g;
                int csw = ((g & 1) << 2) ^ (row >> 2);
                const float* vr = &Vt[row * 256];
                float vA[8], vB[8];
                int qa0 = t*8 + ch*2;
                int qb0 = (t+4)*8 + ch*2;
                *(float4*)&vA[0] = *(const float4*)(vr + (((qa0    ) ^ t       ^ csw) << 2));
                *(float4*)&vA[4] = *(const float4*)(vr + (((qa0 + 1) ^ t       ^ csw) << 2));
                *(float4*)&vB[0] = *(const float4*)(vr + (((qb0    ) ^ (t + 4) ^ csw) << 2));
                *(float4*)&vB[4] = *(const float4*)(vr + (((qb0 + 1) ^ (t + 4) ^ csw) << 2));
                #pragma unroll
                for (int kf = 0; kf < 8; kf++) {
                    mma_tf32(co[nf],
                             __float_as_uint(sf[kf][0]), __float_as_uint(sf[kf][1]),
                             __float_as_uint(sf[kf][2]), __float_as_uint(sf[kf][3]),
                             __float_as_uint(vA[kf]),    __float_as_uint(vB[kf]));
                }
            }
        }

        rs0 += __shfl_xor_sync(0xffffffffu, rs0, 1);
        rs0 += __shfl_xor_sync(0xffffffffu, rs0, 2);
        rs1 += __shfl_xor_sync(0xffffffffu, rs1, 1);
        rs1 += __shfl_xor_sync(0xffffffffu, rs1, 2);
        float inv0 = 1.0f / rs0;
        float inv1 = 1.0f / rs1;

        #pragma unroll
        for (int nf = 0; nf < 4; nf++) {
            int col = head * 32 + nf*8 + 2*t;
            obase[((size_t)(mrow + g    ) * 256 + col) >> 1] =
                pack_bf16x2(co[nf][0] * inv0, co[nf][1] * inv0);
            obase[((size_t)(mrow + g + 8) * 256 + col) >> 1] =
                pack_bf16x2(co[nf][2] * inv1, co[nf][3] * inv1);
        }
    }
}

// ============================================================
// Kernel 4: proj GEMM (bf16) + bias + residual + coalesced scatter
// ============================================================
__global__ __launch_bounds__(256, 2) void gemm_proj_bf16(const float* __restrict__ bias,
                                                         float* __restrict__ out)
{
    // union: 2-stage bf16 A/B tiles (40KB) reused as fp32 C staging (66.5KB)
    __shared__ __align__(16) char smem_raw[128 * 130 * 4];
    __nv_bfloat16* As0 = (__nv_bfloat16*)smem_raw;
    __nv_bfloat16* Bs0 = (__nv_bfloat16*)(smem_raw + 2 * STAGE_BYTES);
    float (*Cs)[130]   = (float (*)[130])smem_raw;

    int tid  = threadIdx.x;
    int lane = tid & 31, warp = tid >> 5;
    int g = lane >> 2, t = lane & 3;
    int wm = (warp & 1) * 64;
    int wn = (warp >> 1) * 32;

    const __nv_bfloat16* Ab = g_att_bf   + (size_t)blockIdx.y * 128 * 256;
    const __nv_bfloat16* Bb = g_wproj_bf + (size_t)blockIdx.x * 128 * 256;

    uint32_t asb = (uint32_t)__cvta_generic_to_shared(As0);
    uint32_t bsb = (uint32_t)__cvta_generic_to_shared(Bs0);

    float c[4][4][4] = {};
    gemm_bf16_main(c, Ab, Bb, asb, bsb);

    __syncthreads();   // done with A/B smem before Cs overlay

    int nbase = blockIdx.x * 128;
    #pragma unroll
    for (int m = 0; m < 4; m++) {
        int rl = wm + m*16 + g;
        #pragma unroll
        for (int j = 0; j < 4; j++) {
            int cl = wn + j*8 + 2*t;
            float2 bv = *(const float2*)&bias[nbase + cl];
            *(float2*)&Cs[rl    ][cl] = make_float2(c[m][j][0] + bv.x, c[m][j][1] + bv.y);
            *(float2*)&Cs[rl + 8][cl] = make_float2(c[m][j][2] + bv.x, c[m][j][3] + bv.y);
        }
    }
    __syncthreads();

    int by   = blockIdx.y;
    int n    = by >> 1;
    int half = by & 1;
    int b  = n >> 6, hi = (n >> 3) & 7, wi = n & 7;

    int cc  = tid & 127;
    int trh = tid >> 7;
    #pragma unroll
    for (int tr2 = 0; tr2 < 8; tr2++) {
        int tr = tr2 * 2 + trh;
        int t2 = tr >> 3, r = tr & 7;
        int l0 = t2 * 64 + r * 8;
        int t_full = half * 2 + t2;
        int bt = b * 4 + t_full;
        int h  = hi * 8 + r;
        int col = nbase + cc;
        size_t m0 = (size_t)by * 128 + l0;
        size_t oaddr = (((size_t)bt * 256 + col) * 64 + h) * 64 + wi * 8;
        #pragma unroll
        for (int j = 0; j < 2; j++) {
            float4 v;
            v.x = Cs[l0 + 4*j + 0][cc] + g_xw[(m0 + 4*j + 0) * 256 + col];
            v.y = Cs[l0 + 4*j + 1][cc] + g_xw[(m0 + 4*j + 1) * 256 + col];
            v.z = Cs[l0 + 4*j + 2][cc] + g_xw[(m0 + 4*j + 2) * 256 + col];
            v.w = Cs[l0 + 4*j + 3][cc] + g_xw[(m0 + 4*j + 3) * 256 + col];
            *(float4*)&out[oaddr + 4*j] = v;
        }
    }
}

// ============================================================
extern "C" void kernel_launch(void* const* d_in, const int* in_sizes, int n_in,
                              void* d_out, int out_size)
{
    const float* x      = (const float*)d_in[0];
    const float* w_qkv  = (const float*)d_in[1];
    const float* b_qkv  = (const float*)d_in[2];
    const float* w_proj = (const float*)d_in[3];
    const float* b_proj = (const float*)d_in[4];
    const float* gamma  = (const float*)d_in[5];
    const float* beta   = (const float*)d_in[6];
    float* out = (float*)d_out;

    prep_weights<<<768, 256>>>(w_qkv, w_proj);
    ln_gather_kernel<<<512, 256>>>(x, gamma, beta);
    gemm_qkv_bf16<<<dim3(6, 256), 256>>>(b_qkv);
    attn_mma<<<NWIN * 8, 256>>>();
    gemm_proj_bf16<<<dim3(2, 256), 256>>>(b_proj, out);
}

// round 10
// speedup vs baseline: 1.6601x; 1.0440x over previous
#include <cuda_runtime.h>
#include <cuda_bf16.h>
#include <math.h>
#include <stdint.h>

#define CCH   256
#define TT      4
#define HH     64
#define WWID   64
#define NWIN  128
#define MTOT  (NWIN*256)
#define ATT_SCALE 0.1767766952966369f
#define LOG2E     1.4426950408889634f

// -------- global scratch --------
__device__ __nv_bfloat16  g_xn_bf[MTOT * CCH];       // LN output (bf16)
__device__ float          g_qk   [MTOT * 512];       // fp32: q scaled(*log2e)+tf32+perm | k tf32+perm
__device__ __nv_bfloat16  g_v_bf [MTOT * CCH];       // v (bf16)
__device__ __nv_bfloat16  g_att_bf[MTOT * CCH];      // attention output (bf16)
__device__ __nv_bfloat16  g_wqkv_bf[768 * 256];
__device__ __nv_bfloat16  g_wproj_bf[256 * 256];

__device__ __forceinline__ float to_tf32(float x) {
    float r;
    asm("cvt.rna.tf32.f32 %0, %1;" : "=f"(r) : "f"(x));
    return r;
}

__device__ __forceinline__ float ex2_approx(float x) {
    float r;
    asm("ex2.approx.f32 %0, %1;" : "=f"(r) : "f"(x));
    return r;
}

// pack (lo, hi) floats into bf16x2 word: mem order [lo, hi]
__device__ __forceinline__ uint32_t pack_bf16x2(float lo, float hi) {
    uint32_t r;
    asm("cvt.rn.bf16x2.f32 %0, %1, %2;" : "=r"(r) : "f"(hi), "f"(lo));
    return r;
}

__device__ __forceinline__ void mma_tf32(float* c,
                                         uint32_t a0, uint32_t a1, uint32_t a2, uint32_t a3,
                                         uint32_t b0, uint32_t b1) {
    asm volatile("mma.sync.aligned.m16n8k8.row.col.f32.tf32.tf32.f32 "
                 "{%0,%1,%2,%3}, {%4,%5,%6,%7}, {%8,%9}, {%0,%1,%2,%3};"
                 : "+f"(c[0]), "+f"(c[1]), "+f"(c[2]), "+f"(c[3])
                 : "r"(a0), "r"(a1), "r"(a2), "r"(a3), "r"(b0), "r"(b1));
}

__device__ __forceinline__ void mma_bf16(float* c,
                                         uint32_t a0, uint32_t a1, uint32_t a2, uint32_t a3,
                                         uint32_t b0, uint32_t b1) {
    asm volatile("mma.sync.aligned.m16n8k16.row.col.f32.bf16.bf16.f32 "
                 "{%0,%1,%2,%3}, {%4,%5,%6,%7}, {%8,%9}, {%0,%1,%2,%3};"
                 : "+f"(c[0]), "+f"(c[1]), "+f"(c[2]), "+f"(c[3])
                 : "r"(a0), "r"(a1), "r"(a2), "r"(a3), "r"(b0), "r"(b1));
}

__device__ __forceinline__ void ldsm_x4(uint32_t& r0, uint32_t& r1, uint32_t& r2, uint32_t& r3,
                                        uint32_t addr) {
    asm volatile("ldmatrix.sync.aligned.m8n8.x4.shared.b16 {%0,%1,%2,%3}, [%4];"
                 : "=r"(r0), "=r"(r1), "=r"(r2), "=r"(r3) : "r"(addr));
}

__device__ __forceinline__ void cpasync16(uint32_t dst, const void* src) {
    asm volatile("cp.async.ca.shared.global [%0], [%1], 16;\n" :: "r"(dst), "l"(src));
}
#define CP_COMMIT asm volatile("cp.async.commit_group;\n" ::: "memory")
#define CP_WAIT1  asm volatile("cp.async.wait_group 1;\n" ::: "memory")
#define CP_WAIT0  asm volatile("cp.async.wait_group 0;\n" ::: "memory")

// ============================================================
// Kernel 0: weight prep (fp32 -> bf16 copies)
// ============================================================
__global__ void prep_weights(const float* __restrict__ wq, const float* __restrict__ wp)
{
    int i = blockIdx.x * blockDim.x + threadIdx.x;
    if (i < 768 * 256)  g_wqkv_bf[i]  = __float2bfloat16_rn(wq[i]);
    if (i < 256 * 256)  g_wproj_bf[i] = __float2bfloat16_rn(wp[i]);
}

// ============================================================
// Kernel 1: coalesced gather + LayerNorm (bf16 xn only; no residual copy)
// ============================================================
__global__ __launch_bounds__(256) void ln_gather_kernel(const float* __restrict__ x,
                                                        const float* __restrict__ gamma,
                                                        const float* __restrict__ beta)
{
    __shared__ float tile[256][65];
    __shared__ float rsum[4][64], rsq[4][64];
    __shared__ float mus[64], rstds[64];

    int bx  = blockIdx.x;
    int bt  = bx >> 6;
    int h   = bx & 63;
    int tid = threadIdx.x;

    const float* slice = x + ((size_t)bt * 256) * 4096 + h * 64;

    int cl = tid >> 4;
    int w4 = (tid & 15) * 4;
    #pragma unroll
    for (int it = 0; it < 16; it++) {
        int c = it * 16 + cl;
        float4 v = *(const float4*)(slice + (size_t)c * 4096 + w4);
        tile[c][w4 + 0] = v.x; tile[c][w4 + 1] = v.y;
        tile[c][w4 + 2] = v.z; tile[c][w4 + 3] = v.w;
    }
    __syncthreads();

    {
        int w = tid & 63, part = tid >> 6;
        float s = 0.f, q = 0.f;
        #pragma unroll
        for (int i = 0; i < 64; i++) {
            float v = tile[part * 64 + i][w];
            s += v; q += v * v;
        }
        rsum[part][w] = s; rsq[part][w] = q;
    }
    __syncthreads();
    if (tid < 64) {
        float tot = rsum[0][tid] + rsum[1][tid] + rsum[2][tid] + rsum[3][tid];
        float tq  = rsq[0][tid]  + rsq[1][tid]  + rsq[2][tid]  + rsq[3][tid];
        float mu  = tot * (1.0f / 256.0f);
        float var = tq * (1.0f / 256.0f) - mu * mu;
        mus[tid]  = mu;
        rstds[tid] = rsqrtf(var + 1e-5f);
    }
    __syncthreads();

    int c = tid;
    float gm = gamma[c], be = beta[c];
    int b  = bt >> 2, t = bt & 3;
    int hi = h >> 3, r = h & 7;
    int nbase = b * 64 + hi * 8;
    int lbase = t * 64 + r * 8;
    #pragma unroll 8
    for (int w = 0; w < 64; w++) {
        int n = nbase + (w >> 3);
        int l = lbase + (w & 7);
        size_t m = (size_t)n * 256 + l;
        float val = tile[c][w];
        float xn  = (val - mus[w]) * rstds[w] * gm + be;
        g_xn_bf[m * 256 + c] = __float2bfloat16_rn(xn);
    }
}

// ============================================================
// bf16 GEMM common: 128x128 block, BK=32, 8 warps (64x32 each),
// pitch-40 bf16 smem rows, cp.async 2-stage.
// ============================================================
#define STAGE_BYTES (128 * 40 * 2)

__device__ __forceinline__ void stage_load_bf(uint32_t sA, uint32_t sB,
                                              const __nv_bfloat16* Ag,
                                              const __nv_bfloat16* Bg,
                                              int lrow, int lhalf, int kt)
{
    const __nv_bfloat16* a = Ag + (size_t)lrow * 256 + kt + lhalf * 16;
    const __nv_bfloat16* b = Bg + (size_t)lrow * 256 + kt + lhalf * 16;
    uint32_t da = sA + (lrow * 40 + lhalf * 16) * 2;
    uint32_t db = sB + (lrow * 40 + lhalf * 16) * 2;
    cpasync16(da,      a);
    cpasync16(da + 16, a + 8);
    cpasync16(db,      b);
    cpasync16(db + 16, b + 8);
}

__device__ __forceinline__ void gemm_bf16_main(float (*c)[4][4],
                                               const __nv_bfloat16* Ab,
                                               const __nv_bfloat16* Bb,
                                               uint32_t asb, uint32_t bsb)
{
    int tid  = threadIdx.x;
    int lane = tid & 31, warp = tid >> 5;
    int wm = (warp & 1) * 64;
    int wn = (warp >> 1) * 32;

    int lrow = tid >> 1, lhalf = tid & 1;

    int a_row = lane & 15;
    int a_col = (lane >> 4) * 8;
    int b_row = (lane & 7) + (lane >> 4) * 8;
    int b_col = ((lane >> 3) & 1) * 8;

    uint32_t aS[2] = { asb, asb + STAGE_BYTES };
    uint32_t bS[2] = { bsb, bsb + STAGE_BYTES };

    stage_load_bf(aS[0], bS[0], Ab, Bb, lrow, lhalf, 0);
    CP_COMMIT;

    for (int it = 0; it < 8; it++) {
        if (it < 7)
            stage_load_bf(aS[(it+1)&1], bS[(it+1)&1], Ab, Bb, lrow, lhalf, (it+1)*32);
        CP_COMMIT;
        CP_WAIT1;
        __syncthreads();
        int s = it & 1;
        #pragma unroll
        for (int ks = 0; ks < 2; ks++) {
            uint32_t af[4][4];
            #pragma unroll
            for (int mi = 0; mi < 4; mi++) {
                uint32_t addr = aS[s] + ((wm + mi*16 + a_row) * 40 + ks*16 + a_col) * 2;
                ldsm_x4(af[mi][0], af[mi][1], af[mi][2], af[mi][3], addr);
            }
            uint32_t bf[4][2];
            {
                uint32_t addr0 = bS[s] + ((wn +  0 + b_row) * 40 + ks*16 + b_col) * 2;
                uint32_t addr1 = bS[s] + ((wn + 16 + b_row) * 40 + ks*16 + b_col) * 2;
                ldsm_x4(bf[0][0], bf[0][1], bf[1][0], bf[1][1], addr0);
                ldsm_x4(bf[2][0], bf[2][1], bf[3][0], bf[3][1], addr1);
            }
            #pragma unroll
            for (int mi = 0; mi < 4; mi++)
                #pragma unroll
                for (int j = 0; j < 4; j++)
                    mma_bf16(c[mi][j], af[mi][0], af[mi][1], af[mi][2], af[mi][3],
                             bf[j][0], bf[j][1]);
        }
        __syncthreads();
    }
}

// ============================================================
// Kernel 2: QKV GEMM (bf16).  Epilogue: q scaled by ATT_SCALE*LOG2E,
// q/k d-permuted fp32 into g_qk[M,512]; v packed bf16 into g_v_bf.
// ============================================================
__global__ __launch_bounds__(256, 2) void gemm_qkv_bf16(const float* __restrict__ bias)
{
    __shared__ __align__(16) __nv_bfloat16 As[2][128][40];
    __shared__ __align__(16) __nv_bfloat16 Bs[2][128][40];

    int tid  = threadIdx.x;
    int lane = tid & 31, warp = tid >> 5;
    int g = lane >> 2, t = lane & 3;
    int wm = (warp & 1) * 64;
    int wn = (warp >> 1) * 32;

    const __nv_bfloat16* Ab = g_xn_bf   + (size_t)blockIdx.y * 128 * 256;
    const __nv_bfloat16* Bb = g_wqkv_bf + (size_t)blockIdx.x * 128 * 256;

    uint32_t asb = (uint32_t)__cvta_generic_to_shared(&As[0][0][0]);
    uint32_t bsb = (uint32_t)__cvta_generic_to_shared(&Bs[0][0][0]);

    float c[4][4][4] = {};
    gemm_bf16_main(c, Ab, Bb, asb, bsb);

    int mbase = blockIdx.y * 128 + wm;
    int nbase = blockIdx.x * 128 + wn;

    if (blockIdx.x < 4) {        // q and k: fp32, tf32-rounded, d-permuted
        float sc = (blockIdx.x < 2) ? ATT_SCALE * LOG2E : 1.0f;
        #pragma unroll
        for (int m = 0; m < 4; m++) {
            int row0 = mbase + m*16 + g;
            #pragma unroll
            for (int j = 0; j < 4; j++) {
                int col = nbase + j*8 + 2*t;      // 0..511
                float2 bv = *(const float2*)&bias[col];
                float v00 = to_tf32((c[m][j][0] + bv.x) * sc);
                float v01 = to_tf32((c[m][j][1] + bv.y) * sc);
                float v10 = to_tf32((c[m][j][2] + bv.x) * sc);
                float v11 = to_tf32((c[m][j][3] + bv.y) * sc);
                int b32 = col & ~31;
                int d0  = col & 31, d1 = d0 + 1;
                int p0  = ((d0 & 3) << 3) + (d0 >> 2);
                int p1  = ((d1 & 3) << 3) + (d1 >> 2);
                g_qk[(size_t)row0       * 512 + b32 + p0] = v00;
                g_qk[(size_t)row0       * 512 + b32 + p1] = v01;
                g_qk[(size_t)(row0 + 8) * 512 + b32 + p0] = v10;
                g_qk[(size_t)(row0 + 8) * 512 + b32 + p1] = v11;
            }
        }
    } else {                      // v: bf16 packed
        uint32_t* vout = (uint32_t*)g_v_bf;
        #pragma unroll
        for (int m = 0; m < 4; m++) {
            int row0 = mbase + m*16 + g;
            #pragma unroll
            for (int j = 0; j < 4; j++) {
                int col = nbase + j*8 + 2*t;      // 512..767
                float2 bv = *(const float2*)&bias[col];
                int vcol = col - 512;
                vout[((size_t)row0       * 256 + vcol) >> 1] =
                    pack_bf16x2(c[m][j][0] + bv.x, c[m][j][1] + bv.y);
                vout[((size_t)(row0 + 8) * 256 + vcol) >> 1] =
                    pack_bf16x2(c[m][j][2] + bv.x, c[m][j][3] + bv.y);
            }
        }
    }
}

// ============================================================
// Kernel 3: tensor-core attention (R8 mainloop; Q/K from g_qk,
// V from g_v_bf converted to fp32 during transpose).
// ============================================================
__global__ __launch_bounds__(256, 2) void attn_mma()
{
    __shared__ float Ks[256 * 32];
    __shared__ float Vt[32 * 256];

    int win  = blockIdx.x >> 3;
    int head = blockIdx.x & 7;
    int tid  = threadIdx.x;
    int lane = tid & 31, warp = tid >> 5;
    int g = lane >> 2, t = lane & 3;
    bool odd = t & 1;
    int srcA = (lane & ~3) | (t >> 1);
    int srcB = srcA + 2;

    const float* baseQ = g_qk + (size_t)win * 256 * 512 + head * 32;
    const float* baseK = baseQ + 256;
    const __nv_bfloat16* baseV = g_v_bf + (size_t)win * 256 * 256 + head * 32;
    uint32_t* obase = (uint32_t*)g_att_bf + (size_t)win * 256 * 128;

    int keyl = tid >> 3;
    int qc   = tid & 7;

    #pragma unroll
    for (int it = 0; it < 8; it++) {
        int key = it * 32 + keyl;
        int qsw = qc ^ (key & 7);
        uint32_t dst = (uint32_t)__cvta_generic_to_shared(&Ks[key * 32 + qsw * 4]);
        cpasync16(dst, baseK + (size_t)key * 512 + qc * 4);
    }
    CP_COMMIT;

    int d4 = qc * 4;
    #pragma unroll
    for (int it = 0; it < 8; it++) {
        int key = it * 32 + keyl;
        uint2 vv = *(const uint2*)(baseV + (size_t)key * 256 + d4);
        float2 f01 = __bfloat1622float2(*(__nv_bfloat162*)&vv.x);
        float2 f23 = __bfloat1622float2(*(__nv_bfloat162*)&vv.y);
        int keyp = (key & 7) * 32 + (key >> 3);
        int q  = keyp >> 2, lo = keyp & 3;
        int qh3 = q >> 3;
        Vt[(d4+0)*256 + ((q ^ qh3 ^ 0 ^ qc) << 2) + lo] = f01.x;
        Vt[(d4+1)*256 + ((q ^ qh3 ^ 4 ^ qc) << 2) + lo] = f01.y;
        Vt[(d4+2)*256 + ((q ^ qh3 ^ 0 ^ qc) << 2) + lo] = f23.x;
        Vt[(d4+3)*256 + ((q ^ qh3 ^ 4 ^ qc) << 2) + lo] = f23.y;
    }
    CP_WAIT0;
    __syncthreads();

    for (int mt = 0; mt < 2; mt++) {
        int mrow = (mt * 8 + warp) * 16;

        float QG[8], QH[8];
        {
            const float* qp = baseQ + (size_t)mrow * 512 + t * 8;
            *(float4*)&QG[0] = *(const float4*)(qp + (size_t)g * 512);
            *(float4*)&QG[4] = *(const float4*)(qp + (size_t)g * 512 + 4);
            *(float4*)&QH[0] = *(const float4*)(qp + (size_t)(g + 8) * 512);
            *(float4*)&QH[4] = *(const float4*)(qp + (size_t)(g + 8) * 512 + 4);
        }

        float rs0 = 0.f, rs1 = 0.f;
        float co[4][4] = {};

        #pragma unroll
        for (int ch = 0; ch < 4; ch++) {
            int kb = ch * 64;

            float sf[8][4];
            #pragma unroll
            for (int nf = 0; nf < 8; nf++) { sf[nf][0]=0.f; sf[nf][1]=0.f; sf[nf][2]=0.f; sf[nf][3]=0.f; }
            #pragma unroll
            for (int nf = 0; nf < 8; nf++) {
                int key = kb + nf * 8 + g;
                const float* kr = &Ks[key * 32];
                float kbuf[8];
                *(float4*)&kbuf[0] = *(const float4*)(kr + (((2*t    ) ^ g) << 2));
                *(float4*)&kbuf[4] = *(const float4*)(kr + (((2*t + 1) ^ g) << 2));
                #pragma unroll
                for (int kf = 0; kf < 4; kf++) {
                    mma_tf32(sf[nf],
                             __float_as_uint(QG[2*kf]),   __float_as_uint(QH[2*kf]),
                             __float_as_uint(QG[2*kf+1]), __float_as_uint(QH[2*kf+1]),
                             __float_as_uint(kbuf[2*kf]), __float_as_uint(kbuf[2*kf+1]));
                }
            }

            #pragma unroll
            for (int nf = 0; nf < 8; nf++) {
                float e0 = ex2_approx(sf[nf][0]);
                float e1 = ex2_approx(sf[nf][1]);
                float e2 = ex2_approx(sf[nf][2]);
                float e3 = ex2_approx(sf[nf][3]);
                rs0 += e0 + e1;
                rs1 += e2 + e3;
                uint32_t u0 = __float_as_uint(e0);
                uint32_t u1 = __float_as_uint(e1);
                uint32_t u2 = __float_as_uint(e2);
                uint32_t u3 = __float_as_uint(e3);
                uint32_t x0 = __shfl_sync(0xffffffffu, u0, srcA);
                uint32_t x1 = __shfl_sync(0xffffffffu, u1, srcA);
                uint32_t y0 = __shfl_sync(0xffffffffu, u0, srcB);
                uint32_t y1 = __shfl_sync(0xffffffffu, u1, srcB);
                uint32_t z0 = __shfl_sync(0xffffffffu, u2, srcA);
                uint32_t z1 = __shfl_sync(0xffffffffu, u3, srcA);
                uint32_t w0 = __shfl_sync(0xffffffffu, u2, srcB);
                uint32_t w1 = __shfl_sync(0xffffffffu, u3, srcB);
                sf[nf][0] = __uint_as_float(odd ? x1 : x0);
                sf[nf][2] = __uint_as_float(odd ? y1 : y0);
                sf[nf][1] = __uint_as_float(odd ? z1 : z0);
                sf[nf][3] = __uint_as_float(odd ? w1 : w0);
            }

            #pragma unroll
            for (int nf = 0; nf < 4; nf++) {
                int row = nf * 8 + g;
                int csw = ((g & 1) << 2) ^ (row >> 2);
                const float* vr = &Vt[row * 256];
                float vA[8], vB[8];
                int qa0 = t*8 + ch*2;
                int qb0 = (t+4)*8 + ch*2;
                *(float4*)&vA[0] = *(const float4*)(vr + (((qa0    ) ^ t       ^ csw) << 2));
                *(float4*)&vA[4] = *(const float4*)(vr + (((qa0 + 1) ^ t       ^ csw) << 2));
                *(float4*)&vB[0] = *(const float4*)(vr + (((qb0    ) ^ (t + 4) ^ csw) << 2));
                *(float4*)&vB[4] = *(const float4*)(vr + (((qb0 + 1) ^ (t + 4) ^ csw) << 2));
                #pragma unroll
                for (int kf = 0; kf < 8; kf++) {
                    mma_tf32(co[nf],
                             __float_as_uint(sf[kf][0]), __float_as_uint(sf[kf][1]),
                             __float_as_uint(sf[kf][2]), __float_as_uint(sf[kf][3]),
                             __float_as_uint(vA[kf]),    __float_as_uint(vB[kf]));
                }
            }
        }

        rs0 += __shfl_xor_sync(0xffffffffu, rs0, 1);
        rs0 += __shfl_xor_sync(0xffffffffu, rs0, 2);
        rs1 += __shfl_xor_sync(0xffffffffu, rs1, 1);
        rs1 += __shfl_xor_sync(0xffffffffu, rs1, 2);
        float inv0 = 1.0f / rs0;
        float inv1 = 1.0f / rs1;

        #pragma unroll
        for (int nf = 0; nf < 4; nf++) {
            int col = head * 32 + nf*8 + 2*t;
            obase[((size_t)(mrow + g    ) * 256 + col) >> 1] =
                pack_bf16x2(co[nf][0] * inv0, co[nf][1] * inv0);
            obase[((size_t)(mrow + g + 8) * 256 + col) >> 1] =
                pack_bf16x2(co[nf][2] * inv1, co[nf][3] * inv1);
        }
    }
}

// ============================================================
// Kernel 4: proj GEMM (bf16) + bias + residual(from x) + scatter
// ============================================================
__global__ __launch_bounds__(256, 2) void gemm_proj_bf16(const float* __restrict__ bias,
                                                         const float* __restrict__ x,
                                                         float* __restrict__ out)
{
    __shared__ __align__(16) char smem_raw[128 * 130 * 4];
    __nv_bfloat16* As0 = (__nv_bfloat16*)smem_raw;
    __nv_bfloat16* Bs0 = (__nv_bfloat16*)(smem_raw + 2 * STAGE_BYTES);
    float (*Cs)[130]   = (float (*)[130])smem_raw;

    int tid  = threadIdx.x;
    int lane = tid & 31, warp = tid >> 5;
    int g = lane >> 2, t = lane & 3;
    int wm = (warp & 1) * 64;
    int wn = (warp >> 1) * 32;

    const __nv_bfloat16* Ab = g_att_bf   + (size_t)blockIdx.y * 128 * 256;
    const __nv_bfloat16* Bb = g_wproj_bf + (size_t)blockIdx.x * 128 * 256;

    uint32_t asb = (uint32_t)__cvta_generic_to_shared(As0);
    uint32_t bsb = (uint32_t)__cvta_generic_to_shared(Bs0);

    float c[4][4][4] = {};
    gemm_bf16_main(c, Ab, Bb, asb, bsb);

    __syncthreads();   // done with A/B smem before Cs overlay

    int nbase = blockIdx.x * 128;
    #pragma unroll
    for (int m = 0; m < 4; m++) {
        int rl = wm + m*16 + g;
        #pragma unroll
        for (int j = 0; j < 4; j++) {
            int cl = wn + j*8 + 2*t;
            float2 bv = *(const float2*)&bias[nbase + cl];
            *(float2*)&Cs[rl    ][cl] = make_float2(c[m][j][0] + bv.x, c[m][j][1] + bv.y);
            *(float2*)&Cs[rl + 8][cl] = make_float2(c[m][j][2] + bv.x, c[m][j][3] + bv.y);
        }
    }
    __syncthreads();

    int by   = blockIdx.y;
    int n    = by >> 1;
    int half = by & 1;
    int b  = n >> 6, hi = (n >> 3) & 7, wi = n & 7;

    int cc  = tid & 127;
    int trh = tid >> 7;
    #pragma unroll
    for (int tr2 = 0; tr2 < 8; tr2++) {
        int tr = tr2 * 2 + trh;
        int t2 = tr >> 3, r = tr & 7;
        int l0 = t2 * 64 + r * 8;
        int t_full = half * 2 + t2;
        int bt = b * 4 + t_full;
        int h  = hi * 8 + r;
        int col = nbase + cc;
        size_t oaddr = (((size_t)bt * 256 + col) * 64 + h) * 64 + wi * 8;
        #pragma unroll
        for (int j = 0; j < 2; j++) {
            float4 xr = *(const float4*)&x[oaddr + 4*j];
            float4 v;
            v.x = Cs[l0 + 4*j + 0][cc] + xr.x;
            v.y = Cs[l0 + 4*j + 1][cc] + xr.y;
            v.z = Cs[l0 + 4*j + 2][cc] + xr.z;
            v.w = Cs[l0 + 4*j + 3][cc] + xr.w;
            *(float4*)&out[oaddr + 4*j] = v;
        }
    }
}

// ============================================================
extern "C" void kernel_launch(void* const* d_in, const int* in_sizes, int n_in,
                              void* d_out, int out_size)
{
    const float* x      = (const float*)d_in[0];
    const float* w_qkv  = (const float*)d_in[1];
    const float* b_qkv  = (const float*)d_in[2];
    const float* w_proj = (const float*)d_in[3];
    const float* b_proj = (const float*)d_in[4];
    const float* gamma  = (const float*)d_in[5];
    const float* beta   = (const float*)d_in[6];
    float* out = (float*)d_out;

    prep_weights<<<768, 256>>>(w_qkv, w_proj);
    ln_gather_kernel<<<512, 256>>>(x, gamma, beta);
    gemm_qkv_bf16<<<dim3(6, 256), 256>>>(b_qkv);
    attn_mma<<<NWIN * 8, 256>>>();
    gemm_proj_bf16<<<dim3(2, 256), 256>>>(b_proj, x, out);
}

// round 11
// speedup vs baseline: 1.8494x; 1.1140x over previous
#include <cuda_runtime.h>
#include <cuda_bf16.h>
#include <math.h>
#include <stdint.h>

#define CCH   256
#define TT      4
#define HH     64
#define WWID   64
#define NWIN  128
#define MTOT  (NWIN*256)
#define ATT_SCALE 0.1767766952966369f
#define LOG2E     1.4426950408889634f

// -------- global scratch --------
__device__ __nv_bfloat16  g_xn_bf[MTOT * CCH];       // LN output (bf16)
__device__ float          g_qk   [MTOT * 512];       // fp32: q scaled(*log2e)+tf32+perm | k tf32+perm
__device__ __nv_bfloat16  g_v_bf [MTOT * CCH];       // v (bf16)
__device__ __nv_bfloat16  g_att_bf[MTOT * CCH];      // attention output (bf16)
__device__ __nv_bfloat16  g_wqkv_bf[768 * 256];
__device__ __nv_bfloat16  g_wproj_bf[256 * 256];

__device__ __forceinline__ float to_tf32(float x) {
    float r;
    asm("cvt.rna.tf32.f32 %0, %1;" : "=f"(r) : "f"(x));
    return r;
}

__device__ __forceinline__ float ex2_approx(float x) {
    float r;
    asm("ex2.approx.f32 %0, %1;" : "=f"(r) : "f"(x));
    return r;
}

// pack (lo, hi) floats into bf16x2 word: lo -> bits[0:16), hi -> bits[16:32)
__device__ __forceinline__ uint32_t pack_bf16x2(float lo, float hi) {
    uint32_t r;
    asm("cvt.rn.bf16x2.f32 %0, %1, %2;" : "=r"(r) : "f"(hi), "f"(lo));
    return r;
}

__device__ __forceinline__ void mma_tf32(float* c,
                                         uint32_t a0, uint32_t a1, uint32_t a2, uint32_t a3,
                                         uint32_t b0, uint32_t b1) {
    asm volatile("mma.sync.aligned.m16n8k8.row.col.f32.tf32.tf32.f32 "
                 "{%0,%1,%2,%3}, {%4,%5,%6,%7}, {%8,%9}, {%0,%1,%2,%3};"
                 : "+f"(c[0]), "+f"(c[1]), "+f"(c[2]), "+f"(c[3])
                 : "r"(a0), "r"(a1), "r"(a2), "r"(a3), "r"(b0), "r"(b1));
}

__device__ __forceinline__ void mma_bf16(float* c,
                                         uint32_t a0, uint32_t a1, uint32_t a2, uint32_t a3,
                                         uint32_t b0, uint32_t b1) {
    asm volatile("mma.sync.aligned.m16n8k16.row.col.f32.bf16.bf16.f32 "
                 "{%0,%1,%2,%3}, {%4,%5,%6,%7}, {%8,%9}, {%0,%1,%2,%3};"
                 : "+f"(c[0]), "+f"(c[1]), "+f"(c[2]), "+f"(c[3])
                 : "r"(a0), "r"(a1), "r"(a2), "r"(a3), "r"(b0), "r"(b1));
}

__device__ __forceinline__ void ldsm_x4(uint32_t& r0, uint32_t& r1, uint32_t& r2, uint32_t& r3,
                                        uint32_t addr) {
    asm volatile("ldmatrix.sync.aligned.m8n8.x4.shared.b16 {%0,%1,%2,%3}, [%4];"
                 : "=r"(r0), "=r"(r1), "=r"(r2), "=r"(r3) : "r"(addr));
}

__device__ __forceinline__ void ldsm_x4_trans(uint32_t& r0, uint32_t& r1, uint32_t& r2, uint32_t& r3,
                                              uint32_t addr) {
    asm volatile("ldmatrix.sync.aligned.m8n8.x4.trans.shared.b16 {%0,%1,%2,%3}, [%4];"
                 : "=r"(r0), "=r"(r1), "=r"(r2), "=r"(r3) : "r"(addr));
}

__device__ __forceinline__ void cpasync16(uint32_t dst, const void* src) {
    asm volatile("cp.async.ca.shared.global [%0], [%1], 16;\n" :: "r"(dst), "l"(src));
}
#define CP_COMMIT asm volatile("cp.async.commit_group;\n" ::: "memory")
#define CP_WAIT1  asm volatile("cp.async.wait_group 1;\n" ::: "memory")
#define CP_WAIT0  asm volatile("cp.async.wait_group 0;\n" ::: "memory")

// ============================================================
// Kernel 0: weight prep (fp32 -> bf16 copies)
// ============================================================
__global__ void prep_weights(const float* __restrict__ wq, const float* __restrict__ wp)
{
    int i = blockIdx.x * blockDim.x + threadIdx.x;
    if (i < 768 * 256)  g_wqkv_bf[i]  = __float2bfloat16_rn(wq[i]);
    if (i < 256 * 256)  g_wproj_bf[i] = __float2bfloat16_rn(wp[i]);
}

// ============================================================
// Kernel 1: coalesced gather + LayerNorm (bf16 xn only)
// ============================================================
__global__ __launch_bounds__(256) void ln_gather_kernel(const float* __restrict__ x,
                                                        const float* __restrict__ gamma,
                                                        const float* __restrict__ beta)
{
    __shared__ float tile[256][65];
    __shared__ float rsum[4][64], rsq[4][64];
    __shared__ float mus[64], rstds[64];

    int bx  = blockIdx.x;
    int bt  = bx >> 6;
    int h   = bx & 63;
    int tid = threadIdx.x;

    const float* slice = x + ((size_t)bt * 256) * 4096 + h * 64;

    int cl = tid >> 4;
    int w4 = (tid & 15) * 4;
    #pragma unroll
    for (int it = 0; it < 16; it++) {
        int c = it * 16 + cl;
        float4 v = *(const float4*)(slice + (size_t)c * 4096 + w4);
        tile[c][w4 + 0] = v.x; tile[c][w4 + 1] = v.y;
        tile[c][w4 + 2] = v.z; tile[c][w4 + 3] = v.w;
    }
    __syncthreads();

    {
        int w = tid & 63, part = tid >> 6;
        float s = 0.f, q = 0.f;
        #pragma unroll
        for (int i = 0; i < 64; i++) {
            float v = tile[part * 64 + i][w];
            s += v; q += v * v;
        }
        rsum[part][w] = s; rsq[part][w] = q;
    }
    __syncthreads();
    if (tid < 64) {
        float tot = rsum[0][tid] + rsum[1][tid] + rsum[2][tid] + rsum[3][tid];
        float tq  = rsq[0][tid]  + rsq[1][tid]  + rsq[2][tid]  + rsq[3][tid];
        float mu  = tot * (1.0f / 256.0f);
        float var = tq * (1.0f / 256.0f) - mu * mu;
        mus[tid]  = mu;
        rstds[tid] = rsqrtf(var + 1e-5f);
    }
    __syncthreads();

    int c = tid;
    float gm = gamma[c], be = beta[c];
    int b  = bt >> 2, t = bt & 3;
    int hi = h >> 3, r = h & 7;
    int nbase = b * 64 + hi * 8;
    int lbase = t * 64 + r * 8;
    #pragma unroll 8
    for (int w = 0; w < 64; w++) {
        int n = nbase + (w >> 3);
        int l = lbase + (w & 7);
        size_t m = (size_t)n * 256 + l;
        float val = tile[c][w];
        float xn  = (val - mus[w]) * rstds[w] * gm + be;
        g_xn_bf[m * 256 + c] = __float2bfloat16_rn(xn);
    }
}

// ============================================================
// bf16 GEMM common: 128x128 block, BK=32, 8 warps (64x32 each),
// pitch-40 bf16 smem rows, cp.async 2-stage.
// ============================================================
#define STAGE_BYTES (128 * 40 * 2)

__device__ __forceinline__ void stage_load_bf(uint32_t sA, uint32_t sB,
                                              const __nv_bfloat16* Ag,
                                              const __nv_bfloat16* Bg,
                                              int lrow, int lhalf, int kt)
{
    const __nv_bfloat16* a = Ag + (size_t)lrow * 256 + kt + lhalf * 16;
    const __nv_bfloat16* b = Bg + (size_t)lrow * 256 + kt + lhalf * 16;
    uint32_t da = sA + (lrow * 40 + lhalf * 16) * 2;
    uint32_t db = sB + (lrow * 40 + lhalf * 16) * 2;
    cpasync16(da,      a);
    cpasync16(da + 16, a + 8);
    cpasync16(db,      b);
    cpasync16(db + 16, b + 8);
}

__device__ __forceinline__ void gemm_bf16_main(float (*c)[4][4],
                                               const __nv_bfloat16* Ab,
                                               const __nv_bfloat16* Bb,
                                               uint32_t asb, uint32_t bsb)
{
    int tid  = threadIdx.x;
    int lane = tid & 31, warp = tid >> 5;
    int wm = (warp & 1) * 64;
    int wn = (warp >> 1) * 32;

    int lrow = tid >> 1, lhalf = tid & 1;

    int a_row = lane & 15;
    int a_col = (lane >> 4) * 8;
    int b_row = (lane & 7) + (lane >> 4) * 8;
    int b_col = ((lane >> 3) & 1) * 8;

    uint32_t aS[2] = { asb, asb + STAGE_BYTES };
    uint32_t bS[2] = { bsb, bsb + STAGE_BYTES };

    stage_load_bf(aS[0], bS[0], Ab, Bb, lrow, lhalf, 0);
    CP_COMMIT;

    for (int it = 0; it < 8; it++) {
        if (it < 7)
            stage_load_bf(aS[(it+1)&1], bS[(it+1)&1], Ab, Bb, lrow, lhalf, (it+1)*32);
        CP_COMMIT;
        CP_WAIT1;
        __syncthreads();
        int s = it & 1;
        #pragma unroll
        for (int ks = 0; ks < 2; ks++) {
            uint32_t af[4][4];
            #pragma unroll
            for (int mi = 0; mi < 4; mi++) {
                uint32_t addr = aS[s] + ((wm + mi*16 + a_row) * 40 + ks*16 + a_col) * 2;
                ldsm_x4(af[mi][0], af[mi][1], af[mi][2], af[mi][3], addr);
            }
            uint32_t bf[4][2];
            {
                uint32_t addr0 = bS[s] + ((wn +  0 + b_row) * 40 + ks*16 + b_col) * 2;
                uint32_t addr1 = bS[s] + ((wn + 16 + b_row) * 40 + ks*16 + b_col) * 2;
                ldsm_x4(bf[0][0], bf[0][1], bf[1][0], bf[1][1], addr0);
                ldsm_x4(bf[2][0], bf[2][1], bf[3][0], bf[3][1], addr1);
            }
            #pragma unroll
            for (int mi = 0; mi < 4; mi++)
                #pragma unroll
                for (int j = 0; j < 4; j++)
                    mma_bf16(c[mi][j], af[mi][0], af[mi][1], af[mi][2], af[mi][3],
                             bf[j][0], bf[j][1]);
        }
        __syncthreads();
    }
}

// ============================================================
// Kernel 2: QKV GEMM (bf16).  Epilogue: q scaled by ATT_SCALE*LOG2E,
// q/k d-permuted fp32 into g_qk[M,512]; v packed bf16 into g_v_bf.
// ============================================================
__global__ __launch_bounds__(256, 2) void gemm_qkv_bf16(const float* __restrict__ bias)
{
    __shared__ __align__(16) __nv_bfloat16 As[2][128][40];
    __shared__ __align__(16) __nv_bfloat16 Bs[2][128][40];

    int tid  = threadIdx.x;
    int lane = tid & 31, warp = tid >> 5;
    int g = lane >> 2, t = lane & 3;
    int wm = (warp & 1) * 64;
    int wn = (warp >> 1) * 32;

    const __nv_bfloat16* Ab = g_xn_bf   + (size_t)blockIdx.y * 128 * 256;
    const __nv_bfloat16* Bb = g_wqkv_bf + (size_t)blockIdx.x * 128 * 256;

    uint32_t asb = (uint32_t)__cvta_generic_to_shared(&As[0][0][0]);
    uint32_t bsb = (uint32_t)__cvta_generic_to_shared(&Bs[0][0][0]);

    float c[4][4][4] = {};
    gemm_bf16_main(c, Ab, Bb, asb, bsb);

    int mbase = blockIdx.y * 128 + wm;
    int nbase = blockIdx.x * 128 + wn;

    if (blockIdx.x < 4) {        // q and k: fp32, tf32-rounded, d-permuted
        float sc = (blockIdx.x < 2) ? ATT_SCALE * LOG2E : 1.0f;
        #pragma unroll
        for (int m = 0; m < 4; m++) {
            int row0 = mbase + m*16 + g;
            #pragma unroll
            for (int j = 0; j < 4; j++) {
                int col = nbase + j*8 + 2*t;      // 0..511
                float2 bv = *(const float2*)&bias[col];
                float v00 = to_tf32((c[m][j][0] + bv.x) * sc);
                float v01 = to_tf32((c[m][j][1] + bv.y) * sc);
                float v10 = to_tf32((c[m][j][2] + bv.x) * sc);
                float v11 = to_tf32((c[m][j][3] + bv.y) * sc);
                int b32 = col & ~31;
                int d0  = col & 31, d1 = d0 + 1;
                int p0  = ((d0 & 3) << 3) + (d0 >> 2);
                int p1  = ((d1 & 3) << 3) + (d1 >> 2);
                g_qk[(size_t)row0       * 512 + b32 + p0] = v00;
                g_qk[(size_t)row0       * 512 + b32 + p1] = v01;
                g_qk[(size_t)(row0 + 8) * 512 + b32 + p0] = v10;
                g_qk[(size_t)(row0 + 8) * 512 + b32 + p1] = v11;
            }
        }
    } else {                      // v: bf16 packed
        uint32_t* vout = (uint32_t*)g_v_bf;
        #pragma unroll
        for (int m = 0; m < 4; m++) {
            int row0 = mbase + m*16 + g;
            #pragma unroll
            for (int j = 0; j < 4; j++) {
                int col = nbase + j*8 + 2*t;      // 512..767
                float2 bv = *(const float2*)&bias[col];
                int vcol = col - 512;
                vout[((size_t)row0       * 256 + vcol) >> 1] =
                    pack_bf16x2(c[m][j][0] + bv.x, c[m][j][1] + bv.y);
                vout[((size_t)(row0 + 8) * 256 + vcol) >> 1] =
                    pack_bf16x2(c[m][j][2] + bv.x, c[m][j][3] + bv.y);
            }
        }
    }
}

// ============================================================
// Kernel 3: attention. QK^T tf32 (unchanged); PV bf16 m16n8k16:
// P packed straight from S C-frags (no shuffles), V natural-layout
// bf16 in smem (cp.async), B-frags via ldmatrix.x4.trans.
// ============================================================
__global__ __launch_bounds__(256, 2) void attn_mma()
{
    __shared__ float Ks[256 * 32];
    __shared__ __align__(16) __nv_bfloat16 Vs[256 * 40];   // [key][40], 80B pitch

    int win  = blockIdx.x >> 3;
    int head = blockIdx.x & 7;
    int tid  = threadIdx.x;
    int lane = tid & 31, warp = tid >> 5;
    int g = lane >> 2, t = lane & 3;

    const float* baseQ = g_qk + (size_t)win * 256 * 512 + head * 32;
    const float* baseK = baseQ + 256;
    const __nv_bfloat16* baseV = g_v_bf + (size_t)win * 256 * 256 + head * 32;
    uint32_t* obase = (uint32_t*)g_att_bf + (size_t)win * 256 * 128;

    uint32_t vs_base = (uint32_t)__cvta_generic_to_shared(Vs);

    int keyl = tid >> 3;
    int qc   = tid & 7;

    // --- K via cp.async into swizzled fp32 chunks (unchanged) ---
    #pragma unroll
    for (int it = 0; it < 8; it++) {
        int key = it * 32 + keyl;
        int qsw = qc ^ (key & 7);
        uint32_t dst = (uint32_t)__cvta_generic_to_shared(&Ks[key * 32 + qsw * 4]);
        cpasync16(dst, baseK + (size_t)key * 512 + qc * 4);
    }
    // --- V via cp.async, natural [key][d] bf16, pitch 40 ---
    {
        int vkey = tid;                       // 256 threads = 256 keys
        uint32_t dst = vs_base + vkey * 80;
        const __nv_bfloat16* src = baseV + (size_t)vkey * 256;
        cpasync16(dst,      src);
        cpasync16(dst + 16, src + 8);
        cpasync16(dst + 32, src + 16);
        cpasync16(dst + 48, src + 24);
    }
    CP_COMMIT;
    CP_WAIT0;
    __syncthreads();

    // ldmatrix.trans lane address offset (within a 16key x 16d tile)
    int mat = lane >> 3;
    uint32_t voff_lane = vs_base + ((mat & 1) * 8 + (lane & 7)) * 80 + (mat >> 1) * 16;

    for (int mt = 0; mt < 2; mt++) {
        int mrow = (mt * 8 + warp) * 16;

        // Q fragments (d-permuted fp32, full-sector LDG.128)
        float QG[8], QH[8];
        {
            const float* qp = baseQ + (size_t)mrow * 512 + t * 8;
            *(float4*)&QG[0] = *(const float4*)(qp + (size_t)g * 512);
            *(float4*)&QG[4] = *(const float4*)(qp + (size_t)g * 512 + 4);
            *(float4*)&QH[0] = *(const float4*)(qp + (size_t)(g + 8) * 512);
            *(float4*)&QH[4] = *(const float4*)(qp + (size_t)(g + 8) * 512 + 4);
        }

        float rs0 = 0.f, rs1 = 0.f;
        float co[4][4] = {};

        #pragma unroll
        for (int ch = 0; ch < 4; ch++) {
            int kb = ch * 64;

            // ---- S = Q K^T chunk (16 x 64), tf32 ----
            float sf[8][4];
            #pragma unroll
            for (int nf = 0; nf < 8; nf++) { sf[nf][0]=0.f; sf[nf][1]=0.f; sf[nf][2]=0.f; sf[nf][3]=0.f; }
            #pragma unroll
            for (int nf = 0; nf < 8; nf++) {
                int key = kb + nf * 8 + g;
                const float* kr = &Ks[key * 32];
                float kbuf[8];
                *(float4*)&kbuf[0] = *(const float4*)(kr + (((2*t    ) ^ g) << 2));
                *(float4*)&kbuf[4] = *(const float4*)(kr + (((2*t + 1) ^ g) << 2));
                #pragma unroll
                for (int kf = 0; kf < 4; kf++) {
                    mma_tf32(sf[nf],
                             __float_as_uint(QG[2*kf]),   __float_as_uint(QH[2*kf]),
                             __float_as_uint(QG[2*kf+1]), __float_as_uint(QH[2*kf+1]),
                             __float_as_uint(kbuf[2*kf]), __float_as_uint(kbuf[2*kf+1]));
                }
            }

            // ---- exp2 + rowsum (in place, no shuffles) ----
            #pragma unroll
            for (int nf = 0; nf < 8; nf++) {
                float e0 = ex2_approx(sf[nf][0]);
                float e1 = ex2_approx(sf[nf][1]);
                float e2 = ex2_approx(sf[nf][2]);
                float e3 = ex2_approx(sf[nf][3]);
                rs0 += e0 + e1;
                rs1 += e2 + e3;
                sf[nf][0] = e0; sf[nf][1] = e1; sf[nf][2] = e2; sf[nf][3] = e3;
            }

            // ---- O += P V : bf16 m16n8k16, P from C-frags directly ----
            #pragma unroll
            for (int kc = 0; kc < 4; kc++) {
                // A-frags: S chunks 2kc (k 0-7) and 2kc+1 (k 8-15)
                uint32_t pa0 = pack_bf16x2(sf[2*kc  ][0], sf[2*kc  ][1]);
                uint32_t pa1 = pack_bf16x2(sf[2*kc  ][2], sf[2*kc  ][3]);
                uint32_t pa2 = pack_bf16x2(sf[2*kc+1][0], sf[2*kc+1][1]);
                uint32_t pa3 = pack_bf16x2(sf[2*kc+1][2], sf[2*kc+1][3]);
                uint32_t vaddr = voff_lane + (kb + kc * 16) * 80;
                uint32_t b0, b1, b2, b3, b4, b5, b6, b7;
                ldsm_x4_trans(b0, b1, b2, b3, vaddr);        // d 0-15
                ldsm_x4_trans(b4, b5, b6, b7, vaddr + 32);   // d 16-31
                mma_bf16(co[0], pa0, pa1, pa2, pa3, b0, b1);
                mma_bf16(co[1], pa0, pa1, pa2, pa3, b2, b3);
                mma_bf16(co[2], pa0, pa1, pa2, pa3, b4, b5);
                mma_bf16(co[3], pa0, pa1, pa2, pa3, b6, b7);
            }
        }

        rs0 += __shfl_xor_sync(0xffffffffu, rs0, 1);
        rs0 += __shfl_xor_sync(0xffffffffu, rs0, 2);
        rs1 += __shfl_xor_sync(0xffffffffu, rs1, 1);
        rs1 += __shfl_xor_sync(0xffffffffu, rs1, 2);
        float inv0 = 1.0f / rs0;
        float inv1 = 1.0f / rs1;

        #pragma unroll
        for (int nf = 0; nf < 4; nf++) {
            int col = head * 32 + nf*8 + 2*t;
            obase[((size_t)(mrow + g    ) * 256 + col) >> 1] =
                pack_bf16x2(co[nf][0] * inv0, co[nf][1] * inv0);
            obase[((size_t)(mrow + g + 8) * 256 + col) >> 1] =
                pack_bf16x2(co[nf][2] * inv1, co[nf][3] * inv1);
        }
    }
}

// ============================================================
// Kernel 4: proj GEMM (bf16) + bias + residual(from x) + scatter
// ============================================================
__global__ __launch_bounds__(256, 2) void gemm_proj_bf16(const float* __restrict__ bias,
                                                         const float* __restrict__ x,
                                                         float* __restrict__ out)
{
    __shared__ __align__(16) char smem_raw[128 * 130 * 4];
    __nv_bfloat16* As0 = (__nv_bfloat16*)smem_raw;
    __nv_bfloat16* Bs0 = (__nv_bfloat16*)(smem_raw + 2 * STAGE_BYTES);
    float (*Cs)[130]   = (float (*)[130])smem_raw;

    int tid  = threadIdx.x;
    int lane = tid & 31, warp = tid >> 5;
    int g = lane >> 2, t = lane & 3;
    int wm = (warp & 1) * 64;
    int wn = (warp >> 1) * 32;

    const __nv_bfloat16* Ab = g_att_bf   + (size_t)blockIdx.y * 128 * 256;
    const __nv_bfloat16* Bb = g_wproj_bf + (size_t)blockIdx.x * 128 * 256;

    uint32_t asb = (uint32_t)__cvta_generic_to_shared(As0);
    uint32_t bsb = (uint32_t)__cvta_generic_to_shared(Bs0);

    float c[4][4][4] = {};
    gemm_bf16_main(c, Ab, Bb, asb, bsb);

    __syncthreads();

    int nbase = blockIdx.x * 128;
    #pragma unroll
    for (int m = 0; m < 4; m++) {
        int rl = wm + m*16 + g;
        #pragma unroll
        for (int j = 0; j < 4; j++) {
            int cl = wn + j*8 + 2*t;
            float2 bv = *(const float2*)&bias[nbase + cl];
            *(float2*)&Cs[rl    ][cl] = make_float2(c[m][j][0] + bv.x, c[m][j][1] + bv.y);
            *(float2*)&Cs[rl + 8][cl] = make_float2(c[m][j][2] + bv.x, c[m][j][3] + bv.y);
        }
    }
    __syncthreads();

    int by   = blockIdx.y;
    int n    = by >> 1;
    int half = by & 1;
    int b  = n >> 6, hi = (n >> 3) & 7, wi = n & 7;

    int cc  = tid & 127;
    int trh = tid >> 7;
    #pragma unroll
    for (int tr2 = 0; tr2 < 8; tr2++) {
        int tr = tr2 * 2 + trh;
        int t2 = tr >> 3, r = tr & 7;
        int l0 = t2 * 64 + r * 8;
        int t_full = half * 2 + t2;
        int bt = b * 4 + t_full;
        int h  = hi * 8 + r;
        int col = nbase + cc;
        size_t oaddr = (((size_t)bt * 256 + col) * 64 + h) * 64 + wi * 8;
        #pragma unroll
        for (int j = 0; j < 2; j++) {
            float4 xr = *(const float4*)&x[oaddr + 4*j];
            float4 v;
            v.x = Cs[l0 + 4*j + 0][cc] + xr.x;
            v.y = Cs[l0 + 4*j + 1][cc] + xr.y;
            v.z = Cs[l0 + 4*j + 2][cc] + xr.z;
            v.w = Cs[l0 + 4*j + 3][cc] + xr.w;
            *(float4*)&out[oaddr + 4*j] = v;
        }
    }
}

// ============================================================
extern "C" void kernel_launch(void* const* d_in, const int* in_sizes, int n_in,
                              void* d_out, int out_size)
{
    const float* x      = (const float*)d_in[0];
    const float* w_qkv  = (const float*)d_in[1];
    const float* b_qkv  = (const float*)d_in[2];
    const float* w_proj = (const float*)d_in[3];
    const float* b_proj = (const float*)d_in[4];
    const float* gamma  = (const float*)d_in[5];
    const float* beta   = (const float*)d_in[6];
    float* out = (float*)d_out;

    prep_weights<<<768, 256>>>(w_qkv, w_proj);
    ln_gather_kernel<<<512, 256>>>(x, gamma, beta);
    gemm_qkv_bf16<<<dim3(6, 256), 256>>>(b_qkv);
    attn_mma<<<NWIN * 8, 256>>>();
    gemm_proj_bf16<<<dim3(2, 256), 256>>>(b_proj, x, out);
}

// round 12
// speedup vs baseline: 1.8687x; 1.0104x over previous
#include <cuda_runtime.h>
#include <cuda_bf16.h>
#include <math.h>
#include <stdint.h>

#define CCH   256
#define TT      4
#define HH     64
#define WWID   64
#define NWIN  128
#define MTOT  (NWIN*256)
#define ATT_SCALE 0.1767766952966369f
#define LOG2E     1.4426950408889634f

// -------- global scratch --------
__device__ __nv_bfloat16  g_xn_bf[MTOT * CCH];       // LN output (bf16)
__device__ float          g_qk   [MTOT * 512];       // fp32: q scaled(*log2e)+tf32+perm | k tf32+perm
__device__ __nv_bfloat16  g_v_bf [MTOT * CCH];       // v (bf16)
__device__ __nv_bfloat16  g_att_bf[MTOT * CCH];      // attention output (bf16)
__device__ __nv_bfloat16  g_wqkv_bf[768 * 256];
__device__ __nv_bfloat16  g_wproj_bf[256 * 256];

__device__ __forceinline__ float to_tf32(float x) {
    float r;
    asm("cvt.rna.tf32.f32 %0, %1;" : "=f"(r) : "f"(x));
    return r;
}

__device__ __forceinline__ float ex2_approx(float x) {
    float r;
    asm("ex2.approx.f32 %0, %1;" : "=f"(r) : "f"(x));
    return r;
}

// pack (lo, hi) floats into bf16x2 word
__device__ __forceinline__ uint32_t pack_bf16x2(float lo, float hi) {
    uint32_t r;
    asm("cvt.rn.bf16x2.f32 %0, %1, %2;" : "=r"(r) : "f"(hi), "f"(lo));
    return r;
}

__device__ __forceinline__ void mma_tf32(float* c,
                                         uint32_t a0, uint32_t a1, uint32_t a2, uint32_t a3,
                                         uint32_t b0, uint32_t b1) {
    asm volatile("mma.sync.aligned.m16n8k8.row.col.f32.tf32.tf32.f32 "
                 "{%0,%1,%2,%3}, {%4,%5,%6,%7}, {%8,%9}, {%0,%1,%2,%3};"
                 : "+f"(c[0]), "+f"(c[1]), "+f"(c[2]), "+f"(c[3])
                 : "r"(a0), "r"(a1), "r"(a2), "r"(a3), "r"(b0), "r"(b1));
}

__device__ __forceinline__ void mma_bf16(float* c,
                                         uint32_t a0, uint32_t a1, uint32_t a2, uint32_t a3,
                                         uint32_t b0, uint32_t b1) {
    asm volatile("mma.sync.aligned.m16n8k16.row.col.f32.bf16.bf16.f32 "
                 "{%0,%1,%2,%3}, {%4,%5,%6,%7}, {%8,%9}, {%0,%1,%2,%3};"
                 : "+f"(c[0]), "+f"(c[1]), "+f"(c[2]), "+f"(c[3])
                 : "r"(a0), "r"(a1), "r"(a2), "r"(a3), "r"(b0), "r"(b1));
}

__device__ __forceinline__ void ldsm_x4(uint32_t& r0, uint32_t& r1, uint32_t& r2, uint32_t& r3,
                                        uint32_t addr) {
    asm volatile("ldmatrix.sync.aligned.m8n8.x4.shared.b16 {%0,%1,%2,%3}, [%4];"
                 : "=r"(r0), "=r"(r1), "=r"(r2), "=r"(r3) : "r"(addr));
}

__device__ __forceinline__ void ldsm_x4_trans(uint32_t& r0, uint32_t& r1, uint32_t& r2, uint32_t& r3,
                                              uint32_t addr) {
    asm volatile("ldmatrix.sync.aligned.m8n8.x4.trans.shared.b16 {%0,%1,%2,%3}, [%4];"
                 : "=r"(r0), "=r"(r1), "=r"(r2), "=r"(r3) : "r"(addr));
}

__device__ __forceinline__ void cpasync16(uint32_t dst, const void* src) {
    asm volatile("cp.async.ca.shared.global [%0], [%1], 16;\n" :: "r"(dst), "l"(src));
}
#define CP_COMMIT asm volatile("cp.async.commit_group;\n" ::: "memory")
#define CP_WAIT1  asm volatile("cp.async.wait_group 1;\n" ::: "memory")
#define CP_WAIT0  asm volatile("cp.async.wait_group 0;\n" ::: "memory")

// ============================================================
// Kernel 0: weight prep (fp32 -> bf16 copies)
// ============================================================
__global__ void prep_weights(const float* __restrict__ wq, const float* __restrict__ wp)
{
    int i = blockIdx.x * blockDim.x + threadIdx.x;
    if (i < 768 * 256)  g_wqkv_bf[i]  = __float2bfloat16_rn(wq[i]);
    if (i < 256 * 256)  g_wproj_bf[i] = __float2bfloat16_rn(wp[i]);
}

// ============================================================
// Kernel 1: coalesced gather + LayerNorm (bf16 xn only)
// ============================================================
__global__ __launch_bounds__(256) void ln_gather_kernel(const float* __restrict__ x,
                                                        const float* __restrict__ gamma,
                                                        const float* __restrict__ beta)
{
    __shared__ float tile[256][65];
    __shared__ float rsum[4][64], rsq[4][64];
    __shared__ float mus[64], rstds[64];

    int bx  = blockIdx.x;
    int bt  = bx >> 6;
    int h   = bx & 63;
    int tid = threadIdx.x;

    const float* slice = x + ((size_t)bt * 256) * 4096 + h * 64;

    int cl = tid >> 4;
    int w4 = (tid & 15) * 4;
    #pragma unroll
    for (int it = 0; it < 16; it++) {
        int c = it * 16 + cl;
        float4 v = *(const float4*)(slice + (size_t)c * 4096 + w4);
        tile[c][w4 + 0] = v.x; tile[c][w4 + 1] = v.y;
        tile[c][w4 + 2] = v.z; tile[c][w4 + 3] = v.w;
    }
    __syncthreads();

    {
        int w = tid & 63, part = tid >> 6;
        float s = 0.f, q = 0.f;
        #pragma unroll
        for (int i = 0; i < 64; i++) {
            float v = tile[part * 64 + i][w];
            s += v; q += v * v;
        }
        rsum[part][w] = s; rsq[part][w] = q;
    }
    __syncthreads();
    if (tid < 64) {
        float tot = rsum[0][tid] + rsum[1][tid] + rsum[2][tid] + rsum[3][tid];
        float tq  = rsq[0][tid]  + rsq[1][tid]  + rsq[2][tid]  + rsq[3][tid];
        float mu  = tot * (1.0f / 256.0f);
        float var = tq * (1.0f / 256.0f) - mu * mu;
        mus[tid]  = mu;
        rstds[tid] = rsqrtf(var + 1e-5f);
    }
    __syncthreads();

    int c = tid;
    float gm = gamma[c], be = beta[c];
    int b  = bt >> 2, t = bt & 3;
    int hi = h >> 3, r = h & 7;
    int nbase = b * 64 + hi * 8;
    int lbase = t * 64 + r * 8;
    #pragma unroll 8
    for (int w = 0; w < 64; w++) {
        int n = nbase + (w >> 3);
        int l = lbase + (w & 7);
        size_t m = (size_t)n * 256 + l;
        float val = tile[c][w];
        float xn  = (val - mus[w]) * rstds[w] * gm + be;
        g_xn_bf[m * 256 + c] = __float2bfloat16_rn(xn);
    }
}

// ============================================================
// bf16 GEMM common: 128x128 block, BK=32, 8 warps (64x32 each),
// pitch-40 bf16 smem rows, cp.async 2-stage.
// ============================================================
#define STAGE_BYTES (128 * 40 * 2)

__device__ __forceinline__ void stage_load_bf(uint32_t sA, uint32_t sB,
                                              const __nv_bfloat16* Ag,
                                              const __nv_bfloat16* Bg,
                                              int lrow, int lhalf, int kt)
{
    const __nv_bfloat16* a = Ag + (size_t)lrow * 256 + kt + lhalf * 16;
    const __nv_bfloat16* b = Bg + (size_t)lrow * 256 + kt + lhalf * 16;
    uint32_t da = sA + (lrow * 40 + lhalf * 16) * 2;
    uint32_t db = sB + (lrow * 40 + lhalf * 16) * 2;
    cpasync16(da,      a);
    cpasync16(da + 16, a + 8);
    cpasync16(db,      b);
    cpasync16(db + 16, b + 8);
}

__device__ __forceinline__ void gemm_bf16_main(float (*c)[4][4],
                                               const __nv_bfloat16* Ab,
                                               const __nv_bfloat16* Bb,
                                               uint32_t asb, uint32_t bsb)
{
    int tid  = threadIdx.x;
    int lane = tid & 31, warp = tid >> 5;
    int wm = (warp & 1) * 64;
    int wn = (warp >> 1) * 32;

    int lrow = tid >> 1, lhalf = tid & 1;

    int a_row = lane & 15;
    int a_col = (lane >> 4) * 8;
    int b_row = (lane & 7) + (lane >> 4) * 8;
    int b_col = ((lane >> 3) & 1) * 8;

    uint32_t aS[2] = { asb, asb + STAGE_BYTES };
    uint32_t bS[2] = { bsb, bsb + STAGE_BYTES };

    stage_load_bf(aS[0], bS[0], Ab, Bb, lrow, lhalf, 0);
    CP_COMMIT;

    for (int it = 0; it < 8; it++) {
        if (it < 7)
            stage_load_bf(aS[(it+1)&1], bS[(it+1)&1], Ab, Bb, lrow, lhalf, (it+1)*32);
        CP_COMMIT;
        CP_WAIT1;
        __syncthreads();
        int s = it & 1;
        #pragma unroll
        for (int ks = 0; ks < 2; ks++) {
            uint32_t af[4][4];
            #pragma unroll
            for (int mi = 0; mi < 4; mi++) {
                uint32_t addr = aS[s] + ((wm + mi*16 + a_row) * 40 + ks*16 + a_col) * 2;
                ldsm_x4(af[mi][0], af[mi][1], af[mi][2], af[mi][3], addr);
            }
            uint32_t bf[4][2];
            {
                uint32_t addr0 = bS[s] + ((wn +  0 + b_row) * 40 + ks*16 + b_col) * 2;
                uint32_t addr1 = bS[s] + ((wn + 16 + b_row) * 40 + ks*16 + b_col) * 2;
                ldsm_x4(bf[0][0], bf[0][1], bf[1][0], bf[1][1], addr0);
                ldsm_x4(bf[2][0], bf[2][1], bf[3][0], bf[3][1], addr1);
            }
            #pragma unroll
            for (int mi = 0; mi < 4; mi++)
                #pragma unroll
                for (int j = 0; j < 4; j++)
                    mma_bf16(c[mi][j], af[mi][0], af[mi][1], af[mi][2], af[mi][3],
                             bf[j][0], bf[j][1]);
        }
        __syncthreads();
    }
}

// ============================================================
// Kernel 2: QKV GEMM (bf16).  Epilogue: q scaled by ATT_SCALE*LOG2E,
// q/k d-permuted fp32 into g_qk[M,512]; v packed bf16 into g_v_bf.
// ============================================================
__global__ __launch_bounds__(256, 2) void gemm_qkv_bf16(const float* __restrict__ bias)
{
    __shared__ __align__(16) __nv_bfloat16 As[2][128][40];
    __shared__ __align__(16) __nv_bfloat16 Bs[2][128][40];

    int tid  = threadIdx.x;
    int lane = tid & 31, warp = tid >> 5;
    int g = lane >> 2, t = lane & 3;
    int wm = (warp & 1) * 64;
    int wn = (warp >> 1) * 32;

    const __nv_bfloat16* Ab = g_xn_bf   + (size_t)blockIdx.y * 128 * 256;
    const __nv_bfloat16* Bb = g_wqkv_bf + (size_t)blockIdx.x * 128 * 256;

    uint32_t asb = (uint32_t)__cvta_generic_to_shared(&As[0][0][0]);
    uint32_t bsb = (uint32_t)__cvta_generic_to_shared(&Bs[0][0][0]);

    float c[4][4][4] = {};
    gemm_bf16_main(c, Ab, Bb, asb, bsb);

    int mbase = blockIdx.y * 128 + wm;
    int nbase = blockIdx.x * 128 + wn;

    if (blockIdx.x < 4) {        // q and k: fp32, tf32-rounded, d-permuted
        float sc = (blockIdx.x < 2) ? ATT_SCALE * LOG2E : 1.0f;
        #pragma unroll
        for (int m = 0; m < 4; m++) {
            int row0 = mbase + m*16 + g;
            #pragma unroll
            for (int j = 0; j < 4; j++) {
                int col = nbase + j*8 + 2*t;      // 0..511
                float2 bv = *(const float2*)&bias[col];
                float v00 = to_tf32((c[m][j][0] + bv.x) * sc);
                float v01 = to_tf32((c[m][j][1] + bv.y) * sc);
                float v10 = to_tf32((c[m][j][2] + bv.x) * sc);
                float v11 = to_tf32((c[m][j][3] + bv.y) * sc);
                int b32 = col & ~31;
                int d0  = col & 31, d1 = d0 + 1;
                int p0  = ((d0 & 3) << 3) + (d0 >> 2);
                int p1  = ((d1 & 3) << 3) + (d1 >> 2);
                g_qk[(size_t)row0       * 512 + b32 + p0] = v00;
                g_qk[(size_t)row0       * 512 + b32 + p1] = v01;
                g_qk[(size_t)(row0 + 8) * 512 + b32 + p0] = v10;
                g_qk[(size_t)(row0 + 8) * 512 + b32 + p1] = v11;
            }
        }
    } else {                      // v: bf16 packed
        uint32_t* vout = (uint32_t*)g_v_bf;
        #pragma unroll
        for (int m = 0; m < 4; m++) {
            int row0 = mbase + m*16 + g;
            #pragma unroll
            for (int j = 0; j < 4; j++) {
                int col = nbase + j*8 + 2*t;      // 512..767
                float2 bv = *(const float2*)&bias[col];
                int vcol = col - 512;
                vout[((size_t)row0       * 256 + vcol) >> 1] =
                    pack_bf16x2(c[m][j][0] + bv.x, c[m][j][1] + bv.y);
                vout[((size_t)(row0 + 8) * 256 + vcol) >> 1] =
                    pack_bf16x2(c[m][j][2] + bv.x, c[m][j][3] + bv.y);
            }
        }
    }
}

// ============================================================
// Kernel 3: attention. m32 warp tiles: each warp owns 32 queries
// (two 16-row mma tiles), K/V fragments loaded ONCE and shared by
// both tiles. Key chunk = 32 (keeps sf in register budget).
// QK^T tf32; PV bf16 m16n8k16 with register-packed P.
// ============================================================
__global__ __launch_bounds__(256, 2) void attn_mma()
{
    __shared__ float Ks[256 * 32];
    __shared__ __align__(16) __nv_bfloat16 Vs[256 * 40];   // [key][40], 80B pitch

    int win  = blockIdx.x >> 3;
    int head = blockIdx.x & 7;
    int tid  = threadIdx.x;
    int lane = tid & 31, warp = tid >> 5;
    int g = lane >> 2, t = lane & 3;

    const float* baseQ = g_qk + (size_t)win * 256 * 512 + head * 32;
    const float* baseK = baseQ + 256;
    const __nv_bfloat16* baseV = g_v_bf + (size_t)win * 256 * 256 + head * 32;
    uint32_t* obase = (uint32_t*)g_att_bf + (size_t)win * 256 * 128;

    uint32_t vs_base = (uint32_t)__cvta_generic_to_shared(Vs);

    int keyl = tid >> 3;
    int qc   = tid & 7;

    // --- K via cp.async into swizzled fp32 chunks ---
    #pragma unroll
    for (int it = 0; it < 8; it++) {
        int key = it * 32 + keyl;
        int qsw = qc ^ (key & 7);
        uint32_t dst = (uint32_t)__cvta_generic_to_shared(&Ks[key * 32 + qsw * 4]);
        cpasync16(dst, baseK + (size_t)key * 512 + qc * 4);
    }
    // --- V via cp.async, natural [key][d] bf16, pitch 40 ---
    {
        int vkey = tid;
        uint32_t dst = vs_base + vkey * 80;
        const __nv_bfloat16* src = baseV + (size_t)vkey * 256;
        cpasync16(dst,      src);
        cpasync16(dst + 16, src + 8);
        cpasync16(dst + 32, src + 16);
        cpasync16(dst + 48, src + 24);
    }
    CP_COMMIT;

    // --- Q fragments for this warp's 32 queries (4 row-groups x 8) ---
    int mrow = warp * 32;
    float Q[4][8];
    {
        const float* qp = baseQ + (size_t)mrow * 512 + t * 8;
        #pragma unroll
        for (int hh = 0; hh < 4; hh++) {
            *(float4*)&Q[hh][0] = *(const float4*)(qp + (size_t)(g + hh * 8) * 512);
            *(float4*)&Q[hh][4] = *(const float4*)(qp + (size_t)(g + hh * 8) * 512 + 4);
        }
    }

    CP_WAIT0;
    __syncthreads();

    // ldmatrix.trans lane address offset
    int mat = lane >> 3;
    uint32_t voff_lane = vs_base + ((mat & 1) * 8 + (lane & 7)) * 80 + (mat >> 1) * 16;

    float rs[4] = {0.f, 0.f, 0.f, 0.f};   // [tile0 r0, tile0 r1, tile1 r0, tile1 r1]
    float co[2][4][4] = {};

    #pragma unroll
    for (int ch = 0; ch < 8; ch++) {
        int kb = ch * 32;

        // ---- S = Q K^T : 32 queries x 32 keys, tf32; kbuf shared ----
        float sf[2][4][4];
        #pragma unroll
        for (int ta = 0; ta < 2; ta++)
            #pragma unroll
            for (int nf = 0; nf < 4; nf++) {
                sf[ta][nf][0]=0.f; sf[ta][nf][1]=0.f; sf[ta][nf][2]=0.f; sf[ta][nf][3]=0.f;
            }
        #pragma unroll
        for (int nf = 0; nf < 4; nf++) {
            int key = kb + nf * 8 + g;
            const float* kr = &Ks[key * 32];
            float kbuf[8];
            *(float4*)&kbuf[0] = *(const float4*)(kr + (((2*t    ) ^ g) << 2));
            *(float4*)&kbuf[4] = *(const float4*)(kr + (((2*t + 1) ^ g) << 2));
            #pragma unroll
            for (int kf = 0; kf < 4; kf++) {
                mma_tf32(sf[0][nf],
                         __float_as_uint(Q[0][2*kf]),   __float_as_uint(Q[1][2*kf]),
                         __float_as_uint(Q[0][2*kf+1]), __float_as_uint(Q[1][2*kf+1]),
                         __float_as_uint(kbuf[2*kf]),   __float_as_uint(kbuf[2*kf+1]));
                mma_tf32(sf[1][nf],
                         __float_as_uint(Q[2][2*kf]),   __float_as_uint(Q[3][2*kf]),
                         __float_as_uint(Q[2][2*kf+1]), __float_as_uint(Q[3][2*kf+1]),
                         __float_as_uint(kbuf[2*kf]),   __float_as_uint(kbuf[2*kf+1]));
            }
        }

        // ---- exp2 + rowsum ----
        #pragma unroll
        for (int ta = 0; ta < 2; ta++)
            #pragma unroll
            for (int nf = 0; nf < 4; nf++) {
                float e0 = ex2_approx(sf[ta][nf][0]);
                float e1 = ex2_approx(sf[ta][nf][1]);
                float e2 = ex2_approx(sf[ta][nf][2]);
                float e3 = ex2_approx(sf[ta][nf][3]);
                rs[ta*2 + 0] += e0 + e1;
                rs[ta*2 + 1] += e2 + e3;
                sf[ta][nf][0] = e0; sf[ta][nf][1] = e1;
                sf[ta][nf][2] = e2; sf[ta][nf][3] = e3;
            }

        // ---- O += P V : V ldsm shared by both tiles ----
        #pragma unroll
        for (int kc = 0; kc < 2; kc++) {
            uint32_t vaddr = voff_lane + (kb + kc * 16) * 80;
            uint32_t b0, b1, b2, b3, b4, b5, b6, b7;
            ldsm_x4_trans(b0, b1, b2, b3, vaddr);        // d 0-15
            ldsm_x4_trans(b4, b5, b6, b7, vaddr + 32);   // d 16-31
            #pragma unroll
            for (int ta = 0; ta < 2; ta++) {
                uint32_t pa0 = pack_bf16x2(sf[ta][2*kc  ][0], sf[ta][2*kc  ][1]);
                uint32_t pa1 = pack_bf16x2(sf[ta][2*kc  ][2], sf[ta][2*kc  ][3]);
                uint32_t pa2 = pack_bf16x2(sf[ta][2*kc+1][0], sf[ta][2*kc+1][1]);
                uint32_t pa3 = pack_bf16x2(sf[ta][2*kc+1][2], sf[ta][2*kc+1][3]);
                mma_bf16(co[ta][0], pa0, pa1, pa2, pa3, b0, b1);
                mma_bf16(co[ta][1], pa0, pa1, pa2, pa3, b2, b3);
                mma_bf16(co[ta][2], pa0, pa1, pa2, pa3, b4, b5);
                mma_bf16(co[ta][3], pa0, pa1, pa2, pa3, b6, b7);
            }
        }
    }

    // ---- epilogue per tile ----
    #pragma unroll
    for (int ta = 0; ta < 2; ta++) {
        float r0 = rs[ta*2 + 0];
        float r1 = rs[ta*2 + 1];
        r0 += __shfl_xor_sync(0xffffffffu, r0, 1);
        r0 += __shfl_xor_sync(0xffffffffu, r0, 2);
        r1 += __shfl_xor_sync(0xffffffffu, r1, 1);
        r1 += __shfl_xor_sync(0xffffffffu, r1, 2);
        float inv0 = 1.0f / r0;
        float inv1 = 1.0f / r1;

        int mr = mrow + ta * 16;
        #pragma unroll
        for (int nf = 0; nf < 4; nf++) {
            int col = head * 32 + nf*8 + 2*t;
            obase[((size_t)(mr + g    ) * 256 + col) >> 1] =
                pack_bf16x2(co[ta][nf][0] * inv0, co[ta][nf][1] * inv0);
            obase[((size_t)(mr + g + 8) * 256 + col) >> 1] =
                pack_bf16x2(co[ta][nf][2] * inv1, co[ta][nf][3] * inv1);
        }
    }
}

// ============================================================
// Kernel 4: proj GEMM (bf16) + bias + residual(from x) + scatter
// ============================================================
__global__ __launch_bounds__(256, 2) void gemm_proj_bf16(const float* __restrict__ bias,
                                                         const float* __restrict__ x,
                                                         float* __restrict__ out)
{
    __shared__ __align__(16) char smem_raw[128 * 130 * 4];
    __nv_bfloat16* As0 = (__nv_bfloat16*)smem_raw;
    __nv_bfloat16* Bs0 = (__nv_bfloat16*)(smem_raw + 2 * STAGE_BYTES);
    float (*Cs)[130]   = (float (*)[130])smem_raw;

    int tid  = threadIdx.x;
    int lane = tid & 31, warp = tid >> 5;
    int g = lane >> 2, t = lane & 3;
    int wm = (warp & 1) * 64;
    int wn = (warp >> 1) * 32;

    const __nv_bfloat16* Ab = g_att_bf   + (size_t)blockIdx.y * 128 * 256;
    const __nv_bfloat16* Bb = g_wproj_bf + (size_t)blockIdx.x * 128 * 256;

    uint32_t asb = (uint32_t)__cvta_generic_to_shared(As0);
    uint32_t bsb = (uint32_t)__cvta_generic_to_shared(Bs0);

    float c[4][4][4] = {};
    gemm_bf16_main(c, Ab, Bb, asb, bsb);

    __syncthreads();

    int nbase = blockIdx.x * 128;
    #pragma unroll
    for (int m = 0; m < 4; m++) {
        int rl = wm + m*16 + g;
        #pragma unroll
        for (int j = 0; j < 4; j++) {
            int cl = wn + j*8 + 2*t;
            float2 bv = *(const float2*)&bias[nbase + cl];
            *(float2*)&Cs[rl    ][cl] = make_float2(c[m][j][0] + bv.x, c[m][j][1] + bv.y);
            *(float2*)&Cs[rl + 8][cl] = make_float2(c[m][j][2] + bv.x, c[m][j][3] + bv.y);
        }
    }
    __syncthreads();

    int by   = blockIdx.y;
    int n    = by >> 1;
    int half = by & 1;
    int b  = n >> 6, hi = (n >> 3) & 7, wi = n & 7;

    int cc  = tid & 127;
    int trh = tid >> 7;
    #pragma unroll
    for (int tr2 = 0; tr2 < 8; tr2++) {
        int tr = tr2 * 2 + trh;
        int t2 = tr >> 3, r = tr & 7;
        int l0 = t2 * 64 + r * 8;
        int t_full = half * 2 + t2;
        int bt = b * 4 + t_full;
        int h  = hi * 8 + r;
        int col = nbase + cc;
        size_t oaddr = (((size_t)bt * 256 + col) * 64 + h) * 64 + wi * 8;
        #pragma unroll
        for (int j = 0; j < 2; j++) {
            float4 xr = *(const float4*)&x[oaddr + 4*j];
            float4 v;
            v.x = Cs[l0 + 4*j + 0][cc] + xr.x;
            v.y = Cs[l0 + 4*j + 1][cc] + xr.y;
            v.z = Cs[l0 + 4*j + 2][cc] + xr.z;
            v.w = Cs[l0 + 4*j + 3][cc] + xr.w;
            *(float4*)&out[oaddr + 4*j] = v;
        }
    }
}

// ============================================================
extern "C" void kernel_launch(void* const* d_in, const int* in_sizes, int n_in,
                              void* d_out, int out_size)
{
    const float* x      = (const float*)d_in[0];
    const float* w_qkv  = (const float*)d_in[1];
    const float* b_qkv  = (const float*)d_in[2];
    const float* w_proj = (const float*)d_in[3];
    const float* b_proj = (const float*)d_in[4];
    const float* gamma  = (const float*)d_in[5];
    const float* beta   = (const float*)d_in[6];
    float* out = (float*)d_out;

    prep_weights<<<768, 256>>>(w_qkv, w_proj);
    ln_gather_kernel<<<512, 256>>>(x, gamma, beta);
    gemm_qkv_bf16<<<dim3(6, 256), 256>>>(b_qkv);
    attn_mma<<<NWIN * 8, 256>>>();
    gemm_proj_bf16<<<dim3(2, 256), 256>>>(b_proj, x, out);
}

// round 13
// speedup vs baseline: 2.1706x; 1.1615x over previous
#include <cuda_runtime.h>
#include <cuda_bf16.h>
#include <math.h>
#include <stdint.h>

#define CCH   256
#define TT      4
#define HH     64
#define WWID   64
#define NWIN  128
#define MTOT  (NWIN*256)
#define ATT_SCALE 0.1767766952966369f
#define LOG2E     1.4426950408889634f

// -------- global scratch --------
__device__ __nv_bfloat16  g_xn_bf[MTOT * CCH];       // LN output (bf16)
__device__ __nv_bfloat16  g_q_bf [MTOT * CCH];       // q: scaled(*log2e), pair-permuted, bf16
__device__ __nv_bfloat16  g_k_bf [MTOT * CCH];       // k natural bf16
__device__ __nv_bfloat16  g_v_bf [MTOT * CCH];       // v natural bf16
__device__ __nv_bfloat16  g_att_bf[MTOT * CCH];      // attention output (bf16)
__device__ __nv_bfloat16  g_wqkv_bf[768 * 256];
__device__ __nv_bfloat16  g_wproj_bf[256 * 256];

__device__ __forceinline__ float ex2_approx(float x) {
    float r;
    asm("ex2.approx.f32 %0, %1;" : "=f"(r) : "f"(x));
    return r;
}

// pack (lo, hi) floats into bf16x2 word
__device__ __forceinline__ uint32_t pack_bf16x2(float lo, float hi) {
    uint32_t r;
    asm("cvt.rn.bf16x2.f32 %0, %1, %2;" : "=r"(r) : "f"(hi), "f"(lo));
    return r;
}

__device__ __forceinline__ void mma_bf16(float* c,
                                         uint32_t a0, uint32_t a1, uint32_t a2, uint32_t a3,
                                         uint32_t b0, uint32_t b1) {
    asm volatile("mma.sync.aligned.m16n8k16.row.col.f32.bf16.bf16.f32 "
                 "{%0,%1,%2,%3}, {%4,%5,%6,%7}, {%8,%9}, {%0,%1,%2,%3};"
                 : "+f"(c[0]), "+f"(c[1]), "+f"(c[2]), "+f"(c[3])
                 : "r"(a0), "r"(a1), "r"(a2), "r"(a3), "r"(b0), "r"(b1));
}

__device__ __forceinline__ void ldsm_x4(uint32_t& r0, uint32_t& r1, uint32_t& r2, uint32_t& r3,
                                        uint32_t addr) {
    asm volatile("ldmatrix.sync.aligned.m8n8.x4.shared.b16 {%0,%1,%2,%3}, [%4];"
                 : "=r"(r0), "=r"(r1), "=r"(r2), "=r"(r3) : "r"(addr));
}

__device__ __forceinline__ void ldsm_x4_trans(uint32_t& r0, uint32_t& r1, uint32_t& r2, uint32_t& r3,
                                              uint32_t addr) {
    asm volatile("ldmatrix.sync.aligned.m8n8.x4.trans.shared.b16 {%0,%1,%2,%3}, [%4];"
                 : "=r"(r0), "=r"(r1), "=r"(r2), "=r"(r3) : "r"(addr));
}

__device__ __forceinline__ void cpasync16(uint32_t dst, const void* src) {
    asm volatile("cp.async.ca.shared.global [%0], [%1], 16;\n" :: "r"(dst), "l"(src));
}
#define CP_COMMIT asm volatile("cp.async.commit_group;\n" ::: "memory")
#define CP_WAIT1  asm volatile("cp.async.wait_group 1;\n" ::: "memory")
#define CP_WAIT0  asm volatile("cp.async.wait_group 0;\n" ::: "memory")

// ============================================================
// Kernel 0: weight prep (fp32 -> bf16 copies)
// ============================================================
__global__ void prep_weights(const float* __restrict__ wq, const float* __restrict__ wp)
{
    int i = blockIdx.x * blockDim.x + threadIdx.x;
    if (i < 768 * 256)  g_wqkv_bf[i]  = __float2bfloat16_rn(wq[i]);
    if (i < 256 * 256)  g_wproj_bf[i] = __float2bfloat16_rn(wp[i]);
}

// ============================================================
// Kernel 1: coalesced gather + LayerNorm (bf16 xn only)
// ============================================================
__global__ __launch_bounds__(256) void ln_gather_kernel(const float* __restrict__ x,
                                                        const float* __restrict__ gamma,
                                                        const float* __restrict__ beta)
{
    __shared__ float tile[256][65];
    __shared__ float rsum[4][64], rsq[4][64];
    __shared__ float mus[64], rstds[64];

    int bx  = blockIdx.x;
    int bt  = bx >> 6;
    int h   = bx & 63;
    int tid = threadIdx.x;

    const float* slice = x + ((size_t)bt * 256) * 4096 + h * 64;

    int cl = tid >> 4;
    int w4 = (tid & 15) * 4;
    #pragma unroll
    for (int it = 0; it < 16; it++) {
        int c = it * 16 + cl;
        float4 v = *(const float4*)(slice + (size_t)c * 4096 + w4);
        tile[c][w4 + 0] = v.x; tile[c][w4 + 1] = v.y;
        tile[c][w4 + 2] = v.z; tile[c][w4 + 3] = v.w;
    }
    __syncthreads();

    {
        int w = tid & 63, part = tid >> 6;
        float s = 0.f, q = 0.f;
        #pragma unroll
        for (int i = 0; i < 64; i++) {
            float v = tile[part * 64 + i][w];
            s += v; q += v * v;
        }
        rsum[part][w] = s; rsq[part][w] = q;
    }
    __syncthreads();
    if (tid < 64) {
        float tot = rsum[0][tid] + rsum[1][tid] + rsum[2][tid] + rsum[3][tid];
        float tq  = rsq[0][tid]  + rsq[1][tid]  + rsq[2][tid]  + rsq[3][tid];
        float mu  = tot * (1.0f / 256.0f);
        float var = tq * (1.0f / 256.0f) - mu * mu;
        mus[tid]  = mu;
        rstds[tid] = rsqrtf(var + 1e-5f);
    }
    __syncthreads();

    int c = tid;
    float gm = gamma[c], be = beta[c];
    int b  = bt >> 2, t = bt & 3;
    int hi = h >> 3, r = h & 7;
    int nbase = b * 64 + hi * 8;
    int lbase = t * 64 + r * 8;
    #pragma unroll 8
    for (int w = 0; w < 64; w++) {
        int n = nbase + (w >> 3);
        int l = lbase + (w & 7);
        size_t m = (size_t)n * 256 + l;
        float val = tile[c][w];
        float xn  = (val - mus[w]) * rstds[w] * gm + be;
        g_xn_bf[m * 256 + c] = __float2bfloat16_rn(xn);
    }
}

// ============================================================
// bf16 GEMM common: 128x128 block, BK=32, 8 warps (64x32 each),
// pitch-40 bf16 smem rows, cp.async 2-stage.
// ============================================================
#define STAGE_BYTES (128 * 40 * 2)

__device__ __forceinline__ void stage_load_bf(uint32_t sA, uint32_t sB,
                                              const __nv_bfloat16* Ag,
                                              const __nv_bfloat16* Bg,
                                              int lrow, int lhalf, int kt)
{
    const __nv_bfloat16* a = Ag + (size_t)lrow * 256 + kt + lhalf * 16;
    const __nv_bfloat16* b = Bg + (size_t)lrow * 256 + kt + lhalf * 16;
    uint32_t da = sA + (lrow * 40 + lhalf * 16) * 2;
    uint32_t db = sB + (lrow * 40 + lhalf * 16) * 2;
    cpasync16(da,      a);
    cpasync16(da + 16, a + 8);
    cpasync16(db,      b);
    cpasync16(db + 16, b + 8);
}

__device__ __forceinline__ void gemm_bf16_main(float (*c)[4][4],
                                               const __nv_bfloat16* Ab,
                                               const __nv_bfloat16* Bb,
                                               uint32_t asb, uint32_t bsb)
{
    int tid  = threadIdx.x;
    int lane = tid & 31, warp = tid >> 5;
    int wm = (warp & 1) * 64;
    int wn = (warp >> 1) * 32;

    int lrow = tid >> 1, lhalf = tid & 1;

    int a_row = lane & 15;
    int a_col = (lane >> 4) * 8;
    int b_row = (lane & 7) + (lane >> 4) * 8;
    int b_col = ((lane >> 3) & 1) * 8;

    uint32_t aS[2] = { asb, asb + STAGE_BYTES };
    uint32_t bS[2] = { bsb, bsb + STAGE_BYTES };

    stage_load_bf(aS[0], bS[0], Ab, Bb, lrow, lhalf, 0);
    CP_COMMIT;

    for (int it = 0; it < 8; it++) {
        if (it < 7)
            stage_load_bf(aS[(it+1)&1], bS[(it+1)&1], Ab, Bb, lrow, lhalf, (it+1)*32);
        CP_COMMIT;
        CP_WAIT1;
        __syncthreads();
        int s = it & 1;
        #pragma unroll
        for (int ks = 0; ks < 2; ks++) {
            uint32_t af[4][4];
            #pragma unroll
            for (int mi = 0; mi < 4; mi++) {
                uint32_t addr = aS[s] + ((wm + mi*16 + a_row) * 40 + ks*16 + a_col) * 2;
                ldsm_x4(af[mi][0], af[mi][1], af[mi][2], af[mi][3], addr);
            }
            uint32_t bf[4][2];
            {
                uint32_t addr0 = bS[s] + ((wn +  0 + b_row) * 40 + ks*16 + b_col) * 2;
                uint32_t addr1 = bS[s] + ((wn + 16 + b_row) * 40 + ks*16 + b_col) * 2;
                ldsm_x4(bf[0][0], bf[0][1], bf[1][0], bf[1][1], addr0);
                ldsm_x4(bf[2][0], bf[2][1], bf[3][0], bf[3][1], addr1);
            }
            #pragma unroll
            for (int mi = 0; mi < 4; mi++)
                #pragma unroll
                for (int j = 0; j < 4; j++)
                    mma_bf16(c[mi][j], af[mi][0], af[mi][1], af[mi][2], af[mi][3],
                             bf[j][0], bf[j][1]);
        }
        __syncthreads();
    }
}

// ============================================================
// Kernel 2: QKV GEMM (bf16). Epilogue all-bf16:
//   q (cols 0-255):   *(ATT_SCALE*LOG2E), pair-permuted within head
//   k (cols 256-511): natural
//   v (cols 512-767): natural
// Pair permute: pair j (d=2j,2j+1) of a head stored at word (j&3)*4 + (j>>2),
// so one lane's 4 k16 A-frag words per row are one contiguous uint4.
// ============================================================
__global__ __launch_bounds__(256, 2) void gemm_qkv_bf16(const float* __restrict__ bias)
{
    __shared__ __align__(16) __nv_bfloat16 As[2][128][40];
    __shared__ __align__(16) __nv_bfloat16 Bs[2][128][40];

    int tid  = threadIdx.x;
    int lane = tid & 31, warp = tid >> 5;
    int g = lane >> 2, t = lane & 3;
    int wm = (warp & 1) * 64;
    int wn = (warp >> 1) * 32;

    const __nv_bfloat16* Ab = g_xn_bf   + (size_t)blockIdx.y * 128 * 256;
    const __nv_bfloat16* Bb = g_wqkv_bf + (size_t)blockIdx.x * 128 * 256;

    uint32_t asb = (uint32_t)__cvta_generic_to_shared(&As[0][0][0]);
    uint32_t bsb = (uint32_t)__cvta_generic_to_shared(&Bs[0][0][0]);

    float c[4][4][4] = {};
    gemm_bf16_main(c, Ab, Bb, asb, bsb);

    int mbase = blockIdx.y * 128 + wm;
    int nbase = blockIdx.x * 128 + wn;

    if (blockIdx.x < 2) {               // q: scale + pair-permute
        const float sc = ATT_SCALE * LOG2E;
        uint32_t* qout = (uint32_t*)g_q_bf;
        #pragma unroll
        for (int m = 0; m < 4; m++) {
            int row0 = mbase + m*16 + g;
            #pragma unroll
            for (int j = 0; j < 4; j++) {
                int col = nbase + j*8 + 2*t;          // 0..255
                float2 bv = *(const float2*)&bias[col];
                // pair index within head = j*4 + t -> word position t*4 + j
                int word = (col >> 5) * 16 + t*4 + j;
                qout[(size_t)row0       * 128 + word] =
                    pack_bf16x2((c[m][j][0] + bv.x) * sc, (c[m][j][1] + bv.y) * sc);
                qout[(size_t)(row0 + 8) * 128 + word] =
                    pack_bf16x2((c[m][j][2] + bv.x) * sc, (c[m][j][3] + bv.y) * sc);
            }
        }
    } else {                            // k or v: natural bf16
        uint32_t* outp = (blockIdx.x < 4) ? (uint32_t*)g_k_bf : (uint32_t*)g_v_bf;
        int cbase = (blockIdx.x < 4) ? 256 : 512;
        #pragma unroll
        for (int m = 0; m < 4; m++) {
            int row0 = mbase + m*16 + g;
            #pragma unroll
            for (int j = 0; j < 4; j++) {
                int col = nbase + j*8 + 2*t;          // global qkv col
                float2 bv = *(const float2*)&bias[col];
                int vcol = col - cbase;
                outp[((size_t)row0       * 256 + vcol) >> 1] =
                    pack_bf16x2(c[m][j][0] + bv.x, c[m][j][1] + bv.y);
                outp[((size_t)(row0 + 8) * 256 + vcol) >> 1] =
                    pack_bf16x2(c[m][j][2] + bv.x, c[m][j][3] + bv.y);
            }
        }
    }
}

// ============================================================
// Kernel 3: attention, all-bf16 mma.
// m32 warp tiles (2 x m16), key chunk 32.
// QK^T: bf16 m16n8k16, K natural bf16 in smem, B-frags via ldmatrix.
// PV:   bf16 m16n8k16, P packed from C-frags, V via ldmatrix.trans.
// ============================================================
__global__ __launch_bounds__(256, 2) void attn_mma()
{
    __shared__ __align__(16) __nv_bfloat16 Ks[256 * 40];   // [key][40], 80B pitch
    __shared__ __align__(16) __nv_bfloat16 Vs[256 * 40];

    int win  = blockIdx.x >> 3;
    int head = blockIdx.x & 7;
    int tid  = threadIdx.x;
    int lane = tid & 31, warp = tid >> 5;
    int g = lane >> 2, t = lane & 3;

    const __nv_bfloat16* baseK = g_k_bf + (size_t)win * 256 * 256 + head * 32;
    const __nv_bfloat16* baseV = g_v_bf + (size_t)win * 256 * 256 + head * 32;
    const uint32_t* qwords = (const uint32_t*)g_q_bf + (size_t)win * 256 * 128 + head * 16;
    uint32_t* obase = (uint32_t*)g_att_bf + (size_t)win * 256 * 128;

    uint32_t ks_base = (uint32_t)__cvta_generic_to_shared(Ks);
    uint32_t vs_base = (uint32_t)__cvta_generic_to_shared(Vs);

    // --- K and V via cp.async: each thread loads one key row (64B each) ---
    {
        int key = tid;
        uint32_t dk = ks_base + key * 80;
        uint32_t dv = vs_base + key * 80;
        const __nv_bfloat16* sk = baseK + (size_t)key * 256;
        const __nv_bfloat16* sv = baseV + (size_t)key * 256;
        cpasync16(dk,      sk);      cpasync16(dk + 16, sk + 8);
        cpasync16(dk + 32, sk + 16); cpasync16(dk + 48, sk + 24);
        cpasync16(dv,      sv);      cpasync16(dv + 16, sv + 8);
        cpasync16(dv + 32, sv + 16); cpasync16(dv + 48, sv + 24);
    }
    CP_COMMIT;

    // --- Q A-fragments: one uint4 per row-group (pair-permuted layout) ---
    int mrow = warp * 32;
    uint32_t Qw[4][4];     // [rowgroup][a0h0, a2h0, a0h1, a2h1]
    #pragma unroll
    for (int rg = 0; rg < 4; rg++) {
        int row = mrow + rg * 8 + g;
        *(uint4*)&Qw[rg][0] = *(const uint4*)(qwords + (size_t)row * 128 + t * 4);
    }

    CP_WAIT0;
    __syncthreads();

    // ldmatrix lane offsets
    int bk_row = (lane & 7) + (lane >> 4) * 8;
    int bk_col = ((lane >> 3) & 1) * 8;
    uint32_t koff_lane = ks_base + bk_row * 80 + bk_col * 2;
    int mat = lane >> 3;
    uint32_t voff_lane = vs_base + ((mat & 1) * 8 + (lane & 7)) * 80 + (mat >> 1) * 16;

    float rs[4] = {0.f, 0.f, 0.f, 0.f};
    float co[2][4][4] = {};

    #pragma unroll
    for (int ch = 0; ch < 8; ch++) {
        int kb = ch * 32;

        // ---- S = Q K^T : 32 queries x 32 keys, bf16 k16 ----
        float sf[2][4][4] = {};
        #pragma unroll
        for (int kh = 0; kh < 2; kh++) {
            uint32_t kf[4][2];
            ldsm_x4(kf[0][0], kf[0][1], kf[1][0], kf[1][1],
                    koff_lane + (kb     ) * 80 + kh * 32);
            ldsm_x4(kf[2][0], kf[2][1], kf[3][0], kf[3][1],
                    koff_lane + (kb + 16) * 80 + kh * 32);
            #pragma unroll
            for (int ta = 0; ta < 2; ta++) {
                uint32_t a0 = Qw[2*ta    ][2*kh    ];
                uint32_t a1 = Qw[2*ta + 1][2*kh    ];
                uint32_t a2 = Qw[2*ta    ][2*kh + 1];
                uint32_t a3 = Qw[2*ta + 1][2*kh + 1];
                #pragma unroll
                for (int nf = 0; nf < 4; nf++)
                    mma_bf16(sf[ta][nf], a0, a1, a2, a3, kf[nf][0], kf[nf][1]);
            }
        }

        // ---- exp2 + rowsum ----
        #pragma unroll
        for (int ta = 0; ta < 2; ta++)
            #pragma unroll
            for (int nf = 0; nf < 4; nf++) {
                float e0 = ex2_approx(sf[ta][nf][0]);
                float e1 = ex2_approx(sf[ta][nf][1]);
                float e2 = ex2_approx(sf[ta][nf][2]);
                float e3 = ex2_approx(sf[ta][nf][3]);
                rs[ta*2 + 0] += e0 + e1;
                rs[ta*2 + 1] += e2 + e3;
                sf[ta][nf][0] = e0; sf[ta][nf][1] = e1;
                sf[ta][nf][2] = e2; sf[ta][nf][3] = e3;
            }

        // ---- O += P V : V ldsm shared by both tiles ----
        #pragma unroll
        for (int kc = 0; kc < 2; kc++) {
            uint32_t vaddr = voff_lane + (kb + kc * 16) * 80;
            uint32_t b0, b1, b2, b3, b4, b5, b6, b7;
            ldsm_x4_trans(b0, b1, b2, b3, vaddr);        // d 0-15
            ldsm_x4_trans(b4, b5, b6, b7, vaddr + 32);   // d 16-31
            #pragma unroll
            for (int ta = 0; ta < 2; ta++) {
                uint32_t pa0 = pack_bf16x2(sf[ta][2*kc  ][0], sf[ta][2*kc  ][1]);
                uint32_t pa1 = pack_bf16x2(sf[ta][2*kc  ][2], sf[ta][2*kc  ][3]);
                uint32_t pa2 = pack_bf16x2(sf[ta][2*kc+1][0], sf[ta][2*kc+1][1]);
                uint32_t pa3 = pack_bf16x2(sf[ta][2*kc+1][2], sf[ta][2*kc+1][3]);
                mma_bf16(co[ta][0], pa0, pa1, pa2, pa3, b0, b1);
                mma_bf16(co[ta][1], pa0, pa1, pa2, pa3, b2, b3);
                mma_bf16(co[ta][2], pa0, pa1, pa2, pa3, b4, b5);
                mma_bf16(co[ta][3], pa0, pa1, pa2, pa3, b6, b7);
            }
        }
    }

    // ---- epilogue per tile ----
    #pragma unroll
    for (int ta = 0; ta < 2; ta++) {
        float r0 = rs[ta*2 + 0];
        float r1 = rs[ta*2 + 1];
        r0 += __shfl_xor_sync(0xffffffffu, r0, 1);
        r0 += __shfl_xor_sync(0xffffffffu, r0, 2);
        r1 += __shfl_xor_sync(0xffffffffu, r1, 1);
        r1 += __shfl_xor_sync(0xffffffffu, r1, 2);
        float inv0 = 1.0f / r0;
        float inv1 = 1.0f / r1;

        int mr = mrow + ta * 16;
        #pragma unroll
        for (int nf = 0; nf < 4; nf++) {
            int col = head * 32 + nf*8 + 2*t;
            obase[((size_t)(mr + g    ) * 256 + col) >> 1] =
                pack_bf16x2(co[ta][nf][0] * inv0, co[ta][nf][1] * inv0);
            obase[((size_t)(mr + g + 8) * 256 + col) >> 1] =
                pack_bf16x2(co[ta][nf][2] * inv1, co[ta][nf][3] * inv1);
        }
    }
}

// ============================================================
// Kernel 4: proj GEMM (bf16) + bias + residual(from x) + scatter
// ============================================================
__global__ __launch_bounds__(256, 2) void gemm_proj_bf16(const float* __restrict__ bias,
                                                         const float* __restrict__ x,
                                                         float* __restrict__ out)
{
    __shared__ __align__(16) char smem_raw[128 * 130 * 4];
    __nv_bfloat16* As0 = (__nv_bfloat16*)smem_raw;
    __nv_bfloat16* Bs0 = (__nv_bfloat16*)(smem_raw + 2 * STAGE_BYTES);
    float (*Cs)[130]   = (float (*)[130])smem_raw;

    int tid  = threadIdx.x;
    int lane = tid & 31, warp = tid >> 5;
    int g = lane >> 2, t = lane & 3;
    int wm = (warp & 1) * 64;
    int wn = (warp >> 1) * 32;

    const __nv_bfloat16* Ab = g_att_bf   + (size_t)blockIdx.y * 128 * 256;
    const __nv_bfloat16* Bb = g_wproj_bf + (size_t)blockIdx.x * 128 * 256;

    uint32_t asb = (uint32_t)__cvta_generic_to_shared(As0);
    uint32_t bsb = (uint32_t)__cvta_generic_to_shared(Bs0);

    float c[4][4][4] = {};
    gemm_bf16_main(c, Ab, Bb, asb, bsb);

    __syncthreads();

    int nbase = blockIdx.x * 128;
    #pragma unroll
    for (int m = 0; m < 4; m++) {
        int rl = wm + m*16 + g;
        #pragma unroll
        for (int j = 0; j < 4; j++) {
            int cl = wn + j*8 + 2*t;
            float2 bv = *(const float2*)&bias[nbase + cl];
            *(float2*)&Cs[rl    ][cl] = make_float2(c[m][j][0] + bv.x, c[m][j][1] + bv.y);
            *(float2*)&Cs[rl + 8][cl] = make_float2(c[m][j][2] + bv.x, c[m][j][3] + bv.y);
        }
    }
    __syncthreads();

    int by   = blockIdx.y;
    int n    = by >> 1;
    int half = by & 1;
    int b  = n >> 6, hi = (n >> 3) & 7, wi = n & 7;

    int cc  = tid & 127;
    int trh = tid >> 7;
    #pragma unroll
    for (int tr2 = 0; tr2 < 8; tr2++) {
        int tr = tr2 * 2 + trh;
        int t2 = tr >> 3, r = tr & 7;
        int l0 = t2 * 64 + r * 8;
        int t_full = half * 2 + t2;
        int bt = b * 4 + t_full;
        int h  = hi * 8 + r;
        int col = nbase + cc;
        size_t oaddr = (((size_t)bt * 256 + col) * 64 + h) * 64 + wi * 8;
        #pragma unroll
        for (int j = 0; j < 2; j++) {
            float4 xr = *(const float4*)&x[oaddr + 4*j];
            float4 v;
            v.x = Cs[l0 + 4*j + 0][cc] + xr.x;
            v.y = Cs[l0 + 4*j + 1][cc] + xr.y;
            v.z = Cs[l0 + 4*j + 2][cc] + xr.z;
            v.w = Cs[l0 + 4*j + 3][cc] + xr.w;
            *(float4*)&out[oaddr + 4*j] = v;
        }
    }
}

// ============================================================
extern "C" void kernel_launch(void* const* d_in, const int* in_sizes, int n_in,
                              void* d_out, int out_size)
{
    const float* x      = (const float*)d_in[0];
    const float* w_qkv  = (const float*)d_in[1];
    const float* b_qkv  = (const float*)d_in[2];
    const float* w_proj = (const float*)d_in[3];
    const float* b_proj = (const float*)d_in[4];
    const float* gamma  = (const float*)d_in[5];
    const float* beta   = (const float*)d_in[6];
    float* out = (float*)d_out;

    prep_weights<<<768, 256>>>(w_qkv, w_proj);
    ln_gather_kernel<<<512, 256>>>(x, gamma, beta);
    gemm_qkv_bf16<<<dim3(6, 256), 256>>>(b_qkv);
    attn_mma<<<NWIN * 8, 256>>>();
    gemm_proj_bf16<<<dim3(2, 256), 256>>>(b_proj, x, out);
}

// round 14
// speedup vs baseline: 2.1976x; 1.0125x over previous
#include <cuda_runtime.h>
#include <cuda_bf16.h>
#include <math.h>
#include <stdint.h>

#define CCH   256
#define TT      4
#define HH     64
#define WWID   64
#define NWIN  128
#define MTOT  (NWIN*256)
#define ATT_SCALE 0.1767766952966369f
#define LOG2E     1.4426950408889634f

// -------- global scratch --------
__device__ __nv_bfloat16  g_xn_bf[MTOT * CCH];       // LN output (bf16)
__device__ __nv_bfloat16  g_q_bf [MTOT * CCH];       // q: scaled(*log2e), pair-permuted, bf16
__device__ __nv_bfloat16  g_k_bf [MTOT * CCH];       // k natural bf16
__device__ __nv_bfloat16  g_v_bf [MTOT * CCH];       // v natural bf16
__device__ __nv_bfloat16  g_att_bf[MTOT * CCH];      // attention output (bf16)
__device__ __nv_bfloat16  g_wqkv_bf[768 * 256];
__device__ __nv_bfloat16  g_wproj_bf[256 * 256];

__device__ __forceinline__ float ex2_approx(float x) {
    float r;
    asm("ex2.approx.f32 %0, %1;" : "=f"(r) : "f"(x));
    return r;
}

// pack (lo, hi) floats into bf16x2 word
__device__ __forceinline__ uint32_t pack_bf16x2(float lo, float hi) {
    uint32_t r;
    asm("cvt.rn.bf16x2.f32 %0, %1, %2;" : "=r"(r) : "f"(hi), "f"(lo));
    return r;
}

__device__ __forceinline__ void mma_bf16(float* c,
                                         uint32_t a0, uint32_t a1, uint32_t a2, uint32_t a3,
                                         uint32_t b0, uint32_t b1) {
    asm volatile("mma.sync.aligned.m16n8k16.row.col.f32.bf16.bf16.f32 "
                 "{%0,%1,%2,%3}, {%4,%5,%6,%7}, {%8,%9}, {%0,%1,%2,%3};"
                 : "+f"(c[0]), "+f"(c[1]), "+f"(c[2]), "+f"(c[3])
                 : "r"(a0), "r"(a1), "r"(a2), "r"(a3), "r"(b0), "r"(b1));
}

__device__ __forceinline__ void ldsm_x4(uint32_t& r0, uint32_t& r1, uint32_t& r2, uint32_t& r3,
                                        uint32_t addr) {
    asm volatile("ldmatrix.sync.aligned.m8n8.x4.shared.b16 {%0,%1,%2,%3}, [%4];"
                 : "=r"(r0), "=r"(r1), "=r"(r2), "=r"(r3) : "r"(addr));
}

__device__ __forceinline__ void ldsm_x4_trans(uint32_t& r0, uint32_t& r1, uint32_t& r2, uint32_t& r3,
                                              uint32_t addr) {
    asm volatile("ldmatrix.sync.aligned.m8n8.x4.trans.shared.b16 {%0,%1,%2,%3}, [%4];"
                 : "=r"(r0), "=r"(r1), "=r"(r2), "=r"(r3) : "r"(addr));
}

__device__ __forceinline__ void cpasync16(uint32_t dst, const void* src) {
    asm volatile("cp.async.ca.shared.global [%0], [%1], 16;\n" :: "r"(dst), "l"(src));
}
#define CP_COMMIT asm volatile("cp.async.commit_group;\n" ::: "memory")
#define CP_WAIT1  asm volatile("cp.async.wait_group 1;\n" ::: "memory")
#define CP_WAIT0  asm volatile("cp.async.wait_group 0;\n" ::: "memory")

// ============================================================
// Kernel 0: weight prep (fp32 -> bf16 copies)
// ============================================================
__global__ void prep_weights(const float* __restrict__ wq, const float* __restrict__ wp)
{
    int i = blockIdx.x * blockDim.x + threadIdx.x;
    if (i < 768 * 256)  g_wqkv_bf[i]  = __float2bfloat16_rn(wq[i]);
    if (i < 256 * 256)  g_wproj_bf[i] = __float2bfloat16_rn(wp[i]);
}

// ============================================================
// Kernel 1: coalesced gather + LayerNorm (bf16 xn only)
// ============================================================
__global__ __launch_bounds__(256) void ln_gather_kernel(const float* __restrict__ x,
                                                        const float* __restrict__ gamma,
                                                        const float* __restrict__ beta)
{
    __shared__ float tile[256][65];
    __shared__ float rsum[4][64], rsq[4][64];
    __shared__ float mus[64], rstds[64];

    int bx  = blockIdx.x;
    int bt  = bx >> 6;
    int h   = bx & 63;
    int tid = threadIdx.x;

    const float* slice = x + ((size_t)bt * 256) * 4096 + h * 64;

    int cl = tid >> 4;
    int w4 = (tid & 15) * 4;
    #pragma unroll
    for (int it = 0; it < 16; it++) {
        int c = it * 16 + cl;
        float4 v = *(const float4*)(slice + (size_t)c * 4096 + w4);
        tile[c][w4 + 0] = v.x; tile[c][w4 + 1] = v.y;
        tile[c][w4 + 2] = v.z; tile[c][w4 + 3] = v.w;
    }
    __syncthreads();

    {
        int w = tid & 63, part = tid >> 6;
        float s = 0.f, q = 0.f;
        #pragma unroll
        for (int i = 0; i < 64; i++) {
            float v = tile[part * 64 + i][w];
            s += v; q += v * v;
        }
        rsum[part][w] = s; rsq[part][w] = q;
    }
    __syncthreads();
    if (tid < 64) {
        float tot = rsum[0][tid] + rsum[1][tid] + rsum[2][tid] + rsum[3][tid];
        float tq  = rsq[0][tid]  + rsq[1][tid]  + rsq[2][tid]  + rsq[3][tid];
        float mu  = tot * (1.0f / 256.0f);
        float var = tq * (1.0f / 256.0f) - mu * mu;
        mus[tid]  = mu;
        rstds[tid] = rsqrtf(var + 1e-5f);
    }
    __syncthreads();

    int c = tid;
    float gm = gamma[c], be = beta[c];
    int b  = bt >> 2, t = bt & 3;
    int hi = h >> 3, r = h & 7;
    int nbase = b * 64 + hi * 8;
    int lbase = t * 64 + r * 8;
    #pragma unroll 8
    for (int w = 0; w < 64; w++) {
        int n = nbase + (w >> 3);
        int l = lbase + (w & 7);
        size_t m = (size_t)n * 256 + l;
        float val = tile[c][w];
        float xn  = (val - mus[w]) * rstds[w] * gm + be;
        g_xn_bf[m * 256 + c] = __float2bfloat16_rn(xn);
    }
}

// ============================================================
// bf16 GEMM common: 128x128 block, BK=32, 8 warps (64x32 each),
// pitch-40 bf16 smem rows, cp.async 3-stage, ONE barrier per k-iter.
// ============================================================
#define STAGE_BYTES (128 * 40 * 2)

__device__ __forceinline__ void stage_load_bf(uint32_t sA, uint32_t sB,
                                              const __nv_bfloat16* Ag,
                                              const __nv_bfloat16* Bg,
                                              int lrow, int lhalf, int kt)
{
    const __nv_bfloat16* a = Ag + (size_t)lrow * 256 + kt + lhalf * 16;
    const __nv_bfloat16* b = Bg + (size_t)lrow * 256 + kt + lhalf * 16;
    uint32_t da = sA + (lrow * 40 + lhalf * 16) * 2;
    uint32_t db = sB + (lrow * 40 + lhalf * 16) * 2;
    cpasync16(da,      a);
    cpasync16(da + 16, a + 8);
    cpasync16(db,      b);
    cpasync16(db + 16, b + 8);
}

__device__ __forceinline__ void gemm_bf16_main(float (*c)[4][4],
                                               const __nv_bfloat16* Ab,
                                               const __nv_bfloat16* Bb,
                                               uint32_t asb, uint32_t bsb)
{
    int tid  = threadIdx.x;
    int lane = tid & 31, warp = tid >> 5;
    int wm = (warp & 1) * 64;
    int wn = (warp >> 1) * 32;

    int lrow = tid >> 1, lhalf = tid & 1;

    int a_row = lane & 15;
    int a_col = (lane >> 4) * 8;
    int b_row = (lane & 7) + (lane >> 4) * 8;
    int b_col = ((lane >> 3) & 1) * 8;

    uint32_t aS[3] = { asb, asb + STAGE_BYTES, asb + 2 * STAGE_BYTES };
    uint32_t bS[3] = { bsb, bsb + STAGE_BYTES, bsb + 2 * STAGE_BYTES };

    // prologue: stages 0 and 1 in flight
    stage_load_bf(aS[0], bS[0], Ab, Bb, lrow, lhalf, 0);
    CP_COMMIT;
    stage_load_bf(aS[1], bS[1], Ab, Bb, lrow, lhalf, 32);
    CP_COMMIT;

    #pragma unroll
    for (int it = 0; it < 8; it++) {
        // own stage-it copies done (tail: drain everything)
        if (it == 7) { CP_WAIT0; } else { CP_WAIT1; }
        __syncthreads();   // publish stage it to all; all threads done reading buf (it+2)%3
        // prefetch 2 tiles ahead into the buffer just vacated
        if (it < 6) {
            stage_load_bf(aS[(it+2)%3], bS[(it+2)%3], Ab, Bb, lrow, lhalf, (it+2)*32);
            CP_COMMIT;
        }
        int s = it % 3;
        #pragma unroll
        for (int ks = 0; ks < 2; ks++) {
            uint32_t af[4][4];
            #pragma unroll
            for (int mi = 0; mi < 4; mi++) {
                uint32_t addr = aS[s] + ((wm + mi*16 + a_row) * 40 + ks*16 + a_col) * 2;
                ldsm_x4(af[mi][0], af[mi][1], af[mi][2], af[mi][3], addr);
            }
            uint32_t bf[4][2];
            {
                uint32_t addr0 = bS[s] + ((wn +  0 + b_row) * 40 + ks*16 + b_col) * 2;
                uint32_t addr1 = bS[s] + ((wn + 16 + b_row) * 40 + ks*16 + b_col) * 2;
                ldsm_x4(bf[0][0], bf[0][1], bf[1][0], bf[1][1], addr0);
                ldsm_x4(bf[2][0], bf[2][1], bf[3][0], bf[3][1], addr1);
            }
            #pragma unroll
            for (int mi = 0; mi < 4; mi++)
                #pragma unroll
                for (int j = 0; j < 4; j++)
                    mma_bf16(c[mi][j], af[mi][0], af[mi][1], af[mi][2], af[mi][3],
                             bf[j][0], bf[j][1]);
        }
    }
    __syncthreads();   // protect buffers before any smem reuse by caller
}

// ============================================================
// Kernel 2: QKV GEMM (bf16). Epilogue all-bf16:
//   q: *(ATT_SCALE*LOG2E), pair-permuted within head; k, v natural.
// ============================================================
__global__ __launch_bounds__(256, 2) void gemm_qkv_bf16(const float* __restrict__ bias)
{
    __shared__ __align__(16) __nv_bfloat16 As[3][128][40];
    __shared__ __align__(16) __nv_bfloat16 Bs[3][128][40];

    int tid  = threadIdx.x;
    int lane = tid & 31, warp = tid >> 5;
    int g = lane >> 2, t = lane & 3;
    int wm = (warp & 1) * 64;
    int wn = (warp >> 1) * 32;

    const __nv_bfloat16* Ab = g_xn_bf   + (size_t)blockIdx.y * 128 * 256;
    const __nv_bfloat16* Bb = g_wqkv_bf + (size_t)blockIdx.x * 128 * 256;

    uint32_t asb = (uint32_t)__cvta_generic_to_shared(&As[0][0][0]);
    uint32_t bsb = (uint32_t)__cvta_generic_to_shared(&Bs[0][0][0]);

    float c[4][4][4] = {};
    gemm_bf16_main(c, Ab, Bb, asb, bsb);

    int mbase = blockIdx.y * 128 + wm;
    int nbase = blockIdx.x * 128 + wn;

    if (blockIdx.x < 2) {               // q: scale + pair-permute
        const float sc = ATT_SCALE * LOG2E;
        uint32_t* qout = (uint32_t*)g_q_bf;
        #pragma unroll
        for (int m = 0; m < 4; m++) {
            int row0 = mbase + m*16 + g;
            #pragma unroll
            for (int j = 0; j < 4; j++) {
                int col = nbase + j*8 + 2*t;          // 0..255
                float2 bv = *(const float2*)&bias[col];
                int word = (col >> 5) * 16 + t*4 + j;
                qout[(size_t)row0       * 128 + word] =
                    pack_bf16x2((c[m][j][0] + bv.x) * sc, (c[m][j][1] + bv.y) * sc);
                qout[(size_t)(row0 + 8) * 128 + word] =
                    pack_bf16x2((c[m][j][2] + bv.x) * sc, (c[m][j][3] + bv.y) * sc);
            }
        }
    } else {                            // k or v: natural bf16
        uint32_t* outp = (blockIdx.x < 4) ? (uint32_t*)g_k_bf : (uint32_t*)g_v_bf;
        int cbase = (blockIdx.x < 4) ? 256 : 512;
        #pragma unroll
        for (int m = 0; m < 4; m++) {
            int row0 = mbase + m*16 + g;
            #pragma unroll
            for (int j = 0; j < 4; j++) {
                int col = nbase + j*8 + 2*t;
                float2 bv = *(const float2*)&bias[col];
                int vcol = col - cbase;
                outp[((size_t)row0       * 256 + vcol) >> 1] =
                    pack_bf16x2(c[m][j][0] + bv.x, c[m][j][1] + bv.y);
                outp[((size_t)(row0 + 8) * 256 + vcol) >> 1] =
                    pack_bf16x2(c[m][j][2] + bv.x, c[m][j][3] + bv.y);
            }
        }
    }
}

// ============================================================
// Kernel 3: attention, all-bf16 mma (unchanged from R13).
// ============================================================
__global__ __launch_bounds__(256, 2) void attn_mma()
{
    __shared__ __align__(16) __nv_bfloat16 Ks[256 * 40];   // [key][40], 80B pitch
    __shared__ __align__(16) __nv_bfloat16 Vs[256 * 40];

    int win  = blockIdx.x >> 3;
    int head = blockIdx.x & 7;
    int tid  = threadIdx.x;
    int lane = tid & 31, warp = tid >> 5;
    int g = lane >> 2, t = lane & 3;

    const __nv_bfloat16* baseK = g_k_bf + (size_t)win * 256 * 256 + head * 32;
    const __nv_bfloat16* baseV = g_v_bf + (size_t)win * 256 * 256 + head * 32;
    const uint32_t* qwords = (const uint32_t*)g_q_bf + (size_t)win * 256 * 128 + head * 16;
    uint32_t* obase = (uint32_t*)g_att_bf + (size_t)win * 256 * 128;

    uint32_t ks_base = (uint32_t)__cvta_generic_to_shared(Ks);
    uint32_t vs_base = (uint32_t)__cvta_generic_to_shared(Vs);

    {
        int key = tid;
        uint32_t dk = ks_base + key * 80;
        uint32_t dv = vs_base + key * 80;
        const __nv_bfloat16* sk = baseK + (size_t)key * 256;
        const __nv_bfloat16* sv = baseV + (size_t)key * 256;
        cpasync16(dk,      sk);      cpasync16(dk + 16, sk + 8);
        cpasync16(dk + 32, sk + 16); cpasync16(dk + 48, sk + 24);
        cpasync16(dv,      sv);      cpasync16(dv + 16, sv + 8);
        cpasync16(dv + 32, sv + 16); cpasync16(dv + 48, sv + 24);
    }
    CP_COMMIT;

    int mrow = warp * 32;
    uint32_t Qw[4][4];
    #pragma unroll
    for (int rg = 0; rg < 4; rg++) {
        int row = mrow + rg * 8 + g;
        *(uint4*)&Qw[rg][0] = *(const uint4*)(qwords + (size_t)row * 128 + t * 4);
    }

    CP_WAIT0;
    __syncthreads();

    int bk_row = (lane & 7) + (lane >> 4) * 8;
    int bk_col = ((lane >> 3) & 1) * 8;
    uint32_t koff_lane = ks_base + bk_row * 80 + bk_col * 2;
    int mat = lane >> 3;
    uint32_t voff_lane = vs_base + ((mat & 1) * 8 + (lane & 7)) * 80 + (mat >> 1) * 16;

    float rs[4] = {0.f, 0.f, 0.f, 0.f};
    float co[2][4][4] = {};

    #pragma unroll
    for (int ch = 0; ch < 8; ch++) {
        int kb = ch * 32;

        float sf[2][4][4] = {};
        #pragma unroll
        for (int kh = 0; kh < 2; kh++) {
            uint32_t kf[4][2];
            ldsm_x4(kf[0][0], kf[0][1], kf[1][0], kf[1][1],
                    koff_lane + (kb     ) * 80 + kh * 32);
            ldsm_x4(kf[2][0], kf[2][1], kf[3][0], kf[3][1],
                    koff_lane + (kb + 16) * 80 + kh * 32);
            #pragma unroll
            for (int ta = 0; ta < 2; ta++) {
                uint32_t a0 = Qw[2*ta    ][2*kh    ];
                uint32_t a1 = Qw[2*ta + 1][2*kh    ];
                uint32_t a2 = Qw[2*ta    ][2*kh + 1];
                uint32_t a3 = Qw[2*ta + 1][2*kh + 1];
                #pragma unroll
                for (int nf = 0; nf < 4; nf++)
                    mma_bf16(sf[ta][nf], a0, a1, a2, a3, kf[nf][0], kf[nf][1]);
            }
        }

        #pragma unroll
        for (int ta = 0; ta < 2; ta++)
            #pragma unroll
            for (int nf = 0; nf < 4; nf++) {
                float e0 = ex2_approx(sf[ta][nf][0]);
                float e1 = ex2_approx(sf[ta][nf][1]);
                float e2 = ex2_approx(sf[ta][nf][2]);
                float e3 = ex2_approx(sf[ta][nf][3]);
                rs[ta*2 + 0] += e0 + e1;
                rs[ta*2 + 1] += e2 + e3;
                sf[ta][nf][0] = e0; sf[ta][nf][1] = e1;
                sf[ta][nf][2] = e2; sf[ta][nf][3] = e3;
            }

        #pragma unroll
        for (int kc = 0; kc < 2; kc++) {
            uint32_t vaddr = voff_lane + (kb + kc * 16) * 80;
            uint32_t b0, b1, b2, b3, b4, b5, b6, b7;
            ldsm_x4_trans(b0, b1, b2, b3, vaddr);
            ldsm_x4_trans(b4, b5, b6, b7, vaddr + 32);
            #pragma unroll
            for (int ta = 0; ta < 2; ta++) {
                uint32_t pa0 = pack_bf16x2(sf[ta][2*kc  ][0], sf[ta][2*kc  ][1]);
                uint32_t pa1 = pack_bf16x2(sf[ta][2*kc  ][2], sf[ta][2*kc  ][3]);
                uint32_t pa2 = pack_bf16x2(sf[ta][2*kc+1][0], sf[ta][2*kc+1][1]);
                uint32_t pa3 = pack_bf16x2(sf[ta][2*kc+1][2], sf[ta][2*kc+1][3]);
                mma_bf16(co[ta][0], pa0, pa1, pa2, pa3, b0, b1);
                mma_bf16(co[ta][1], pa0, pa1, pa2, pa3, b2, b3);
                mma_bf16(co[ta][2], pa0, pa1, pa2, pa3, b4, b5);
                mma_bf16(co[ta][3], pa0, pa1, pa2, pa3, b6, b7);
            }
        }
    }

    #pragma unroll
    for (int ta = 0; ta < 2; ta++) {
        float r0 = rs[ta*2 + 0];
        float r1 = rs[ta*2 + 1];
        r0 += __shfl_xor_sync(0xffffffffu, r0, 1);
        r0 += __shfl_xor_sync(0xffffffffu, r0, 2);
        r1 += __shfl_xor_sync(0xffffffffu, r1, 1);
        r1 += __shfl_xor_sync(0xffffffffu, r1, 2);
        float inv0 = 1.0f / r0;
        float inv1 = 1.0f / r1;

        int mr = mrow + ta * 16;
        #pragma unroll
        for (int nf = 0; nf < 4; nf++) {
            int col = head * 32 + nf*8 + 2*t;
            obase[((size_t)(mr + g    ) * 256 + col) >> 1] =
                pack_bf16x2(co[ta][nf][0] * inv0, co[ta][nf][1] * inv0);
            obase[((size_t)(mr + g + 8) * 256 + col) >> 1] =
                pack_bf16x2(co[ta][nf][2] * inv1, co[ta][nf][3] * inv1);
        }
    }
}

// ============================================================
// Kernel 4: proj GEMM (bf16) + bias + residual(from x) + scatter
// ============================================================
__global__ __launch_bounds__(256, 2) void gemm_proj_bf16(const float* __restrict__ bias,
                                                         const float* __restrict__ x,
                                                         float* __restrict__ out)
{
    // union: 3-stage bf16 A/B tiles (61.4KB) reused as fp32 C staging (66.6KB)
    __shared__ __align__(16) char smem_raw[128 * 130 * 4];
    __nv_bfloat16* As0 = (__nv_bfloat16*)smem_raw;
    __nv_bfloat16* Bs0 = (__nv_bfloat16*)(smem_raw + 3 * STAGE_BYTES);
    float (*Cs)[130]   = (float (*)[130])smem_raw;

    int tid  = threadIdx.x;
    int lane = tid & 31, warp = tid >> 5;
    int g = lane >> 2, t = lane & 3;
    int wm = (warp & 1) * 64;
    int wn = (warp >> 1) * 32;

    const __nv_bfloat16* Ab = g_att_bf   + (size_t)blockIdx.y * 128 * 256;
    const __nv_bfloat16* Bb = g_wproj_bf + (size_t)blockIdx.x * 128 * 256;

    uint32_t asb = (uint32_t)__cvta_generic_to_shared(As0);
    uint32_t bsb = (uint32_t)__cvta_generic_to_shared(Bs0);

    float c[4][4][4] = {};
    gemm_bf16_main(c, Ab, Bb, asb, bsb);
    // gemm_bf16_main ends with __syncthreads -> safe to overlay Cs

    int nbase = blockIdx.x * 128;
    #pragma unroll
    for (int m = 0; m < 4; m++) {
        int rl = wm + m*16 + g;
        #pragma unroll
        for (int j = 0; j < 4; j++) {
            int cl = wn + j*8 + 2*t;
            float2 bv = *(const float2*)&bias[nbase + cl];
            *(float2*)&Cs[rl    ][cl] = make_float2(c[m][j][0] + bv.x, c[m][j][1] + bv.y);
            *(float2*)&Cs[rl + 8][cl] = make_float2(c[m][j][2] + bv.x, c[m][j][3] + bv.y);
        }
    }
    __syncthreads();

    int by   = blockIdx.y;
    int n    = by >> 1;
    int half = by & 1;
    int b  = n >> 6, hi = (n >> 3) & 7, wi = n & 7;

    int cc  = tid & 127;
    int trh = tid >> 7;
    #pragma unroll
    for (int tr2 = 0; tr2 < 8; tr2++) {
        int tr = tr2 * 2 + trh;
        int t2 = tr >> 3, r = tr & 7;
        int l0 = t2 * 64 + r * 8;
        int t_full = half * 2 + t2;
        int bt = b * 4 + t_full;
        int h  = hi * 8 + r;
        int col = nbase + cc;
        size_t oaddr = (((size_t)bt * 256 + col) * 64 + h) * 64 + wi * 8;
        #pragma unroll
        for (int j = 0; j < 2; j++) {
            float4 xr = *(const float4*)&x[oaddr + 4*j];
            float4 v;
            v.x = Cs[l0 + 4*j + 0][cc] + xr.x;
            v.y = Cs[l0 + 4*j + 1][cc] + xr.y;
            v.z = Cs[l0 + 4*j + 2][cc] + xr.z;
            v.w = Cs[l0 + 4*j + 3][cc] + xr.w;
            *(float4*)&out[oaddr + 4*j] = v;
        }
    }
}

// ============================================================
extern "C" void kernel_launch(void* const* d_in, const int* in_sizes, int n_in,
                              void* d_out, int out_size)
{
    const float* x      = (const float*)d_in[0];
    const float* w_qkv  = (const float*)d_in[1];
    const float* b_qkv  = (const float*)d_in[2];
    const float* w_proj = (const float*)d_in[3];
    const float* b_proj = (const float*)d_in[4];
    const float* gamma  = (const float*)d_in[5];
    const float* beta   = (const float*)d_in[6];
    float* out = (float*)d_out;

    prep_weights<<<768, 256>>>(w_qkv, w_proj);
    ln_gather_kernel<<<512, 256>>>(x, gamma, beta);
    gemm_qkv_bf16<<<dim3(6, 256), 256>>>(b_qkv);
    attn_mma<<<NWIN * 8, 256>>>();
    gemm_proj_bf16<<<dim3(2, 256), 256>>>(b_proj, x, out);
}

// round 15
// speedup vs baseline: 2.2597x; 1.0282x over previous
#include <cuda_runtime.h>
#include <cuda_bf16.h>
#include <math.h>
#include <stdint.h>

#define CCH   256
#define TT      4
#define HH     64
#define WWID   64
#define NWIN  128
#define MTOT  (NWIN*256)
#define ATT_SCALE 0.1767766952966369f
#define LOG2E     1.4426950408889634f

// -------- global scratch --------
__device__ __nv_bfloat16  g_xn_bf[MTOT * CCH];       // LN output (bf16)
__device__ __nv_bfloat16  g_q_bf [MTOT * CCH];       // q: scaled(*log2e), pair-permuted, bf16
__device__ __nv_bfloat16  g_k_bf [MTOT * CCH];       // k natural bf16
__device__ uint16_t       g_v_f16[MTOT * CCH];       // v natural f16
__device__ __nv_bfloat16  g_att_bf[MTOT * CCH];      // attention output (bf16)
__device__ __nv_bfloat16  g_wqkv_bf[768 * 256];
__device__ __nv_bfloat16  g_wproj_bf[256 * 256];

// pack (lo, hi) floats into bf16x2 word
__device__ __forceinline__ uint32_t pack_bf16x2(float lo, float hi) {
    uint32_t r;
    asm("cvt.rn.bf16x2.f32 %0, %1, %2;" : "=r"(r) : "f"(hi), "f"(lo));
    return r;
}

// pack (lo, hi) floats into f16x2 word
__device__ __forceinline__ uint32_t pack_f16x2(float lo, float hi) {
    uint32_t r;
    asm("cvt.rn.f16x2.f32 %0, %1, %2;" : "=r"(r) : "f"(hi), "f"(lo));
    return r;
}

// 2-way packed exp2 on f16x2
__device__ __forceinline__ uint32_t ex2_f16x2(uint32_t x) {
    uint32_t r;
    asm("ex2.approx.f16x2 %0, %1;" : "=r"(r) : "r"(x));
    return r;
}

__device__ __forceinline__ void mma_bf16(float* c,
                                         uint32_t a0, uint32_t a1, uint32_t a2, uint32_t a3,
                                         uint32_t b0, uint32_t b1) {
    asm volatile("mma.sync.aligned.m16n8k16.row.col.f32.bf16.bf16.f32 "
                 "{%0,%1,%2,%3}, {%4,%5,%6,%7}, {%8,%9}, {%0,%1,%2,%3};"
                 : "+f"(c[0]), "+f"(c[1]), "+f"(c[2]), "+f"(c[3])
                 : "r"(a0), "r"(a1), "r"(a2), "r"(a3), "r"(b0), "r"(b1));
}

__device__ __forceinline__ void mma_f16(float* c,
                                        uint32_t a0, uint32_t a1, uint32_t a2, uint32_t a3,
                                        uint32_t b0, uint32_t b1) {
    asm volatile("mma.sync.aligned.m16n8k16.row.col.f32.f16.f16.f32 "
                 "{%0,%1,%2,%3}, {%4,%5,%6,%7}, {%8,%9}, {%0,%1,%2,%3};"
                 : "+f"(c[0]), "+f"(c[1]), "+f"(c[2]), "+f"(c[3])
                 : "r"(a0), "r"(a1), "r"(a2), "r"(a3), "r"(b0), "r"(b1));
}

__device__ __forceinline__ void ldsm_x4(uint32_t& r0, uint32_t& r1, uint32_t& r2, uint32_t& r3,
                                        uint32_t addr) {
    asm volatile("ldmatrix.sync.aligned.m8n8.x4.shared.b16 {%0,%1,%2,%3}, [%4];"
                 : "=r"(r0), "=r"(r1), "=r"(r2), "=r"(r3) : "r"(addr));
}

__device__ __forceinline__ void ldsm_x4_trans(uint32_t& r0, uint32_t& r1, uint32_t& r2, uint32_t& r3,
                                              uint32_t addr) {
    asm volatile("ldmatrix.sync.aligned.m8n8.x4.trans.shared.b16 {%0,%1,%2,%3}, [%4];"
                 : "=r"(r0), "=r"(r1), "=r"(r2), "=r"(r3) : "r"(addr));
}

__device__ __forceinline__ void cpasync16(uint32_t dst, const void* src) {
    asm volatile("cp.async.ca.shared.global [%0], [%1], 16;\n" :: "r"(dst), "l"(src));
}
#define CP_COMMIT asm volatile("cp.async.commit_group;\n" ::: "memory")
#define CP_WAIT1  asm volatile("cp.async.wait_group 1;\n" ::: "memory")
#define CP_WAIT0  asm volatile("cp.async.wait_group 0;\n" ::: "memory")

// ============================================================
// Kernel 0: weight prep (fp32 -> bf16 copies)
// ============================================================
__global__ void prep_weights(const float* __restrict__ wq, const float* __restrict__ wp)
{
    int i = blockIdx.x * blockDim.x + threadIdx.x;
    if (i < 768 * 256)  g_wqkv_bf[i]  = __float2bfloat16_rn(wq[i]);
    if (i < 256 * 256)  g_wproj_bf[i] = __float2bfloat16_rn(wp[i]);
}

// ============================================================
// Kernel 1: coalesced gather + LayerNorm (bf16 xn only)
// ============================================================
__global__ __launch_bounds__(256) void ln_gather_kernel(const float* __restrict__ x,
                                                        const float* __restrict__ gamma,
                                                        const float* __restrict__ beta)
{
    __shared__ float tile[256][65];
    __shared__ float rsum[4][64], rsq[4][64];
    __shared__ float mus[64], rstds[64];

    int bx  = blockIdx.x;
    int bt  = bx >> 6;
    int h   = bx & 63;
    int tid = threadIdx.x;

    const float* slice = x + ((size_t)bt * 256) * 4096 + h * 64;

    int cl = tid >> 4;
    int w4 = (tid & 15) * 4;
    #pragma unroll
    for (int it = 0; it < 16; it++) {
        int c = it * 16 + cl;
        float4 v = *(const float4*)(slice + (size_t)c * 4096 + w4);
        tile[c][w4 + 0] = v.x; tile[c][w4 + 1] = v.y;
        tile[c][w4 + 2] = v.z; tile[c][w4 + 3] = v.w;
    }
    __syncthreads();

    {
        int w = tid & 63, part = tid >> 6;
        float s = 0.f, q = 0.f;
        #pragma unroll
        for (int i = 0; i < 64; i++) {
            float v = tile[part * 64 + i][w];
            s += v; q += v * v;
        }
        rsum[part][w] = s; rsq[part][w] = q;
    }
    __syncthreads();
    if (tid < 64) {
        float tot = rsum[0][tid] + rsum[1][tid] + rsum[2][tid] + rsum[3][tid];
        float tq  = rsq[0][tid]  + rsq[1][tid]  + rsq[2][tid]  + rsq[3][tid];
        float mu  = tot * (1.0f / 256.0f);
        float var = tq * (1.0f / 256.0f) - mu * mu;
        mus[tid]  = mu;
        rstds[tid] = rsqrtf(var + 1e-5f);
    }
    __syncthreads();

    int c = tid;
    float gm = gamma[c], be = beta[c];
    int b  = bt >> 2, t = bt & 3;
    int hi = h >> 3, r = h & 7;
    int nbase = b * 64 + hi * 8;
    int lbase = t * 64 + r * 8;
    #pragma unroll 8
    for (int w = 0; w < 64; w++) {
        int n = nbase + (w >> 3);
        int l = lbase + (w & 7);
        size_t m = (size_t)n * 256 + l;
        float val = tile[c][w];
        float xn  = (val - mus[w]) * rstds[w] * gm + be;
        g_xn_bf[m * 256 + c] = __float2bfloat16_rn(xn);
    }
}

// ============================================================
// bf16 GEMM common: 128x128 block, BK=32, 8 warps (64x32 each),
// pitch-40 bf16 smem rows, cp.async 3-stage, ONE barrier per k-iter.
// ============================================================
#define STAGE_BYTES (128 * 40 * 2)

__device__ __forceinline__ void stage_load_bf(uint32_t sA, uint32_t sB,
                                              const __nv_bfloat16* Ag,
                                              const __nv_bfloat16* Bg,
                                              int lrow, int lhalf, int kt)
{
    const __nv_bfloat16* a = Ag + (size_t)lrow * 256 + kt + lhalf * 16;
    const __nv_bfloat16* b = Bg + (size_t)lrow * 256 + kt + lhalf * 16;
    uint32_t da = sA + (lrow * 40 + lhalf * 16) * 2;
    uint32_t db = sB + (lrow * 40 + lhalf * 16) * 2;
    cpasync16(da,      a);
    cpasync16(da + 16, a + 8);
    cpasync16(db,      b);
    cpasync16(db + 16, b + 8);
}

__device__ __forceinline__ void gemm_bf16_main(float (*c)[4][4],
                                               const __nv_bfloat16* Ab,
                                               const __nv_bfloat16* Bb,
                                               uint32_t asb, uint32_t bsb)
{
    int tid  = threadIdx.x;
    int lane = tid & 31, warp = tid >> 5;
    int wm = (warp & 1) * 64;
    int wn = (warp >> 1) * 32;

    int lrow = tid >> 1, lhalf = tid & 1;

    int a_row = lane & 15;
    int a_col = (lane >> 4) * 8;
    int b_row = (lane & 7) + (lane >> 4) * 8;
    int b_col = ((lane >> 3) & 1) * 8;

    uint32_t aS[3] = { asb, asb + STAGE_BYTES, asb + 2 * STAGE_BYTES };
    uint32_t bS[3] = { bsb, bsb + STAGE_BYTES, bsb + 2 * STAGE_BYTES };

    stage_load_bf(aS[0], bS[0], Ab, Bb, lrow, lhalf, 0);
    CP_COMMIT;
    stage_load_bf(aS[1], bS[1], Ab, Bb, lrow, lhalf, 32);
    CP_COMMIT;

    #pragma unroll
    for (int it = 0; it < 8; it++) {
        if (it == 7) { CP_WAIT0; } else { CP_WAIT1; }
        __syncthreads();
        if (it < 6) {
            stage_load_bf(aS[(it+2)%3], bS[(it+2)%3], Ab, Bb, lrow, lhalf, (it+2)*32);
            CP_COMMIT;
        }
        int s = it % 3;
        #pragma unroll
        for (int ks = 0; ks < 2; ks++) {
            uint32_t af[4][4];
            #pragma unroll
            for (int mi = 0; mi < 4; mi++) {
                uint32_t addr = aS[s] + ((wm + mi*16 + a_row) * 40 + ks*16 + a_col) * 2;
                ldsm_x4(af[mi][0], af[mi][1], af[mi][2], af[mi][3], addr);
            }
            uint32_t bf[4][2];
            {
                uint32_t addr0 = bS[s] + ((wn +  0 + b_row) * 40 + ks*16 + b_col) * 2;
                uint32_t addr1 = bS[s] + ((wn + 16 + b_row) * 40 + ks*16 + b_col) * 2;
                ldsm_x4(bf[0][0], bf[0][1], bf[1][0], bf[1][1], addr0);
                ldsm_x4(bf[2][0], bf[2][1], bf[3][0], bf[3][1], addr1);
            }
            #pragma unroll
            for (int mi = 0; mi < 4; mi++)
                #pragma unroll
                for (int j = 0; j < 4; j++)
                    mma_bf16(c[mi][j], af[mi][0], af[mi][1], af[mi][2], af[mi][3],
                             bf[j][0], bf[j][1]);
        }
    }
    __syncthreads();
}

// ============================================================
// Kernel 2: QKV GEMM (bf16). Epilogue:
//   q: *(ATT_SCALE*LOG2E), pair-permuted, bf16
//   k: natural bf16;  v: natural f16
// ============================================================
__global__ __launch_bounds__(256, 2) void gemm_qkv_bf16(const float* __restrict__ bias)
{
    __shared__ __align__(16) __nv_bfloat16 As[3][128][40];
    __shared__ __align__(16) __nv_bfloat16 Bs[3][128][40];

    int tid  = threadIdx.x;
    int lane = tid & 31, warp = tid >> 5;
    int g = lane >> 2, t = lane & 3;
    int wm = (warp & 1) * 64;
    int wn = (warp >> 1) * 32;

    const __nv_bfloat16* Ab = g_xn_bf   + (size_t)blockIdx.y * 128 * 256;
    const __nv_bfloat16* Bb = g_wqkv_bf + (size_t)blockIdx.x * 128 * 256;

    uint32_t asb = (uint32_t)__cvta_generic_to_shared(&As[0][0][0]);
    uint32_t bsb = (uint32_t)__cvta_generic_to_shared(&Bs[0][0][0]);

    float c[4][4][4] = {};
    gemm_bf16_main(c, Ab, Bb, asb, bsb);

    int mbase = blockIdx.y * 128 + wm;
    int nbase = blockIdx.x * 128 + wn;

    if (blockIdx.x < 2) {               // q: scale + pair-permute (bf16)
        const float sc = ATT_SCALE * LOG2E;
        uint32_t* qout = (uint32_t*)g_q_bf;
        #pragma unroll
        for (int m = 0; m < 4; m++) {
            int row0 = mbase + m*16 + g;
            #pragma unroll
            for (int j = 0; j < 4; j++) {
                int col = nbase + j*8 + 2*t;          // 0..255
                float2 bv = *(const float2*)&bias[col];
                int word = (col >> 5) * 16 + t*4 + j;
                qout[(size_t)row0       * 128 + word] =
                    pack_bf16x2((c[m][j][0] + bv.x) * sc, (c[m][j][1] + bv.y) * sc);
                qout[(size_t)(row0 + 8) * 128 + word] =
                    pack_bf16x2((c[m][j][2] + bv.x) * sc, (c[m][j][3] + bv.y) * sc);
            }
        }
    } else if (blockIdx.x < 4) {        // k: natural bf16
        uint32_t* outp = (uint32_t*)g_k_bf;
        #pragma unroll
        for (int m = 0; m < 4; m++) {
            int row0 = mbase + m*16 + g;
            #pragma unroll
            for (int j = 0; j < 4; j++) {
                int col = nbase + j*8 + 2*t;
                float2 bv = *(const float2*)&bias[col];
                int vcol = col - 256;
                outp[((size_t)row0       * 256 + vcol) >> 1] =
                    pack_bf16x2(c[m][j][0] + bv.x, c[m][j][1] + bv.y);
                outp[((size_t)(row0 + 8) * 256 + vcol) >> 1] =
                    pack_bf16x2(c[m][j][2] + bv.x, c[m][j][3] + bv.y);
            }
        }
    } else {                            // v: natural f16
        uint32_t* outp = (uint32_t*)g_v_f16;
        #pragma unroll
        for (int m = 0; m < 4; m++) {
            int row0 = mbase + m*16 + g;
            #pragma unroll
            for (int j = 0; j < 4; j++) {
                int col = nbase + j*8 + 2*t;
                float2 bv = *(const float2*)&bias[col];
                int vcol = col - 512;
                outp[((size_t)row0       * 256 + vcol) >> 1] =
                    pack_f16x2(c[m][j][0] + bv.x, c[m][j][1] + bv.y);
                outp[((size_t)(row0 + 8) * 256 + vcol) >> 1] =
                    pack_f16x2(c[m][j][2] + bv.x, c[m][j][3] + bv.y);
            }
        }
    }
}

// ============================================================
// Kernel 3: attention. QK^T bf16 mma; softmax via packed f16x2
// exp2 (P stays f16-packed = PV A-frags); PV f16 mma; rowsums
// accumulated by an extra mma against a constant all-ones B-frag.
// ============================================================
__global__ __launch_bounds__(256, 2) void attn_mma()
{
    __shared__ __align__(16) __nv_bfloat16 Ks[256 * 40];   // [key][40], 80B pitch
    __shared__ __align__(16) uint16_t      Vs[256 * 40];   // f16

    int win  = blockIdx.x >> 3;
    int head = blockIdx.x & 7;
    int tid  = threadIdx.x;
    int lane = tid & 31, warp = tid >> 5;
    int g = lane >> 2, t = lane & 3;

    const __nv_bfloat16* baseK = g_k_bf  + (size_t)win * 256 * 256 + head * 32;
    const uint16_t*      baseV = g_v_f16 + (size_t)win * 256 * 256 + head * 32;
    const uint32_t* qwords = (const uint32_t*)g_q_bf + (size_t)win * 256 * 128 + head * 16;
    uint32_t* obase = (uint32_t*)g_att_bf + (size_t)win * 256 * 128;

    uint32_t ks_base = (uint32_t)__cvta_generic_to_shared(Ks);
    uint32_t vs_base = (uint32_t)__cvta_generic_to_shared(Vs);

    {
        int key = tid;
        uint32_t dk = ks_base + key * 80;
        uint32_t dv = vs_base + key * 80;
        const __nv_bfloat16* sk = baseK + (size_t)key * 256;
        const uint16_t*      sv = baseV + (size_t)key * 256;
        cpasync16(dk,      sk);      cpasync16(dk + 16, sk + 8);
        cpasync16(dk + 32, sk + 16); cpasync16(dk + 48, sk + 24);
        cpasync16(dv,      sv);      cpasync16(dv + 16, sv + 8);
        cpasync16(dv + 32, sv + 16); cpasync16(dv + 48, sv + 24);
    }
    CP_COMMIT;

    int mrow = warp * 32;
    uint32_t Qw[4][4];
    #pragma unroll
    for (int rg = 0; rg < 4; rg++) {
        int row = mrow + rg * 8 + g;
        *(uint4*)&Qw[rg][0] = *(const uint4*)(qwords + (size_t)row * 128 + t * 4);
    }

    CP_WAIT0;
    __syncthreads();

    int bk_row = (lane & 7) + (lane >> 4) * 8;
    int bk_col = ((lane >> 3) & 1) * 8;
    uint32_t koff_lane = ks_base + bk_row * 80 + bk_col * 2;
    int mat = lane >> 3;
    uint32_t voff_lane = vs_base + ((mat & 1) * 8 + (lane & 7)) * 80 + (mat >> 1) * 16;

    const uint32_t F16_ONES = 0x3C003C00u;   // (1.0, 1.0) f16x2

    float rsf[2][4] = {};      // rowsum C-frags (all cols = sum)
    float co[2][4][4] = {};

    #pragma unroll
    for (int ch = 0; ch < 8; ch++) {
        int kb = ch * 32;

        // ---- S = Q K^T : 32 queries x 32 keys, bf16 k16 ----
        float sf[2][4][4] = {};
        #pragma unroll
        for (int kh = 0; kh < 2; kh++) {
            uint32_t kf[4][2];
            ldsm_x4(kf[0][0], kf[0][1], kf[1][0], kf[1][1],
                    koff_lane + (kb     ) * 80 + kh * 32);
            ldsm_x4(kf[2][0], kf[2][1], kf[3][0], kf[3][1],
                    koff_lane + (kb + 16) * 80 + kh * 32);
            #pragma unroll
            for (int ta = 0; ta < 2; ta++) {
                uint32_t a0 = Qw[2*ta    ][2*kh    ];
                uint32_t a1 = Qw[2*ta + 1][2*kh    ];
                uint32_t a2 = Qw[2*ta    ][2*kh + 1];
                uint32_t a3 = Qw[2*ta + 1][2*kh + 1];
                #pragma unroll
                for (int nf = 0; nf < 4; nf++)
                    mma_bf16(sf[ta][nf], a0, a1, a2, a3, kf[nf][0], kf[nf][1]);
            }
        }

        // ---- packed exp2: P as f16x2 (= PV A-frag words) ----
        uint32_t pf[2][4][2];
        #pragma unroll
        for (int ta = 0; ta < 2; ta++)
            #pragma unroll
            for (int nf = 0; nf < 4; nf++) {
                pf[ta][nf][0] = ex2_f16x2(pack_f16x2(sf[ta][nf][0], sf[ta][nf][1]));
                pf[ta][nf][1] = ex2_f16x2(pack_f16x2(sf[ta][nf][2], sf[ta][nf][3]));
            }

        // ---- O += P V (f16 mma) + rowsum mma vs all-ones B ----
        #pragma unroll
        for (int kc = 0; kc < 2; kc++) {
            uint32_t vaddr = voff_lane + (kb + kc * 16) * 80;
            uint32_t b0, b1, b2, b3, b4, b5, b6, b7;
            ldsm_x4_trans(b0, b1, b2, b3, vaddr);
            ldsm_x4_trans(b4, b5, b6, b7, vaddr + 32);
            #pragma unroll
            for (int ta = 0; ta < 2; ta++) {
                uint32_t pa0 = pf[ta][2*kc  ][0];
                uint32_t pa1 = pf[ta][2*kc  ][1];
                uint32_t pa2 = pf[ta][2*kc+1][0];
                uint32_t pa3 = pf[ta][2*kc+1][1];
                mma_f16(co[ta][0], pa0, pa1, pa2, pa3, b0, b1);
                mma_f16(co[ta][1], pa0, pa1, pa2, pa3, b2, b3);
                mma_f16(co[ta][2], pa0, pa1, pa2, pa3, b4, b5);
                mma_f16(co[ta][3], pa0, pa1, pa2, pa3, b6, b7);
                mma_f16(rsf[ta],   pa0, pa1, pa2, pa3, F16_ONES, F16_ONES);
            }
        }
    }

    // ---- epilogue: rowsums sit in rsf (every lane/col) ----
    #pragma unroll
    for (int ta = 0; ta < 2; ta++) {
        float inv0 = 1.0f / rsf[ta][0];
        float inv1 = 1.0f / rsf[ta][2];

        int mr = mrow + ta * 16;
        #pragma unroll
        for (int nf = 0; nf < 4; nf++) {
            int col = head * 32 + nf*8 + 2*t;
            obase[((size_t)(mr + g    ) * 256 + col) >> 1] =
                pack_bf16x2(co[ta][nf][0] * inv0, co[ta][nf][1] * inv0);
            obase[((size_t)(mr + g + 8) * 256 + col) >> 1] =
                pack_bf16x2(co[ta][nf][2] * inv1, co[ta][nf][3] * inv1);
        }
    }
}

// ============================================================
// Kernel 4: proj GEMM (bf16) + bias + residual(from x) + scatter
// ============================================================
__global__ __launch_bounds__(256, 2) void gemm_proj_bf16(const float* __restrict__ bias,
                                                         const float* __restrict__ x,
                                                         float* __restrict__ out)
{
    __shared__ __align__(16) char smem_raw[128 * 130 * 4];
    __nv_bfloat16* As0 = (__nv_bfloat16*)smem_raw;
    __nv_bfloat16* Bs0 = (__nv_bfloat16*)(smem_raw + 3 * STAGE_BYTES);
    float (*Cs)[130]   = (float (*)[130])smem_raw;

    int tid  = threadIdx.x;
    int lane = tid & 31, warp = tid >> 5;
    int g = lane >> 2, t = lane & 3;
    int wm = (warp & 1) * 64;
    int wn = (warp >> 1) * 32;

    const __nv_bfloat16* Ab = g_att_bf   + (size_t)blockIdx.y * 128 * 256;
    const __nv_bfloat16* Bb = g_wproj_bf + (size_t)blockIdx.x * 128 * 256;

    uint32_t asb = (uint32_t)__cvta_generic_to_shared(As0);
    uint32_t bsb = (uint32_t)__cvta_generic_to_shared(Bs0);

    float c[4][4][4] = {};
    gemm_bf16_main(c, Ab, Bb, asb, bsb);

    int nbase = blockIdx.x * 128;
    #pragma unroll
    for (int m = 0; m < 4; m++) {
        int rl = wm + m*16 + g;
        #pragma unroll
        for (int j = 0; j < 4; j++) {
            int cl = wn + j*8 + 2*t;
            float2 bv = *(const float2*)&bias[nbase + cl];
            *(float2*)&Cs[rl    ][cl] = make_float2(c[m][j][0] + bv.x, c[m][j][1] + bv.y);
            *(float2*)&Cs[rl + 8][cl] = make_float2(c[m][j][2] + bv.x, c[m][j][3] + bv.y);
        }
    }
    __syncthreads();

    int by   = blockIdx.y;
    int n    = by >> 1;
    int half = by & 1;
    int b  = n >> 6, hi = (n >> 3) & 7, wi = n & 7;

    int cc  = tid & 127;
    int trh = tid >> 7;
    #pragma unroll
    for (int tr2 = 0; tr2 < 8; tr2++) {
        int tr = tr2 * 2 + trh;
        int t2 = tr >> 3, r = tr & 7;
        int l0 = t2 * 64 + r * 8;
        int t_full = half * 2 + t2;
        int bt = b * 4 + t_full;
        int h  = hi * 8 + r;
        int col = nbase + cc;
        size_t oaddr = (((size_t)bt * 256 + col) * 64 + h) * 64 + wi * 8;
        #pragma unroll
        for (int j = 0; j < 2; j++) {
            float4 xr = *(const float4*)&x[oaddr + 4*j];
            float4 v;
            v.x = Cs[l0 + 4*j + 0][cc] + xr.x;
            v.y = Cs[l0 + 4*j + 1][cc] + xr.y;
            v.z = Cs[l0 + 4*j + 2][cc] + xr.z;
            v.w = Cs[l0 + 4*j + 3][cc] + xr.w;
            *(float4*)&out[oaddr + 4*j] = v;
        }
    }
}

// ============================================================
extern "C" void kernel_launch(void* const* d_in, const int* in_sizes, int n_in,
                              void* d_out, int out_size)
{
    const float* x      = (const float*)d_in[0];
    const float* w_qkv  = (const float*)d_in[1];
    const float* b_qkv  = (const float*)d_in[2];
    const float* w_proj = (const float*)d_in[3];
    const float* b_proj = (const float*)d_in[4];
    const float* gamma  = (const float*)d_in[5];
    const float* beta   = (const float*)d_in[6];
    float* out = (float*)d_out;

    prep_weights<<<768, 256>>>(w_qkv, w_proj);
    ln_gather_kernel<<<512, 256>>>(x, gamma, beta);
    gemm_qkv_bf16<<<dim3(6, 256), 256>>>(b_qkv);
    attn_mma<<<NWIN * 8, 256>>>();
    gemm_proj_bf16<<<dim3(2, 256), 256>>>(b_proj, x, out);
}